// round 7
// baseline (speedup 1.0000x reference)
#include <cuda_runtime.h>
#include <cuda_bf16.h>
#include <cuda_fp16.h>
#include <mma.h>
#include <math.h>
#include <stdint.h>

using namespace nvcuda;

// ---------------- problem constants ----------------
#define N_NODES 10000
#define N_EDGES 80000
#define N_GRAPHS 64
#define HEADS 8
#define F_IN 128
#define D1 512
#define D2 256
#define D3 128
#define OUT_DIM 10

// concatenated weight layout (q|k|v|s per layer)
#define NTOT1 (HEADS * D1 * 3 + D1)   // 12800
#define NTOT2 (HEADS * D2 * 3 + D2)   // 6400
#define NTOT3 (HEADS * D3 * 3 + D3)   // 3200
#define WBASE1 0LL
#define WBASE2 ((long long)F_IN * NTOT1)
#define WBASE3 (WBASE2 + (long long)D1 * NTOT2)
#define WTOTAL (WBASE3 + (long long)D2 * NTOT3)
#define BBASE1 0
#define BBASE2 NTOT1
#define BBASE3 (NTOT1 + NTOT2)
#define BTOTAL (NTOT1 + NTOT2 + NTOT3)
#define NXTOT (N_NODES * F_IN)

// ---------------- device scratch (static, no allocs) ----------------
__device__ float g_q[(size_t)N_NODES * (HEADS * D1)];
__device__ __half g_k[(size_t)N_NODES * (HEADS * D1)];
__device__ __half g_v[(size_t)N_NODES * (HEADS * D1)];
__device__ float g_skip[(size_t)N_NODES * D1];
__device__ float g_hA[(size_t)N_NODES * D1];

__device__ __nv_bfloat16 g_Ahi[(size_t)N_NODES * D1];
__device__ __nv_bfloat16 g_Alo[(size_t)N_NODES * D1];
__device__ __nv_bfloat16 g_Whi[WTOTAL];
__device__ __nv_bfloat16 g_Wlo[WTOTAL];
__device__ float g_bias[BTOTAL];

__device__ int g_deg[N_NODES];
__device__ int g_ptr[N_NODES + 1];
__device__ int g_fill[N_NODES];
__device__ int g_csr_src[N_EDGES];

__device__ float g_gate[N_NODES];
__device__ float g_gmax[N_GRAPHS];
__device__ float g_gsum[N_GRAPHS];
__device__ float g_pool[N_GRAPHS * D3];

// ---------------- cp.async helpers ----------------
__device__ __forceinline__ void cp16(uint32_t dst, const void* src)
{
    asm volatile("cp.async.cg.shared.global [%0], [%1], 16;" :: "r"(dst), "l"(src));
}
__device__ __forceinline__ void cp_commit() { asm volatile("cp.async.commit_group;"); }
template <int Np>
__device__ __forceinline__ void cp_wait() { asm volatile("cp.async.wait_group %0;" :: "n"(Np)); }

// ---------------- one-shot packing: weights + x split + bias ----------------
struct PackArgs {
    const float* wsrc[12];
    long long wcum[13];
    int wncols[12];
    long long wdstBase[12];
    int wntot[12];
    int wcoff[12];
    const float* bsrc[12];
    int bcum[13];
    int boff[12];
    const float* x;
};

__global__ void pack_all(PackArgs P, __nv_bfloat16* __restrict__ Whi, __nv_bfloat16* __restrict__ Wlo,
                         __nv_bfloat16* __restrict__ Ahi, __nv_bfloat16* __restrict__ Alo,
                         float* __restrict__ bias, long long wtotal, long long xtotal, int btotal)
{
    long long i = (long long)blockIdx.x * blockDim.x + threadIdx.x;
    if (i < wtotal) {
        int r = 0;
        while (i >= P.wcum[r + 1]) r++;
        const long long li = i - P.wcum[r];
        const int nc = P.wncols[r];
        const int k = (int)(li / nc), c = (int)(li % nc);
        const float v = P.wsrc[r][li];
        const long long di = P.wdstBase[r] + (long long)k * P.wntot[r] + P.wcoff[r] + c;
        __nv_bfloat16 h = __float2bfloat16(v);
        Whi[di] = h;
        Wlo[di] = __float2bfloat16(v - __bfloat162float(h));
        return;
    }
    i -= wtotal;
    if (i < xtotal) {
        const float v = P.x[i];
        __nv_bfloat16 h = __float2bfloat16(v);
        Ahi[i] = h;
        Alo[i] = __float2bfloat16(v - __bfloat162float(h));
        return;
    }
    int j = (int)(i - xtotal);
    if (j < btotal) {
        int r = 0;
        while (j >= P.bcum[r + 1]) r++;
        bias[P.boff[r] + (j - P.bcum[r])] = P.bsrc[r][j - P.bcum[r]];
    }
}

// ---------------- fused bf16x3 tensor-core GEMM, BK=32, dynamic smem ----------------
// smem layout per stage (bf16 elems): Ah[128*40] Al[128*40] Bh[32*136] Bl[32*136]
#define LDA 40
#define LDB 136
#define ASZ (128 * LDA)       // 5120 elems
#define BSZ (32 * LDB)        // 4352 elems
#define STAGE_E (2 * ASZ + 2 * BSZ)   // 18944 elems = 37888 B
#define GEMM_SMEM_BYTES (2 * STAGE_E * 2)  // 75776 B (>= 128*132*4 epi buffer)

__global__ __launch_bounds__(256)
void gemm_fused(const __nv_bfloat16* __restrict__ Ahi, const __nv_bfloat16* __restrict__ Alo,
                const __nv_bfloat16* __restrict__ Bhi, const __nv_bfloat16* __restrict__ Blo,
                const float* __restrict__ bias,
                float* __restrict__ Q, __half* __restrict__ Ko, __half* __restrict__ Vo,
                float* __restrict__ S,
                int M, int N, int K, int HC, int C)
{
    extern __shared__ __align__(16) __nv_bfloat16 sm[];

    const int tid = threadIdx.x;
    const int warpId = tid >> 5;
    const int wm = warpId >> 2;
    const int wn = warpId & 3;
    const int bm = blockIdx.y * 128;
    const int bn = blockIdx.x * 128;

    // A loader coords: thread -> (row, 16-col half)
    const int ar = tid >> 1, ac = (tid & 1) * 16;
    // B loader coords: thread -> (row, 16-col segment of 128)
    const int br = tid >> 3, bc = (tid & 7) * 16;

    wmma::fragment<wmma::accumulator, 16, 16, 16, float> acc[4][2];
#pragma unroll
    for (int i = 0; i < 4; i++)
#pragma unroll
        for (int j = 0; j < 2; j++) wmma::fill_fragment(acc[i][j], 0.f);

    auto issue = [&](int kb, int s) {
        __nv_bfloat16* base = sm + s * STAGE_E;
        // A hi/lo: 128 rows x 32 cols
        {
            __nv_bfloat16* pAh = base + ar * LDA + ac;
            __nv_bfloat16* pAl = pAh + ASZ;
            const int gr = bm + ar;
            if (gr < M) {
                const size_t off = (size_t)gr * K + kb + ac;
                cp16((uint32_t)__cvta_generic_to_shared(pAh),     Ahi + off);
                cp16((uint32_t)__cvta_generic_to_shared(pAh + 8), Ahi + off + 8);
                cp16((uint32_t)__cvta_generic_to_shared(pAl),     Alo + off);
                cp16((uint32_t)__cvta_generic_to_shared(pAl + 8), Alo + off + 8);
            } else {
                uint4 z = make_uint4(0, 0, 0, 0);
                *reinterpret_cast<uint4*>(pAh) = z;
                *reinterpret_cast<uint4*>(pAh + 8) = z;
                *reinterpret_cast<uint4*>(pAl) = z;
                *reinterpret_cast<uint4*>(pAl + 8) = z;
            }
        }
        // B hi/lo: 32 rows x 128 cols
        {
            __nv_bfloat16* pBh = base + 2 * ASZ + br * LDB + bc;
            const size_t boff = (size_t)(kb + br) * N + bn + bc;
            cp16((uint32_t)__cvta_generic_to_shared(pBh),       Bhi + boff);
            cp16((uint32_t)__cvta_generic_to_shared(pBh + 8),   Bhi + boff + 8);
            cp16((uint32_t)__cvta_generic_to_shared(pBh + BSZ),     Blo + boff);
            cp16((uint32_t)__cvta_generic_to_shared(pBh + BSZ + 8), Blo + boff + 8);
        }
        cp_commit();
    };

    const int nk = K >> 5;     // BK = 32
    issue(0, 0);

    for (int it = 0; it < nk; ++it) {
        const int s = it & 1;
        if (it + 1 < nk) { issue((it + 1) << 5, s ^ 1); cp_wait<1>(); }
        else             { cp_wait<0>(); }
        __syncthreads();

        const __nv_bfloat16* Ah = sm + s * STAGE_E;
        const __nv_bfloat16* Al = Ah + ASZ;
        const __nv_bfloat16* Bh = Ah + 2 * ASZ;
        const __nv_bfloat16* Bl = Bh + BSZ;

#pragma unroll
        for (int kk = 0; kk < 2; kk++) {
            wmma::fragment<wmma::matrix_a, 16, 16, 16, __nv_bfloat16, wmma::row_major> ah[4], al[4];
            wmma::fragment<wmma::matrix_b, 16, 16, 16, __nv_bfloat16, wmma::row_major> bh[2], bl[2];
#pragma unroll
            for (int i = 0; i < 4; i++) {
                wmma::load_matrix_sync(ah[i], Ah + (wm * 64 + i * 16) * LDA + kk * 16, LDA);
                wmma::load_matrix_sync(al[i], Al + (wm * 64 + i * 16) * LDA + kk * 16, LDA);
            }
#pragma unroll
            for (int j = 0; j < 2; j++) {
                wmma::load_matrix_sync(bh[j], Bh + (kk * 16) * LDB + wn * 32 + j * 16, LDB);
                wmma::load_matrix_sync(bl[j], Bl + (kk * 16) * LDB + wn * 32 + j * 16, LDB);
            }
#pragma unroll
            for (int i = 0; i < 4; i++)
#pragma unroll
                for (int j = 0; j < 2; j++) {
                    wmma::mma_sync(acc[i][j], ah[i], bh[j], acc[i][j]);
                    wmma::mma_sync(acc[i][j], ah[i], bl[j], acc[i][j]);
                    wmma::mma_sync(acc[i][j], al[i], bh[j], acc[i][j]);
                }
        }
        __syncthreads();
    }

    // ---- tile-wide epilogue: all frags -> 128x132 fp32 smem, one pass out ----
    constexpr int LDE = 132;
    float* epi = reinterpret_cast<float*>(sm);
#pragma unroll
    for (int i = 0; i < 4; i++)
#pragma unroll
        for (int j = 0; j < 2; j++)
            wmma::store_matrix_sync(epi + (wm * 64 + i * 16) * LDE + wn * 32 + j * 16,
                                    acc[i][j], LDE, wmma::mem_row_major);
    __syncthreads();

#pragma unroll
    for (int f = tid; f < 4096; f += 256) {       // 128 rows x 32 float4
        const int r = f >> 5, c4 = (f & 31) * 4;
        const int row = bm + r;
        if (row >= M) continue;
        float4 vv = *reinterpret_cast<const float4*>(epi + r * LDE + c4);
        const int col = bn + c4;
        const float4 bb = *reinterpret_cast<const float4*>(bias + col);
        vv.x += bb.x; vv.y += bb.y; vv.z += bb.z; vv.w += bb.w;
        if (col < HC) {
            *reinterpret_cast<float4*>(Q + (size_t)row * HC + col) = vv;
        } else if (col < 2 * HC) {
            uint2 p;
            *reinterpret_cast<__half2*>(&p.x) = __floats2half2_rn(vv.x, vv.y);
            *reinterpret_cast<__half2*>(&p.y) = __floats2half2_rn(vv.z, vv.w);
            *reinterpret_cast<uint2*>(Ko + (size_t)row * HC + (col - HC)) = p;
        } else if (col < 3 * HC) {
            uint2 p;
            *reinterpret_cast<__half2*>(&p.x) = __floats2half2_rn(vv.x, vv.y);
            *reinterpret_cast<__half2*>(&p.y) = __floats2half2_rn(vv.z, vv.w);
            *reinterpret_cast<uint2*>(Vo + (size_t)row * HC + (col - 2 * HC)) = p;
        } else {
            *reinterpret_cast<float4*>(S + (size_t)row * C + (col - 3 * HC)) = vv;
        }
    }
}

// ---------------- CSR build ----------------
__global__ void count_deg(const int* __restrict__ ei, int* __restrict__ deg, int E)
{
    int e = blockIdx.x * blockDim.x + threadIdx.x;
    if (e < E) atomicAdd(&deg[ei[E + e]], 1);
}

__global__ void scan_deg(const int* __restrict__ deg, int* __restrict__ ptr,
                         int* __restrict__ fill, int n)
{
    constexpr int PER = 10;
    const int tid = threadIdx.x;
    const int lane = tid & 31, wid = tid >> 5;
    const int base = tid * PER;

    int vals[PER];
    int s = 0;
#pragma unroll
    for (int i = 0; i < PER; i++) {
        const int idx = base + i;
        vals[i] = (idx < n) ? deg[idx] : 0;
        s += vals[i];
    }
    int sc = s;
#pragma unroll
    for (int o = 1; o < 32; o <<= 1) {
        int t = __shfl_up_sync(0xffffffffu, sc, o);
        if (lane >= o) sc += t;
    }
    __shared__ int wsum[32];
    if (lane == 31) wsum[wid] = sc;
    __syncthreads();
    if (wid == 0) {
        int w = wsum[lane];
#pragma unroll
        for (int o = 1; o < 32; o <<= 1) {
            int t = __shfl_up_sync(0xffffffffu, w, o);
            if (lane >= o) w += t;
        }
        wsum[lane] = w;
    }
    __syncthreads();
    int run = (sc - s) + (wid > 0 ? wsum[wid - 1] : 0);
#pragma unroll
    for (int i = 0; i < PER; i++) {
        const int idx = base + i;
        if (idx < n) { ptr[idx] = run; fill[idx] = run; }
        run += vals[i];
    }
    if (tid == 1023) ptr[n] = run;
}

__global__ void fill_csr(const int* __restrict__ ei, int* __restrict__ fill,
                         int* __restrict__ csr_src, int E)
{
    int e = blockIdx.x * blockDim.x + threadIdx.x;
    if (e < E) {
        const int d = ei[E + e];
        const int pos = atomicAdd(&fill[d], 1);
        csr_src[pos] = ei[e];
    }
}

// ---------------- fused attention aggregation ----------------
template <int C, bool SPLIT>
__global__ void attn_kernel(const float* __restrict__ q, const __half* __restrict__ k,
                            const __half* __restrict__ v, const int* __restrict__ ptr,
                            const int* __restrict__ csr_src, const float* __restrict__ skip,
                            float* __restrict__ out,
                            __nv_bfloat16* __restrict__ outHi, __nv_bfloat16* __restrict__ outLo)
{
    constexpr int H = HEADS;
    constexpr int F4 = C / 128;
    __shared__ float red[H * C];

    const int dst  = blockIdx.x;
    const int warp = threadIdx.x >> 5;
    const int lane = threadIdx.x & 31;
    const float scale = rsqrtf((float)C);
    const size_t HC = (size_t)H * C;

    const int beg = ptr[dst], end = ptr[dst + 1];

    const float4* qrow = reinterpret_cast<const float4*>(q + (size_t)dst * HC + warp * C);
    float4 qr[F4], acc[F4];
#pragma unroll
    for (int i = 0; i < F4; i++) {
        qr[i] = qrow[lane + 32 * i];
        acc[i] = make_float4(0.f, 0.f, 0.f, 0.f);
    }
    float m = -INFINITY, s = 0.f;

    for (int j = beg; j < end; j++) {
        const int src = csr_src[j];
        const uint2* krow = reinterpret_cast<const uint2*>(k + (size_t)src * HC + warp * C);
        const uint2* vrow = reinterpret_cast<const uint2*>(v + (size_t)src * HC + warp * C);
        float d = 0.f;
#pragma unroll
        for (int i = 0; i < F4; i++) {
            const uint2 kk = krow[lane + 32 * i];
            const float2 k0 = __half22float2(*reinterpret_cast<const __half2*>(&kk.x));
            const float2 k1 = __half22float2(*reinterpret_cast<const __half2*>(&kk.y));
            d += qr[i].x * k0.x + qr[i].y * k0.y + qr[i].z * k1.x + qr[i].w * k1.y;
        }
#pragma unroll
        for (int o = 16; o > 0; o >>= 1) d += __shfl_xor_sync(0xffffffffu, d, o);
        const float a = d * scale;
        const float mn = fmaxf(m, a);
        const float corr = expf(m - mn);
        const float w = expf(a - mn);
        s = s * corr + w;
        m = mn;
#pragma unroll
        for (int i = 0; i < F4; i++) {
            const uint2 vvp = vrow[lane + 32 * i];
            const float2 v0 = __half22float2(*reinterpret_cast<const __half2*>(&vvp.x));
            const float2 v1 = __half22float2(*reinterpret_cast<const __half2*>(&vvp.y));
            acc[i].x = acc[i].x * corr + w * v0.x;
            acc[i].y = acc[i].y * corr + w * v0.y;
            acc[i].z = acc[i].z * corr + w * v1.x;
            acc[i].w = acc[i].w * corr + w * v1.y;
        }
    }

    const float inv = (end > beg) ? (1.f / (s + 1e-16f)) : 0.f;
#pragma unroll
    for (int i = 0; i < F4; i++) {
        float4 o = make_float4(acc[i].x * inv, acc[i].y * inv, acc[i].z * inv, acc[i].w * inv);
        *reinterpret_cast<float4*>(&red[warp * C + i * 128 + lane * 4]) = o;
    }
    __syncthreads();

    for (int f = threadIdx.x; f < C; f += blockDim.x) {
        float t = 0.f;
#pragma unroll
        for (int h = 0; h < H; h++) t += red[h * C + f];
        t = t * (1.f / H) + skip[(size_t)dst * C + f];
        t = (t > 0.f) ? t : expm1f(t);
        const size_t idx = (size_t)dst * C + f;
        if constexpr (SPLIT) {
            __nv_bfloat16 hh = __float2bfloat16(t);
            outHi[idx] = hh;
            outLo[idx] = __float2bfloat16(t - __bfloat162float(hh));
        } else {
            out[idx] = t;
        }
    }
}

// ---------------- global attention pooling ----------------
__global__ void init_gmax(float* gmax)
{
    if (threadIdx.x < N_GRAPHS) gmax[threadIdx.x] = -INFINITY;
}

__global__ void gate_kernel(const float* __restrict__ h, const float* __restrict__ wg,
                            const float* __restrict__ bg, const int* __restrict__ batch,
                            float* __restrict__ gate, float* __restrict__ gmax, int n)
{
    const int node = (blockIdx.x * blockDim.x + threadIdx.x) >> 5;
    const int lane = threadIdx.x & 31;
    if (node >= n) return;
    const float* row = h + (size_t)node * D3;
    float d = 0.f;
#pragma unroll
    for (int i = 0; i < D3 / 32; i++) d += row[lane + 32 * i] * wg[lane + 32 * i];
#pragma unroll
    for (int o = 16; o > 0; o >>= 1) d += __shfl_xor_sync(0xffffffffu, d, o);
    if (lane == 0) {
        d += bg[0];
        gate[node] = d;
        float* addr = &gmax[batch[node]];
        if (d >= 0.f) atomicMax((int*)addr, __float_as_int(d));
        else          atomicMin((unsigned int*)addr, __float_as_uint(d));
    }
}

__global__ void exp_pool(const float* __restrict__ h, const float* __restrict__ gate,
                         const int* __restrict__ batch, const float* __restrict__ gmax,
                         float* __restrict__ gsum, float* __restrict__ pool)
{
    const int node = blockIdx.x;
    const int f = threadIdx.x;
    const int b = batch[node];
    const float e = expf(gate[node] - gmax[b]);
    if (f == 0) atomicAdd(&gsum[b], e);
    atomicAdd(&pool[b * D3 + f], e * h[(size_t)node * D3 + f]);
}

__global__ void fc_kernel(const float* __restrict__ pool, const float* __restrict__ gsum,
                          const float* __restrict__ wfc, const float* __restrict__ bfc,
                          float* __restrict__ out)
{
    const int t = threadIdx.x;
    if (t >= N_GRAPHS * OUT_DIM) return;
    const int g = t / OUT_DIM, o = t % OUT_DIM;
    float s = 0.f;
#pragma unroll 16
    for (int f = 0; f < D3; f++) s += pool[g * D3 + f] * wfc[f * OUT_DIM + o];
    out[g * OUT_DIM + o] = s / (gsum[g] + 1e-16f) + bfc[o];
}

// ---------------- launch ----------------
extern "C" void kernel_launch(void* const* d_in, const int* in_sizes, int n_in,
                              void* d_out, int out_size)
{
    const float* x     = (const float*)d_in[0];
    const int*   ei    = (const int*)d_in[1];
    const int*   batch = (const int*)d_in[2];
    const float* W[12] = { (const float*)d_in[3],  (const float*)d_in[5],
                           (const float*)d_in[7],  (const float*)d_in[9],
                           (const float*)d_in[11], (const float*)d_in[13],
                           (const float*)d_in[15], (const float*)d_in[17],
                           (const float*)d_in[19], (const float*)d_in[21],
                           (const float*)d_in[23], (const float*)d_in[25] };
    const float* Bv[12] = { (const float*)d_in[4],  (const float*)d_in[6],
                            (const float*)d_in[8],  (const float*)d_in[10],
                            (const float*)d_in[12], (const float*)d_in[14],
                            (const float*)d_in[16], (const float*)d_in[18],
                            (const float*)d_in[20], (const float*)d_in[22],
                            (const float*)d_in[24], (const float*)d_in[26] };
    const float* w_g  = (const float*)d_in[27]; const float* b_g  = (const float*)d_in[28];
    const float* w_fc = (const float*)d_in[29]; const float* b_fc = (const float*)d_in[30];
    float* out = (float*)d_out;

    float *qb, *skipb, *hA, *gateb, *gmaxb, *gsumb, *poolb, *biasb;
    __half *kb, *vb;
    __nv_bfloat16 *Ahi, *Alo, *Whi, *Wlo;
    int *degb, *ptrb, *fillb, *csrb;
    cudaGetSymbolAddress((void**)&qb,    g_q);
    cudaGetSymbolAddress((void**)&kb,    g_k);
    cudaGetSymbolAddress((void**)&vb,    g_v);
    cudaGetSymbolAddress((void**)&skipb, g_skip);
    cudaGetSymbolAddress((void**)&hA,    g_hA);
    cudaGetSymbolAddress((void**)&Ahi,   g_Ahi);
    cudaGetSymbolAddress((void**)&Alo,   g_Alo);
    cudaGetSymbolAddress((void**)&Whi,   g_Whi);
    cudaGetSymbolAddress((void**)&Wlo,   g_Wlo);
    cudaGetSymbolAddress((void**)&biasb, g_bias);
    cudaGetSymbolAddress((void**)&degb,  g_deg);
    cudaGetSymbolAddress((void**)&ptrb,  g_ptr);
    cudaGetSymbolAddress((void**)&fillb, g_fill);
    cudaGetSymbolAddress((void**)&csrb,  g_csr_src);
    cudaGetSymbolAddress((void**)&gateb, g_gate);
    cudaGetSymbolAddress((void**)&gmaxb, g_gmax);
    cudaGetSymbolAddress((void**)&gsumb, g_gsum);
    cudaGetSymbolAddress((void**)&poolb, g_pool);

    const int N = N_NODES, E = N_EDGES;

    // allow >48KB dynamic smem (host-side config, not an allocation)
    static bool attrSet = false;
    if (!attrSet) {
        cudaFuncSetAttribute(gemm_fused, cudaFuncAttributeMaxDynamicSharedMemorySize,
                             GEMM_SMEM_BYTES);
        attrSet = true;
    }

    // region tables
    const int Kl[3]    = { F_IN, D1, D2 };
    const int HCl[3]   = { HEADS * D1, HEADS * D2, HEADS * D3 };
    const int Cl[3]    = { D1, D2, D3 };
    const int NTl[3]   = { NTOT1, NTOT2, NTOT3 };
    const long long WBl[3] = { WBASE1, WBASE2, WBASE3 };
    const int BBl[3]   = { BBASE1, BBASE2, BBASE3 };

    PackArgs P;
    long long wcum = 0;
    int bcum = 0;
    for (int l = 0; l < 3; l++) {
        for (int p = 0; p < 4; p++) {
            const int r = l * 4 + p;
            const int ncols = (p < 3) ? HCl[l] : Cl[l];
            const int coff  = (p < 3) ? p * HCl[l] : 3 * HCl[l];
            P.wsrc[r] = W[r];
            P.wcum[r] = wcum;
            P.wncols[r] = ncols;
            P.wdstBase[r] = WBl[l];
            P.wntot[r] = NTl[l];
            P.wcoff[r] = coff;
            wcum += (long long)Kl[l] * ncols;
            P.bsrc[r] = Bv[r];
            P.bcum[r] = bcum;
            P.boff[r] = BBl[l] + coff;
            bcum += ncols;
        }
    }
    P.wcum[12] = wcum;
    P.bcum[12] = bcum;
    P.x = x;

    const long long packTotal = wcum + NXTOT + bcum;

    // launch order: gemm_fused L1 is the 5th launch (ncu capture slot)
    pack_all<<<(int)((packTotal + 255) / 256), 256>>>(P, Whi, Wlo, Ahi, Alo, biasb,
                                                      wcum, NXTOT, bcum);               // 1
    cudaMemsetAsync(degb, 0, N * sizeof(int));                                          // 2
    count_deg<<<(E + 255) / 256, 256>>>(ei, degb, E);                                   // 3
    scan_deg<<<1, 1024>>>(degb, ptrb, fillb, N);                                        // 4
    {
        dim3 grid(NTOT1 / 128, (N + 127) / 128);                                        // 5 <- profiled
        gemm_fused<<<grid, 256, GEMM_SMEM_BYTES>>>(Ahi, Alo, Whi + WBASE1, Wlo + WBASE1,
                                                   biasb + BBASE1, qb, kb, vb, skipb,
                                                   N, NTOT1, F_IN, HEADS * D1, D1);
    }
    fill_csr<<<(E + 255) / 256, 256>>>(ei, fillb, csrb, E);                             // 6
    attn_kernel<D1, true><<<N, 256>>>(qb, kb, vb, ptrb, csrb, skipb, nullptr, Ahi, Alo);

    {
        dim3 grid(NTOT2 / 128, (N + 127) / 128);
        gemm_fused<<<grid, 256, GEMM_SMEM_BYTES>>>(Ahi, Alo, Whi + WBASE2, Wlo + WBASE2,
                                                   biasb + BBASE2, qb, kb, vb, skipb,
                                                   N, NTOT2, D1, HEADS * D2, D2);
    }
    attn_kernel<D2, true><<<N, 256>>>(qb, kb, vb, ptrb, csrb, skipb, nullptr, Ahi, Alo);

    {
        dim3 grid(NTOT3 / 128, (N + 127) / 128);
        gemm_fused<<<grid, 256, GEMM_SMEM_BYTES>>>(Ahi, Alo, Whi + WBASE3, Wlo + WBASE3,
                                                   biasb + BBASE3, qb, kb, vb, skipb,
                                                   N, NTOT3, D2, HEADS * D3, D3);
    }
    attn_kernel<D3, false><<<N, 256>>>(qb, kb, vb, ptrb, csrb, skipb, hA, nullptr, nullptr);

    // ---- pooling + fc ----
    init_gmax<<<1, 64>>>(gmaxb);
    cudaMemsetAsync(gsumb, 0, N_GRAPHS * sizeof(float));
    cudaMemsetAsync(poolb, 0, N_GRAPHS * D3 * sizeof(float));
    gate_kernel<<<(N * 32 + 255) / 256, 256>>>(hA, w_g, b_g, batch, gateb, gmaxb, N);
    exp_pool<<<N, D3>>>(hA, gateb, batch, gmaxb, gsumb, poolb);
    fc_kernel<<<1, 1024>>>(poolb, gsumb, w_fc, b_fc, out);
}

// round 9
// speedup vs baseline: 1.1725x; 1.1725x over previous
#include <cuda_runtime.h>
#include <cuda_bf16.h>
#include <cuda_fp16.h>
#include <mma.h>
#include <math.h>
#include <stdint.h>

using namespace nvcuda;

// ---------------- problem constants ----------------
#define N_NODES 10000
#define N_EDGES 80000
#define N_GRAPHS 64
#define HEADS 8
#define F_IN 128
#define D1 512
#define D2 256
#define D3 128
#define OUT_DIM 10

// concatenated weight layout (q|k|v|s per layer)
#define NTOT1 (HEADS * D1 * 3 + D1)   // 12800
#define NTOT2 (HEADS * D2 * 3 + D2)   // 6400
#define NTOT3 (HEADS * D3 * 3 + D3)   // 3200
#define WBASE1 0LL
#define WBASE2 ((long long)F_IN * NTOT1)
#define WBASE3 (WBASE2 + (long long)D1 * NTOT2)
#define WTOTAL (WBASE3 + (long long)D2 * NTOT3)
#define BBASE1 0
#define BBASE2 NTOT1
#define BBASE3 (NTOT1 + NTOT2)
#define BTOTAL (NTOT1 + NTOT2 + NTOT3)
#define NXTOT (N_NODES * F_IN)

// ---------------- device scratch (static, no allocs) ----------------
__device__ float g_q[(size_t)N_NODES * (HEADS * D1)];
__device__ __half g_k[(size_t)N_NODES * (HEADS * D1)];
__device__ __half g_v[(size_t)N_NODES * (HEADS * D1)];
__device__ float g_skip[(size_t)N_NODES * D1];
__device__ float g_hA[(size_t)N_NODES * D1];

__device__ __nv_bfloat16 g_Ahi[(size_t)N_NODES * D1];
__device__ __nv_bfloat16 g_Alo[(size_t)N_NODES * D1];
__device__ __nv_bfloat16 g_Whi[WTOTAL];
__device__ __nv_bfloat16 g_Wlo[WTOTAL];
__device__ float g_bias[BTOTAL];

__device__ int g_deg[N_NODES];
__device__ int g_ptr[N_NODES + 1];
__device__ int g_fill[N_NODES];
__device__ int g_csr_src[N_EDGES];

__device__ float g_gate[N_NODES];
__device__ float g_gmax[N_GRAPHS];
__device__ float g_gsum[N_GRAPHS];
__device__ float g_pool[N_GRAPHS * D3];

// ---------------- cp.async helpers ----------------
__device__ __forceinline__ void cp16(uint32_t dst, const void* src)
{
    asm volatile("cp.async.cg.shared.global [%0], [%1], 16;" :: "r"(dst), "l"(src));
}
__device__ __forceinline__ void cp_commit() { asm volatile("cp.async.commit_group;"); }
template <int Np>
__device__ __forceinline__ void cp_wait() { asm volatile("cp.async.wait_group %0;" :: "n"(Np)); }

// ---------------- one-shot packing: weights + x split + bias ----------------
struct PackArgs {
    const float* wsrc[12];
    long long wcum[13];
    int wncols[12];
    long long wdstBase[12];
    int wntot[12];
    int wcoff[12];
    const float* bsrc[12];
    int bcum[13];
    int boff[12];
    const float* x;
};

__global__ void pack_all(PackArgs P, __nv_bfloat16* __restrict__ Whi, __nv_bfloat16* __restrict__ Wlo,
                         __nv_bfloat16* __restrict__ Ahi, __nv_bfloat16* __restrict__ Alo,
                         float* __restrict__ bias, long long wtotal, long long xtotal, int btotal)
{
    long long i = (long long)blockIdx.x * blockDim.x + threadIdx.x;
    if (i < wtotal) {
        int r = 0;
        while (i >= P.wcum[r + 1]) r++;
        const long long li = i - P.wcum[r];
        const int nc = P.wncols[r];
        const int k = (int)(li / nc), c = (int)(li % nc);
        const float v = P.wsrc[r][li];
        const long long di = P.wdstBase[r] + (long long)k * P.wntot[r] + P.wcoff[r] + c;
        __nv_bfloat16 h = __float2bfloat16(v);
        Whi[di] = h;
        Wlo[di] = __float2bfloat16(v - __bfloat162float(h));
        return;
    }
    i -= wtotal;
    if (i < xtotal) {
        const float v = P.x[i];
        __nv_bfloat16 h = __float2bfloat16(v);
        Ahi[i] = h;
        Alo[i] = __float2bfloat16(v - __bfloat162float(h));
        return;
    }
    int j = (int)(i - xtotal);
    if (j < btotal) {
        int r = 0;
        while (j >= P.bcum[r + 1]) r++;
        bias[P.boff[r] + (j - P.bcum[r])] = P.bsrc[r][j - P.bcum[r]];
    }
}

// ---------------- fused bf16x3 tensor-core GEMM (q|k|v|s outputs) ----------------
// block tile 128x128, BK=16, 8 warps (2x4), warp tile 64x32. cp.async 3-stage pipeline.
#define LDA 24
#define LDB 136
#define ASZ (128 * LDA)                 // 3072 elems
#define BSZ (16 * LDB)                  // 2176 elems
#define STAGE_E (2 * ASZ + 2 * BSZ)     // 10496 elems = 20992 B
#define GEMM_SMEM_BYTES (3 * STAGE_E * 2)  // 62976 B

__global__ __launch_bounds__(256, 2)
void gemm_fused(const __nv_bfloat16* __restrict__ Ahi, const __nv_bfloat16* __restrict__ Alo,
                const __nv_bfloat16* __restrict__ Bhi, const __nv_bfloat16* __restrict__ Blo,
                const float* __restrict__ bias,
                float* __restrict__ Q, __half* __restrict__ Ko, __half* __restrict__ Vo,
                float* __restrict__ S,
                int M, int N, int K, int HC, int C)
{
    extern __shared__ __align__(16) __nv_bfloat16 sm[];

    const int tid = threadIdx.x;
    const int warpId = tid >> 5;
    const int lane = tid & 31;
    const int wm = warpId >> 2;
    const int wn = warpId & 3;
    const int bm = blockIdx.y * 128;
    const int bn = blockIdx.x * 128;

    const int arow = tid >> 1, ac8 = (tid & 1) * 8;
    const int brow = tid >> 4, bc8 = (tid & 15) * 8;

    wmma::fragment<wmma::accumulator, 16, 16, 16, float> acc[4][2];
#pragma unroll
    for (int i = 0; i < 4; i++)
#pragma unroll
        for (int j = 0; j < 2; j++) wmma::fill_fragment(acc[i][j], 0.f);

    auto issue = [&](int kb, int s) {
        __nv_bfloat16* base = sm + s * STAGE_E;
        __nv_bfloat16* pAh = base + arow * LDA + ac8;
        __nv_bfloat16* pAl = pAh + ASZ;
        const int gr = bm + arow;
        if (gr < M) {
            const size_t off = (size_t)gr * K + kb + ac8;
            cp16((uint32_t)__cvta_generic_to_shared(pAh), Ahi + off);
            cp16((uint32_t)__cvta_generic_to_shared(pAl), Alo + off);
        } else {
            uint4 z = make_uint4(0, 0, 0, 0);
            *reinterpret_cast<uint4*>(pAh) = z;
            *reinterpret_cast<uint4*>(pAl) = z;
        }
        __nv_bfloat16* pBh = base + 2 * ASZ + brow * LDB + bc8;
        const size_t boff = (size_t)(kb + brow) * N + bn + bc8;
        cp16((uint32_t)__cvta_generic_to_shared(pBh), Bhi + boff);
        cp16((uint32_t)__cvta_generic_to_shared(pBh + BSZ), Blo + boff);
        cp_commit();
    };

    const int nk = K >> 4;
    issue(0, 0);
    if (nk > 1) issue(16, 1);

    int s = 0;
    for (int it = 0; it < nk; ++it) {
        if (it + 2 < nk) { issue((it + 2) << 4, (it + 2) % 3); cp_wait<2>(); }
        else if (it + 1 < nk) { cp_wait<1>(); }
        else { cp_wait<0>(); }
        __syncthreads();

        const __nv_bfloat16* Ah = sm + s * STAGE_E;
        const __nv_bfloat16* Al = Ah + ASZ;
        const __nv_bfloat16* Bh = Ah + 2 * ASZ;
        const __nv_bfloat16* Bl = Bh + BSZ;

        wmma::fragment<wmma::matrix_a, 16, 16, 16, __nv_bfloat16, wmma::row_major> ah[4], al[4];
        wmma::fragment<wmma::matrix_b, 16, 16, 16, __nv_bfloat16, wmma::row_major> bh[2], bl[2];
#pragma unroll
        for (int i = 0; i < 4; i++) {
            wmma::load_matrix_sync(ah[i], Ah + (wm * 64 + i * 16) * LDA, LDA);
            wmma::load_matrix_sync(al[i], Al + (wm * 64 + i * 16) * LDA, LDA);
        }
#pragma unroll
        for (int j = 0; j < 2; j++) {
            wmma::load_matrix_sync(bh[j], Bh + wn * 32 + j * 16, LDB);
            wmma::load_matrix_sync(bl[j], Bl + wn * 32 + j * 16, LDB);
        }
#pragma unroll
        for (int i = 0; i < 4; i++)
#pragma unroll
            for (int j = 0; j < 2; j++) {
                wmma::mma_sync(acc[i][j], ah[i], bh[j], acc[i][j]);
                wmma::mma_sync(acc[i][j], ah[i], bl[j], acc[i][j]);
                wmma::mma_sync(acc[i][j], al[i], bh[j], acc[i][j]);
            }
        __syncthreads();
        s = (s + 1 == 3) ? 0 : s + 1;
    }

    // epilogue: stage each 16x16 frag through smem, add bias, guarded store
    float* wb = reinterpret_cast<float*>(sm) + warpId * 256; // 1KB per warp
#pragma unroll
    for (int i = 0; i < 4; i++)
#pragma unroll
        for (int j = 0; j < 2; j++) {
            wmma::store_matrix_sync(wb, acc[i][j], 16, wmma::mem_row_major);
            __syncwarp();
            const int r0 = bm + wm * 64 + i * 16;
            const int c0 = bn + wn * 32 + j * 16;

            float* fdst = nullptr;
            __half* hdst = nullptr;
            int lc, stride;
            if (c0 < HC)            { fdst = Q;  lc = c0;          stride = HC; }
            else if (c0 < 2 * HC)   { hdst = Ko; lc = c0 - HC;     stride = HC; }
            else if (c0 < 3 * HC)   { hdst = Vo; lc = c0 - 2 * HC; stride = HC; }
            else                    { fdst = S;  lc = c0 - 3 * HC; stride = C;  }

#pragma unroll
            for (int e = lane; e < 64; e += 32) {
                const int r = e >> 2, c4 = (e & 3) * 4;
                if (r0 + r >= M) continue;
                float4 vv = *reinterpret_cast<float4*>(wb + r * 16 + c4);
                const int col = c0 + c4;
                vv.x += bias[col + 0];
                vv.y += bias[col + 1];
                vv.z += bias[col + 2];
                vv.w += bias[col + 3];
                const size_t o = (size_t)(r0 + r) * stride + lc + c4;
                if (fdst) {
                    *reinterpret_cast<float4*>(fdst + o) = vv;
                } else {
                    uint2 p;
                    *reinterpret_cast<__half2*>(&p.x) = __floats2half2_rn(vv.x, vv.y);
                    *reinterpret_cast<__half2*>(&p.y) = __floats2half2_rn(vv.z, vv.w);
                    *reinterpret_cast<uint2*>(hdst + o) = p;
                }
            }
            __syncwarp();
        }
}

// ---------------- CSR build ----------------
__global__ void count_deg(const int* __restrict__ ei, int* __restrict__ deg, int E)
{
    int e = blockIdx.x * blockDim.x + threadIdx.x;
    if (e < E) atomicAdd(&deg[ei[E + e]], 1);
}

__global__ void scan_deg(const int* __restrict__ deg, int* __restrict__ ptr,
                         int* __restrict__ fill, int n)
{
    constexpr int PER = 10;
    const int tid = threadIdx.x;
    const int lane = tid & 31, wid = tid >> 5;
    const int base = tid * PER;

    int vals[PER];
    int s = 0;
#pragma unroll
    for (int i = 0; i < PER; i++) {
        const int idx = base + i;
        vals[i] = (idx < n) ? deg[idx] : 0;
        s += vals[i];
    }
    int sc = s;
#pragma unroll
    for (int o = 1; o < 32; o <<= 1) {
        int t = __shfl_up_sync(0xffffffffu, sc, o);
        if (lane >= o) sc += t;
    }
    __shared__ int wsum[32];
    if (lane == 31) wsum[wid] = sc;
    __syncthreads();
    if (wid == 0) {
        int w = wsum[lane];
#pragma unroll
        for (int o = 1; o < 32; o <<= 1) {
            int t = __shfl_up_sync(0xffffffffu, w, o);
            if (lane >= o) w += t;
        }
        wsum[lane] = w;
    }
    __syncthreads();
    int run = (sc - s) + (wid > 0 ? wsum[wid - 1] : 0);
#pragma unroll
    for (int i = 0; i < PER; i++) {
        const int idx = base + i;
        if (idx < n) { ptr[idx] = run; fill[idx] = run; }
        run += vals[i];
    }
    if (tid == 1023) ptr[n] = run;
}

__global__ void fill_csr(const int* __restrict__ ei, int* __restrict__ fill,
                         int* __restrict__ csr_src, int E)
{
    int e = blockIdx.x * blockDim.x + threadIdx.x;
    if (e < E) {
        const int d = ei[E + e];
        const int pos = atomicAdd(&fill[d], 1);
        csr_src[pos] = ei[e];
    }
}

// ---------------- fused attention aggregation ----------------
template <int C, bool SPLIT>
__global__ void attn_kernel(const float* __restrict__ q, const __half* __restrict__ k,
                            const __half* __restrict__ v, const int* __restrict__ ptr,
                            const int* __restrict__ csr_src, const float* __restrict__ skip,
                            float* __restrict__ out,
                            __nv_bfloat16* __restrict__ outHi, __nv_bfloat16* __restrict__ outLo)
{
    constexpr int H = HEADS;
    constexpr int F4 = C / 128;
    __shared__ float red[H * C];

    const int dst  = blockIdx.x;
    const int warp = threadIdx.x >> 5;
    const int lane = threadIdx.x & 31;
    const float scale = rsqrtf((float)C);
    const size_t HC = (size_t)H * C;

    const int beg = ptr[dst], end = ptr[dst + 1];

    const float4* qrow = reinterpret_cast<const float4*>(q + (size_t)dst * HC + warp * C);
    float4 qr[F4], acc[F4];
#pragma unroll
    for (int i = 0; i < F4; i++) {
        qr[i] = qrow[lane + 32 * i];
        acc[i] = make_float4(0.f, 0.f, 0.f, 0.f);
    }
    float m = -INFINITY, s = 0.f;

    for (int j = beg; j < end; j++) {
        const int src = csr_src[j];
        const uint2* krow = reinterpret_cast<const uint2*>(k + (size_t)src * HC + warp * C);
        const uint2* vrow = reinterpret_cast<const uint2*>(v + (size_t)src * HC + warp * C);
        float d = 0.f;
#pragma unroll
        for (int i = 0; i < F4; i++) {
            const uint2 kk = krow[lane + 32 * i];
            const float2 k0 = __half22float2(*reinterpret_cast<const __half2*>(&kk.x));
            const float2 k1 = __half22float2(*reinterpret_cast<const __half2*>(&kk.y));
            d += qr[i].x * k0.x + qr[i].y * k0.y + qr[i].z * k1.x + qr[i].w * k1.y;
        }
#pragma unroll
        for (int o = 16; o > 0; o >>= 1) d += __shfl_xor_sync(0xffffffffu, d, o);
        const float a = d * scale;
        const float mn = fmaxf(m, a);
        const float corr = expf(m - mn);
        const float w = expf(a - mn);
        s = s * corr + w;
        m = mn;
#pragma unroll
        for (int i = 0; i < F4; i++) {
            const uint2 vvp = vrow[lane + 32 * i];
            const float2 v0 = __half22float2(*reinterpret_cast<const __half2*>(&vvp.x));
            const float2 v1 = __half22float2(*reinterpret_cast<const __half2*>(&vvp.y));
            acc[i].x = acc[i].x * corr + w * v0.x;
            acc[i].y = acc[i].y * corr + w * v0.y;
            acc[i].z = acc[i].z * corr + w * v1.x;
            acc[i].w = acc[i].w * corr + w * v1.y;
        }
    }

    const float inv = (end > beg) ? (1.f / (s + 1e-16f)) : 0.f;
#pragma unroll
    for (int i = 0; i < F4; i++) {
        float4 o = make_float4(acc[i].x * inv, acc[i].y * inv, acc[i].z * inv, acc[i].w * inv);
        *reinterpret_cast<float4*>(&red[warp * C + i * 128 + lane * 4]) = o;
    }
    __syncthreads();

    for (int f = threadIdx.x; f < C; f += blockDim.x) {
        float t = 0.f;
#pragma unroll
        for (int h = 0; h < H; h++) t += red[h * C + f];
        t = t * (1.f / H) + skip[(size_t)dst * C + f];
        t = (t > 0.f) ? t : expm1f(t);
        const size_t idx = (size_t)dst * C + f;
        if constexpr (SPLIT) {
            __nv_bfloat16 hh = __float2bfloat16(t);
            outHi[idx] = hh;
            outLo[idx] = __float2bfloat16(t - __bfloat162float(hh));
        } else {
            out[idx] = t;
        }
    }
}

// ---------------- global attention pooling ----------------
__global__ void init_gmax(float* gmax)
{
    if (threadIdx.x < N_GRAPHS) gmax[threadIdx.x] = -INFINITY;
}

__global__ void gate_kernel(const float* __restrict__ h, const float* __restrict__ wg,
                            const float* __restrict__ bg, const int* __restrict__ batch,
                            float* __restrict__ gate, float* __restrict__ gmax, int n)
{
    const int node = (blockIdx.x * blockDim.x + threadIdx.x) >> 5;
    const int lane = threadIdx.x & 31;
    if (node >= n) return;
    const float* row = h + (size_t)node * D3;
    float d = 0.f;
#pragma unroll
    for (int i = 0; i < D3 / 32; i++) d += row[lane + 32 * i] * wg[lane + 32 * i];
#pragma unroll
    for (int o = 16; o > 0; o >>= 1) d += __shfl_xor_sync(0xffffffffu, d, o);
    if (lane == 0) {
        d += bg[0];
        gate[node] = d;
        float* addr = &gmax[batch[node]];
        if (d >= 0.f) atomicMax((int*)addr, __float_as_int(d));
        else          atomicMin((unsigned int*)addr, __float_as_uint(d));
    }
}

__global__ void exp_pool(const float* __restrict__ h, const float* __restrict__ gate,
                         const int* __restrict__ batch, const float* __restrict__ gmax,
                         float* __restrict__ gsum, float* __restrict__ pool)
{
    const int node = blockIdx.x;
    const int f = threadIdx.x;
    const int b = batch[node];
    const float e = expf(gate[node] - gmax[b]);
    if (f == 0) atomicAdd(&gsum[b], e);
    atomicAdd(&pool[b * D3 + f], e * h[(size_t)node * D3 + f]);
}

__global__ void fc_kernel(const float* __restrict__ pool, const float* __restrict__ gsum,
                          const float* __restrict__ wfc, const float* __restrict__ bfc,
                          float* __restrict__ out)
{
    const int t = threadIdx.x;
    if (t >= N_GRAPHS * OUT_DIM) return;
    const int g = t / OUT_DIM, o = t % OUT_DIM;
    float s = 0.f;
#pragma unroll 16
    for (int f = 0; f < D3; f++) s += pool[g * D3 + f] * wfc[f * OUT_DIM + o];
    out[g * OUT_DIM + o] = s / (gsum[g] + 1e-16f) + bfc[o];
}

// ---------------- launch ----------------
extern "C" void kernel_launch(void* const* d_in, const int* in_sizes, int n_in,
                              void* d_out, int out_size)
{
    const float* x     = (const float*)d_in[0];
    const int*   ei    = (const int*)d_in[1];
    const int*   batch = (const int*)d_in[2];
    const float* W[12] = { (const float*)d_in[3],  (const float*)d_in[5],
                           (const float*)d_in[7],  (const float*)d_in[9],
                           (const float*)d_in[11], (const float*)d_in[13],
                           (const float*)d_in[15], (const float*)d_in[17],
                           (const float*)d_in[19], (const float*)d_in[21],
                           (const float*)d_in[23], (const float*)d_in[25] };
    const float* Bv[12] = { (const float*)d_in[4],  (const float*)d_in[6],
                            (const float*)d_in[8],  (const float*)d_in[10],
                            (const float*)d_in[12], (const float*)d_in[14],
                            (const float*)d_in[16], (const float*)d_in[18],
                            (const float*)d_in[20], (const float*)d_in[22],
                            (const float*)d_in[24], (const float*)d_in[26] };
    const float* w_g  = (const float*)d_in[27]; const float* b_g  = (const float*)d_in[28];
    const float* w_fc = (const float*)d_in[29]; const float* b_fc = (const float*)d_in[30];
    float* out = (float*)d_out;

    float *qb, *skipb, *hA, *gateb, *gmaxb, *gsumb, *poolb, *biasb;
    __half *kb, *vb;
    __nv_bfloat16 *Ahi, *Alo, *Whi, *Wlo;
    int *degb, *ptrb, *fillb, *csrb;
    cudaGetSymbolAddress((void**)&qb,    g_q);
    cudaGetSymbolAddress((void**)&kb,    g_k);
    cudaGetSymbolAddress((void**)&vb,    g_v);
    cudaGetSymbolAddress((void**)&skipb, g_skip);
    cudaGetSymbolAddress((void**)&hA,    g_hA);
    cudaGetSymbolAddress((void**)&Ahi,   g_Ahi);
    cudaGetSymbolAddress((void**)&Alo,   g_Alo);
    cudaGetSymbolAddress((void**)&Whi,   g_Whi);
    cudaGetSymbolAddress((void**)&Wlo,   g_Wlo);
    cudaGetSymbolAddress((void**)&biasb, g_bias);
    cudaGetSymbolAddress((void**)&degb,  g_deg);
    cudaGetSymbolAddress((void**)&ptrb,  g_ptr);
    cudaGetSymbolAddress((void**)&fillb, g_fill);
    cudaGetSymbolAddress((void**)&csrb,  g_csr_src);
    cudaGetSymbolAddress((void**)&gateb, g_gate);
    cudaGetSymbolAddress((void**)&gmaxb, g_gmax);
    cudaGetSymbolAddress((void**)&gsumb, g_gsum);
    cudaGetSymbolAddress((void**)&poolb, g_pool);

    const int N = N_NODES, E = N_EDGES;

    static bool attrSet = false;
    if (!attrSet) {
        cudaFuncSetAttribute(gemm_fused, cudaFuncAttributeMaxDynamicSharedMemorySize,
                             GEMM_SMEM_BYTES);
        attrSet = true;
    }

    // region tables
    const int Kl[3]    = { F_IN, D1, D2 };
    const int HCl[3]   = { HEADS * D1, HEADS * D2, HEADS * D3 };
    const int Cl[3]    = { D1, D2, D3 };
    const int NTl[3]   = { NTOT1, NTOT2, NTOT3 };
    const long long WBl[3] = { WBASE1, WBASE2, WBASE3 };
    const int BBl[3]   = { BBASE1, BBASE2, BBASE3 };

    PackArgs P;
    long long wcum = 0;
    int bcum = 0;
    for (int l = 0; l < 3; l++) {
        for (int p = 0; p < 4; p++) {
            const int r = l * 4 + p;
            const int ncols = (p < 3) ? HCl[l] : Cl[l];
            const int coff  = (p < 3) ? p * HCl[l] : 3 * HCl[l];
            P.wsrc[r] = W[r];
            P.wcum[r] = wcum;
            P.wncols[r] = ncols;
            P.wdstBase[r] = WBl[l];
            P.wntot[r] = NTl[l];
            P.wcoff[r] = coff;
            wcum += (long long)Kl[l] * ncols;
            P.bsrc[r] = Bv[r];
            P.bcum[r] = bcum;
            P.boff[r] = BBl[l] + coff;
            bcum += ncols;
        }
    }
    P.wcum[12] = wcum;
    P.bcum[12] = bcum;
    P.x = x;

    const long long packTotal = wcum + NXTOT + bcum;

    // launch order: gemm_fused L1 is the 5th launch (ncu capture slot)
    pack_all<<<(int)((packTotal + 255) / 256), 256>>>(P, Whi, Wlo, Ahi, Alo, biasb,
                                                      wcum, NXTOT, bcum);               // 1
    cudaMemsetAsync(degb, 0, N * sizeof(int));                                          // 2
    count_deg<<<(E + 255) / 256, 256>>>(ei, degb, E);                                   // 3
    scan_deg<<<1, 1024>>>(degb, ptrb, fillb, N);                                        // 4
    {
        dim3 grid(NTOT1 / 128, (N + 127) / 128);                                        // 5 <- profiled
        gemm_fused<<<grid, 256, GEMM_SMEM_BYTES>>>(Ahi, Alo, Whi + WBASE1, Wlo + WBASE1,
                                                   biasb + BBASE1, qb, kb, vb, skipb,
                                                   N, NTOT1, F_IN, HEADS * D1, D1);
    }
    fill_csr<<<(E + 255) / 256, 256>>>(ei, fillb, csrb, E);                             // 6
    attn_kernel<D1, true><<<N, 256>>>(qb, kb, vb, ptrb, csrb, skipb, nullptr, Ahi, Alo);

    {
        dim3 grid(NTOT2 / 128, (N + 127) / 128);
        gemm_fused<<<grid, 256, GEMM_SMEM_BYTES>>>(Ahi, Alo, Whi + WBASE2, Wlo + WBASE2,
                                                   biasb + BBASE2, qb, kb, vb, skipb,
                                                   N, NTOT2, D1, HEADS * D2, D2);
    }
    attn_kernel<D2, true><<<N, 256>>>(qb, kb, vb, ptrb, csrb, skipb, nullptr, Ahi, Alo);

    {
        dim3 grid(NTOT3 / 128, (N + 127) / 128);
        gemm_fused<<<grid, 256, GEMM_SMEM_BYTES>>>(Ahi, Alo, Whi + WBASE3, Wlo + WBASE3,
                                                   biasb + BBASE3, qb, kb, vb, skipb,
                                                   N, NTOT3, D2, HEADS * D3, D3);
    }
    attn_kernel<D3, false><<<N, 256>>>(qb, kb, vb, ptrb, csrb, skipb, hA, nullptr, nullptr);

    // ---- pooling + fc ----
    init_gmax<<<1, 64>>>(gmaxb);
    cudaMemsetAsync(gsumb, 0, N_GRAPHS * sizeof(float));
    cudaMemsetAsync(poolb, 0, N_GRAPHS * D3 * sizeof(float));
    gate_kernel<<<(N * 32 + 255) / 256, 256>>>(hA, w_g, b_g, batch, gateb, gmaxb, N);
    exp_pool<<<N, D3>>>(hA, gateb, batch, gmaxb, gsumb, poolb);
    fc_kernel<<<1, 1024>>>(poolb, gsumb, w_fc, b_fc, out);
}

// round 10
// speedup vs baseline: 1.3379x; 1.1411x over previous
#include <cuda_runtime.h>
#include <cuda_bf16.h>
#include <cuda_fp16.h>
#include <mma.h>
#include <math.h>
#include <stdint.h>

using namespace nvcuda;

// ---------------- problem constants ----------------
#define N_NODES 10000
#define N_EDGES 80000
#define N_GRAPHS 64
#define HEADS 8
#define F_IN 128
#define D1 512
#define D2 256
#define D3 128
#define OUT_DIM 10

// layer-1 factored layout: [ z(1024) | extras(128) | v(4096) | skip(512) ]
#define ZCOLS (HEADS * F_IN)          // 1024
#define MCOLS (ZCOLS + 128)           // 1152 (z + extras)
#define NTOT1 (MCOLS + HEADS * D1 + D1)   // 5760
#define NTOT2 (HEADS * D2 * 3 + D2)   // 6400
#define NTOT3 (HEADS * D3 * 3 + D3)   // 3200
#define WBASE1 0LL
#define WBASE2 ((long long)F_IN * NTOT1)
#define WBASE3 (WBASE2 + (long long)D1 * NTOT2)
#define WTOTAL (WBASE3 + (long long)D2 * NTOT3)
#define BBASE1 0
#define BBASE2 NTOT1
#define BBASE3 (NTOT1 + NTOT2)
#define BTOTAL (NTOT1 + NTOT2 + NTOT3)
#define NXTOT (N_NODES * F_IN)

// ---------------- device scratch (static, no allocs) ----------------
__device__ float g_q[(size_t)N_NODES * (HEADS * D1)];      // q (L2/L3) or z (L1, stride 1024)
__device__ __half g_k[(size_t)N_NODES * (HEADS * D1)];
__device__ __half g_v[(size_t)N_NODES * (HEADS * D1)];
__device__ float g_skip[(size_t)N_NODES * D1];
__device__ float g_hA[(size_t)N_NODES * D1];

__device__ float g_extras[(size_t)N_NODES * 128];          // alpha(8) beta(8) pad
__device__ __half g_x16[(size_t)N_NODES * F_IN];           // x in fp16 for edge gather
__device__ float g_Mfull[F_IN * MCOLS];                    // WqWk^T + cross vectors
__device__ float g_Mbias[MCOLS];                           // bq.bk consts for alpha cols

__device__ __nv_bfloat16 g_Ahi[(size_t)N_NODES * D1];
__device__ __nv_bfloat16 g_Alo[(size_t)N_NODES * D1];
__device__ __nv_bfloat16 g_Whi[WTOTAL];
__device__ __nv_bfloat16 g_Wlo[WTOTAL];
__device__ float g_bias[BTOTAL];

__device__ int g_deg[N_NODES];
__device__ int g_ptr[N_NODES + 1];
__device__ int g_fill[N_NODES];
__device__ int g_csr_src[N_EDGES];

__device__ float g_gate[N_NODES];
__device__ float g_gmax[N_GRAPHS];
__device__ float g_gsum[N_GRAPHS];
__device__ float g_pool[N_GRAPHS * D3];

// ---------------- cp.async helpers ----------------
__device__ __forceinline__ void cp16(uint32_t dst, const void* src)
{
    asm volatile("cp.async.cg.shared.global [%0], [%1], 16;" :: "r"(dst), "l"(src));
}
__device__ __forceinline__ void cp_commit() { asm volatile("cp.async.commit_group;"); }
template <int Np>
__device__ __forceinline__ void cp_wait() { asm volatile("cp.async.wait_group %0;" :: "n"(Np)); }

// ---------------- layer-1 factorization precompute ----------------
// col j<1024: M_h[:,jj] = Wq_h @ Wk_h[jj,:]  (h=j>>7, jj=j&127)
// col 1024+h: Wq_h @ bk_h ;  col 1032+h: Wk_h @ bq_h ;  cols >=1040: zero
__global__ void make_m(const float* __restrict__ wq, const float* __restrict__ wk,
                       const float* __restrict__ bq, const float* __restrict__ bk,
                       float* __restrict__ Mfull, float* __restrict__ Mbias)
{
    __shared__ float col[D1];
    __shared__ float red[128];
    const int j = blockIdx.x;          // 0..MCOLS-1
    const int tid = threadIdx.x;       // 128

    if (j >= 1040) {
        Mfull[tid * MCOLS + j] = 0.f;
        if (tid == 0) Mbias[j] = 0.f;
        return;
    }

    int h;
    const float* mat;
    if (j < ZCOLS)        { h = j >> 7;   mat = wq; }
    else if (j < 1032)    { h = j - 1024; mat = wq; }
    else                  { h = j - 1032; mat = wk; }
    const int base = h * D1;

    if (j < ZCOLS) {
        const int jj = j & 127;
        for (int c = tid; c < D1; c += 128) col[c] = wk[(size_t)jj * (HEADS * D1) + base + c];
    } else if (j < 1032) {
        for (int c = tid; c < D1; c += 128) col[c] = bk[base + c];
    } else {
        for (int c = tid; c < D1; c += 128) col[c] = bq[base + c];
    }
    __syncthreads();

    const float4* row4 = reinterpret_cast<const float4*>(mat + (size_t)tid * (HEADS * D1) + base);
    float acc = 0.f;
#pragma unroll 4
    for (int c = 0; c < D1 / 4; c++) {
        const float4 r = row4[c];
        acc += r.x * col[c * 4 + 0] + r.y * col[c * 4 + 1]
             + r.z * col[c * 4 + 2] + r.w * col[c * 4 + 3];
    }
    Mfull[tid * MCOLS + j] = acc;

    if (j >= ZCOLS && j < 1032) {
        float p = 0.f;
        for (int c = tid; c < D1; c += 128) p += bq[base + c] * bk[base + c];
        red[tid] = p;
        __syncthreads();
        if (tid < 64) red[tid] += red[tid + 64];
        __syncthreads();
        if (tid < 32) {
            float t = red[tid] + red[tid + 32];
#pragma unroll
            for (int o = 16; o > 0; o >>= 1) t += __shfl_down_sync(0xffffffffu, t, o);
            if (tid == 0) Mbias[j] = t;
        }
    } else {
        if (tid == 0) Mbias[j] = 0.f;
    }
}

// ---------------- one-shot packing: weights + x split/x16 + bias ----------------
struct PackArgs {
    const float* wsrc[12];
    long long wcum[13];
    int wncols[12];
    long long wdstBase[12];
    int wntot[12];
    int wcoff[12];
    const float* bsrc[12];
    int bcum[13];
    int boff[12];
    const float* x;
};

__global__ void pack_all(PackArgs P, __nv_bfloat16* __restrict__ Whi, __nv_bfloat16* __restrict__ Wlo,
                         __nv_bfloat16* __restrict__ Ahi, __nv_bfloat16* __restrict__ Alo,
                         __half* __restrict__ x16,
                         float* __restrict__ bias, long long wtotal, long long xtotal, int btotal)
{
    long long i = (long long)blockIdx.x * blockDim.x + threadIdx.x;
    if (i < wtotal) {
        int r = 0;
        while (i >= P.wcum[r + 1]) r++;
        const long long li = i - P.wcum[r];
        const int nc = P.wncols[r];
        const int k = (int)(li / nc), c = (int)(li % nc);
        const float v = P.wsrc[r][li];
        const long long di = P.wdstBase[r] + (long long)k * P.wntot[r] + P.wcoff[r] + c;
        __nv_bfloat16 h = __float2bfloat16(v);
        Whi[di] = h;
        Wlo[di] = __float2bfloat16(v - __bfloat162float(h));
        return;
    }
    i -= wtotal;
    if (i < xtotal) {
        const float v = P.x[i];
        __nv_bfloat16 h = __float2bfloat16(v);
        Ahi[i] = h;
        Alo[i] = __float2bfloat16(v - __bfloat162float(h));
        x16[i] = __float2half(v);
        return;
    }
    int j = (int)(i - xtotal);
    if (j < btotal) {
        int r = 0;
        while (j >= P.bcum[r + 1]) r++;
        bias[P.boff[r] + (j - P.bcum[r])] = P.bsrc[r][j - P.bcum[r]];
    }
}

// ---------------- fused bf16x3 tensor-core GEMM, table-routed epilogue ----------------
struct EpiTab {
    float* f[4];        // fp32 dst or null
    __half* h[4];       // fp16 dst or null
    int stride[4];
    int start[4];       // start[0] = 0; boundaries are multiples of 128
};

#define LDA 24
#define LDB 136
#define ASZ (128 * LDA)
#define BSZ (16 * LDB)
#define STAGE_E (2 * ASZ + 2 * BSZ)

__global__ __launch_bounds__(256, 2)
void gemm_fused(const __nv_bfloat16* __restrict__ Ahi, const __nv_bfloat16* __restrict__ Alo,
                const __nv_bfloat16* __restrict__ Bhi, const __nv_bfloat16* __restrict__ Blo,
                const float* __restrict__ bias, EpiTab T,
                int M, int N, int K)
{
    __shared__ __align__(16) __nv_bfloat16 sm[2 * STAGE_E];

    const int tid = threadIdx.x;
    const int warpId = tid >> 5;
    const int lane = tid & 31;
    const int wm = warpId >> 2;
    const int wn = warpId & 3;
    const int bm = blockIdx.y * 128;
    const int bn = blockIdx.x * 128;

    const int arow = tid >> 1, ac8 = (tid & 1) * 8;
    const int brow = tid >> 4, bc8 = (tid & 15) * 8;

    wmma::fragment<wmma::accumulator, 16, 16, 16, float> acc[4][2];
#pragma unroll
    for (int i = 0; i < 4; i++)
#pragma unroll
        for (int j = 0; j < 2; j++) wmma::fill_fragment(acc[i][j], 0.f);

    auto issue = [&](int kb, int s) {
        __nv_bfloat16* base = sm + s * STAGE_E;
        __nv_bfloat16* pAh = base + arow * LDA + ac8;
        __nv_bfloat16* pAl = pAh + ASZ;
        const int gr = bm + arow;
        if (gr < M) {
            const size_t off = (size_t)gr * K + kb + ac8;
            cp16((uint32_t)__cvta_generic_to_shared(pAh), Ahi + off);
            cp16((uint32_t)__cvta_generic_to_shared(pAl), Alo + off);
        } else {
            uint4 z = make_uint4(0, 0, 0, 0);
            *reinterpret_cast<uint4*>(pAh) = z;
            *reinterpret_cast<uint4*>(pAl) = z;
        }
        __nv_bfloat16* pBh = base + 2 * ASZ + brow * LDB + bc8;
        const size_t boff = (size_t)(kb + brow) * N + bn + bc8;
        cp16((uint32_t)__cvta_generic_to_shared(pBh), Bhi + boff);
        cp16((uint32_t)__cvta_generic_to_shared(pBh + BSZ), Blo + boff);
        cp_commit();
    };

    const int nk = K >> 4;
    issue(0, 0);

    for (int it = 0; it < nk; ++it) {
        const int s = it & 1;
        if (it + 1 < nk) { issue((it + 1) << 4, s ^ 1); cp_wait<1>(); }
        else             { cp_wait<0>(); }
        __syncthreads();

        const __nv_bfloat16* Ah = sm + s * STAGE_E;
        const __nv_bfloat16* Al = Ah + ASZ;
        const __nv_bfloat16* Bh = Ah + 2 * ASZ;
        const __nv_bfloat16* Bl = Bh + BSZ;

        wmma::fragment<wmma::matrix_a, 16, 16, 16, __nv_bfloat16, wmma::row_major> ah[4], al[4];
        wmma::fragment<wmma::matrix_b, 16, 16, 16, __nv_bfloat16, wmma::row_major> bh[2], bl[2];
#pragma unroll
        for (int i = 0; i < 4; i++) {
            wmma::load_matrix_sync(ah[i], Ah + (wm * 64 + i * 16) * LDA, LDA);
            wmma::load_matrix_sync(al[i], Al + (wm * 64 + i * 16) * LDA, LDA);
        }
#pragma unroll
        for (int j = 0; j < 2; j++) {
            wmma::load_matrix_sync(bh[j], Bh + wn * 32 + j * 16, LDB);
            wmma::load_matrix_sync(bl[j], Bl + wn * 32 + j * 16, LDB);
        }
#pragma unroll
        for (int i = 0; i < 4; i++)
#pragma unroll
            for (int j = 0; j < 2; j++) {
                wmma::mma_sync(acc[i][j], ah[i], bh[j], acc[i][j]);
                wmma::mma_sync(acc[i][j], ah[i], bl[j], acc[i][j]);
                wmma::mma_sync(acc[i][j], al[i], bh[j], acc[i][j]);
            }
        __syncthreads();
    }

    // region is uniform per CTA (all boundaries are multiples of 128)
    const int r = (bn >= T.start[3]) ? 3 : (bn >= T.start[2]) ? 2 : (bn >= T.start[1]) ? 1 : 0;
    float* fdst = T.f[r];
    __half* hdst = T.h[r];
    const int lcb = bn - T.start[r];
    const int stride = T.stride[r];

    float* wb = reinterpret_cast<float*>(sm) + warpId * 256;
#pragma unroll
    for (int i = 0; i < 4; i++)
#pragma unroll
        for (int j = 0; j < 2; j++) {
            wmma::store_matrix_sync(wb, acc[i][j], 16, wmma::mem_row_major);
            __syncwarp();
            const int r0 = bm + wm * 64 + i * 16;
            const int c0 = bn + wn * 32 + j * 16;
#pragma unroll
            for (int e = lane; e < 64; e += 32) {
                const int rr = e >> 2, c4 = (e & 3) * 4;
                if (r0 + rr >= M) continue;
                float4 vv = *reinterpret_cast<float4*>(wb + rr * 16 + c4);
                const int col = c0 + c4;
                vv.x += bias[col + 0];
                vv.y += bias[col + 1];
                vv.z += bias[col + 2];
                vv.w += bias[col + 3];
                const size_t o = (size_t)(r0 + rr) * stride + (lcb + (col - bn));
                if (fdst) {
                    *reinterpret_cast<float4*>(fdst + o) = vv;
                } else {
                    uint2 p;
                    *reinterpret_cast<__half2*>(&p.x) = __floats2half2_rn(vv.x, vv.y);
                    *reinterpret_cast<__half2*>(&p.y) = __floats2half2_rn(vv.z, vv.w);
                    *reinterpret_cast<uint2*>(hdst + o) = p;
                }
            }
            __syncwarp();
        }
}

// ---------------- CSR build ----------------
__global__ void count_deg(const int* __restrict__ ei, int* __restrict__ deg, int E)
{
    int e = blockIdx.x * blockDim.x + threadIdx.x;
    if (e < E) atomicAdd(&deg[ei[E + e]], 1);
}

__global__ void scan_deg(const int* __restrict__ deg, int* __restrict__ ptr,
                         int* __restrict__ fill, int n)
{
    constexpr int PER = 10;
    const int tid = threadIdx.x;
    const int lane = tid & 31, wid = tid >> 5;
    const int base = tid * PER;

    int vals[PER];
    int s = 0;
#pragma unroll
    for (int i = 0; i < PER; i++) {
        const int idx = base + i;
        vals[i] = (idx < n) ? deg[idx] : 0;
        s += vals[i];
    }
    int sc = s;
#pragma unroll
    for (int o = 1; o < 32; o <<= 1) {
        int t = __shfl_up_sync(0xffffffffu, sc, o);
        if (lane >= o) sc += t;
    }
    __shared__ int wsum[32];
    if (lane == 31) wsum[wid] = sc;
    __syncthreads();
    if (wid == 0) {
        int w = wsum[lane];
#pragma unroll
        for (int o = 1; o < 32; o <<= 1) {
            int t = __shfl_up_sync(0xffffffffu, w, o);
            if (lane >= o) w += t;
        }
        wsum[lane] = w;
    }
    __syncthreads();
    int run = (sc - s) + (wid > 0 ? wsum[wid - 1] : 0);
#pragma unroll
    for (int i = 0; i < PER; i++) {
        const int idx = base + i;
        if (idx < n) { ptr[idx] = run; fill[idx] = run; }
        run += vals[i];
    }
    if (tid == 1023) ptr[n] = run;
}

__global__ void fill_csr(const int* __restrict__ ei, int* __restrict__ fill,
                         int* __restrict__ csr_src, int E)
{
    int e = blockIdx.x * blockDim.x + threadIdx.x;
    if (e < E) {
        const int d = ei[E + e];
        const int pos = atomicAdd(&fill[d], 1);
        csr_src[pos] = ei[e];
    }
}

// ---------------- layer-1 attention (factored logits) ----------------
// logit = (z_dst_h . x_src + alpha_dst_h + beta_src_h) / sqrt(D1)
__global__ void attn1_kernel(const float* __restrict__ z, const __half* __restrict__ x16,
                             const float* __restrict__ ex, const __half* __restrict__ v,
                             const int* __restrict__ ptr, const int* __restrict__ csr_src,
                             const float* __restrict__ skip,
                             __nv_bfloat16* __restrict__ outHi, __nv_bfloat16* __restrict__ outLo)
{
    constexpr int C = D1;        // 512 head channels (scale + v width)
    constexpr int F4 = C / 128;  // 4 v-chunks per lane
    __shared__ float red[HEADS * C];

    const int dst  = blockIdx.x;
    const int warp = threadIdx.x >> 5;
    const int lane = threadIdx.x & 31;
    const float scale = rsqrtf((float)C);

    const int beg = ptr[dst], end = ptr[dst + 1];

    const float4 zr = reinterpret_cast<const float4*>(z + (size_t)dst * ZCOLS + warp * F_IN)[lane];
    const float alpha = ex[(size_t)dst * 128 + warp];

    float4 acc[F4];
#pragma unroll
    for (int i = 0; i < F4; i++) acc[i] = make_float4(0.f, 0.f, 0.f, 0.f);
    float m = -INFINITY, s = 0.f;

    for (int j = beg; j < end; j++) {
        const int src = csr_src[j];
        const uint2 xx = reinterpret_cast<const uint2*>(x16 + (size_t)src * F_IN)[lane];
        const float2 x0 = __half22float2(*reinterpret_cast<const __half2*>(&xx.x));
        const float2 x1 = __half22float2(*reinterpret_cast<const __half2*>(&xx.y));
        float d = zr.x * x0.x + zr.y * x0.y + zr.z * x1.x + zr.w * x1.y;
#pragma unroll
        for (int o = 16; o > 0; o >>= 1) d += __shfl_xor_sync(0xffffffffu, d, o);
        const float beta = ex[(size_t)src * 128 + 8 + warp];
        const float a = (d + alpha + beta) * scale;
        const float mn = fmaxf(m, a);
        const float corr = expf(m - mn);
        const float w = expf(a - mn);
        s = s * corr + w;
        m = mn;
        const uint2* vrow = reinterpret_cast<const uint2*>(v + (size_t)src * (HEADS * C) + warp * C);
#pragma unroll
        for (int i = 0; i < F4; i++) {
            const uint2 vvp = vrow[lane + 32 * i];
            const float2 v0 = __half22float2(*reinterpret_cast<const __half2*>(&vvp.x));
            const float2 v1 = __half22float2(*reinterpret_cast<const __half2*>(&vvp.y));
            acc[i].x = acc[i].x * corr + w * v0.x;
            acc[i].y = acc[i].y * corr + w * v0.y;
            acc[i].z = acc[i].z * corr + w * v1.x;
            acc[i].w = acc[i].w * corr + w * v1.y;
        }
    }

    const float inv = (end > beg) ? (1.f / (s + 1e-16f)) : 0.f;
#pragma unroll
    for (int i = 0; i < F4; i++) {
        float4 o = make_float4(acc[i].x * inv, acc[i].y * inv, acc[i].z * inv, acc[i].w * inv);
        *reinterpret_cast<float4*>(&red[warp * C + i * 128 + lane * 4]) = o;
    }
    __syncthreads();

    for (int f = threadIdx.x; f < C; f += blockDim.x) {
        float t = 0.f;
#pragma unroll
        for (int h = 0; h < HEADS; h++) t += red[h * C + f];
        t = t * (1.f / HEADS) + skip[(size_t)dst * C + f];
        t = (t > 0.f) ? t : expm1f(t);
        const size_t idx = (size_t)dst * C + f;
        __nv_bfloat16 hh = __float2bfloat16(t);
        outHi[idx] = hh;
        outLo[idx] = __float2bfloat16(t - __bfloat162float(hh));
    }
}

// ---------------- layers 2/3 attention (q.k form) ----------------
template <int C, bool SPLIT>
__global__ void attn_kernel(const float* __restrict__ q, const __half* __restrict__ k,
                            const __half* __restrict__ v, const int* __restrict__ ptr,
                            const int* __restrict__ csr_src, const float* __restrict__ skip,
                            float* __restrict__ out,
                            __nv_bfloat16* __restrict__ outHi, __nv_bfloat16* __restrict__ outLo)
{
    constexpr int H = HEADS;
    constexpr int F4 = C / 128;
    __shared__ float red[H * C];

    const int dst  = blockIdx.x;
    const int warp = threadIdx.x >> 5;
    const int lane = threadIdx.x & 31;
    const float scale = rsqrtf((float)C);
    const size_t HC = (size_t)H * C;

    const int beg = ptr[dst], end = ptr[dst + 1];

    const float4* qrow = reinterpret_cast<const float4*>(q + (size_t)dst * HC + warp * C);
    float4 qr[F4], acc[F4];
#pragma unroll
    for (int i = 0; i < F4; i++) {
        qr[i] = qrow[lane + 32 * i];
        acc[i] = make_float4(0.f, 0.f, 0.f, 0.f);
    }
    float m = -INFINITY, s = 0.f;

    for (int j = beg; j < end; j++) {
        const int src = csr_src[j];
        const uint2* krow = reinterpret_cast<const uint2*>(k + (size_t)src * HC + warp * C);
        const uint2* vrow = reinterpret_cast<const uint2*>(v + (size_t)src * HC + warp * C);
        float d = 0.f;
#pragma unroll
        for (int i = 0; i < F4; i++) {
            const uint2 kk = krow[lane + 32 * i];
            const float2 k0 = __half22float2(*reinterpret_cast<const __half2*>(&kk.x));
            const float2 k1 = __half22float2(*reinterpret_cast<const __half2*>(&kk.y));
            d += qr[i].x * k0.x + qr[i].y * k0.y + qr[i].z * k1.x + qr[i].w * k1.y;
        }
#pragma unroll
        for (int o = 16; o > 0; o >>= 1) d += __shfl_xor_sync(0xffffffffu, d, o);
        const float a = d * scale;
        const float mn = fmaxf(m, a);
        const float corr = expf(m - mn);
        const float w = expf(a - mn);
        s = s * corr + w;
        m = mn;
#pragma unroll
        for (int i = 0; i < F4; i++) {
            const uint2 vvp = vrow[lane + 32 * i];
            const float2 v0 = __half22float2(*reinterpret_cast<const __half2*>(&vvp.x));
            const float2 v1 = __half22float2(*reinterpret_cast<const __half2*>(&vvp.y));
            acc[i].x = acc[i].x * corr + w * v0.x;
            acc[i].y = acc[i].y * corr + w * v0.y;
            acc[i].z = acc[i].z * corr + w * v1.x;
            acc[i].w = acc[i].w * corr + w * v1.y;
        }
    }

    const float inv = (end > beg) ? (1.f / (s + 1e-16f)) : 0.f;
#pragma unroll
    for (int i = 0; i < F4; i++) {
        float4 o = make_float4(acc[i].x * inv, acc[i].y * inv, acc[i].z * inv, acc[i].w * inv);
        *reinterpret_cast<float4*>(&red[warp * C + i * 128 + lane * 4]) = o;
    }
    __syncthreads();

    for (int f = threadIdx.x; f < C; f += blockDim.x) {
        float t = 0.f;
#pragma unroll
        for (int h = 0; h < H; h++) t += red[h * C + f];
        t = t * (1.f / H) + skip[(size_t)dst * C + f];
        t = (t > 0.f) ? t : expm1f(t);
        const size_t idx = (size_t)dst * C + f;
        if constexpr (SPLIT) {
            __nv_bfloat16 hh = __float2bfloat16(t);
            outHi[idx] = hh;
            outLo[idx] = __float2bfloat16(t - __bfloat162float(hh));
        } else {
            out[idx] = t;
        }
    }
}

// ---------------- global attention pooling ----------------
__global__ void init_gmax(float* gmax)
{
    if (threadIdx.x < N_GRAPHS) gmax[threadIdx.x] = -INFINITY;
}

__global__ void gate_kernel(const float* __restrict__ h, const float* __restrict__ wg,
                            const float* __restrict__ bg, const int* __restrict__ batch,
                            float* __restrict__ gate, float* __restrict__ gmax, int n)
{
    const int node = (blockIdx.x * blockDim.x + threadIdx.x) >> 5;
    const int lane = threadIdx.x & 31;
    if (node >= n) return;
    const float* row = h + (size_t)node * D3;
    float d = 0.f;
#pragma unroll
    for (int i = 0; i < D3 / 32; i++) d += row[lane + 32 * i] * wg[lane + 32 * i];
#pragma unroll
    for (int o = 16; o > 0; o >>= 1) d += __shfl_xor_sync(0xffffffffu, d, o);
    if (lane == 0) {
        d += bg[0];
        gate[node] = d;
        float* addr = &gmax[batch[node]];
        if (d >= 0.f) atomicMax((int*)addr, __float_as_int(d));
        else          atomicMin((unsigned int*)addr, __float_as_uint(d));
    }
}

__global__ void exp_pool(const float* __restrict__ h, const float* __restrict__ gate,
                         const int* __restrict__ batch, const float* __restrict__ gmax,
                         float* __restrict__ gsum, float* __restrict__ pool)
{
    const int node = blockIdx.x;
    const int f = threadIdx.x;
    const int b = batch[node];
    const float e = expf(gate[node] - gmax[b]);
    if (f == 0) atomicAdd(&gsum[b], e);
    atomicAdd(&pool[b * D3 + f], e * h[(size_t)node * D3 + f]);
}

__global__ void fc_kernel(const float* __restrict__ pool, const float* __restrict__ gsum,
                          const float* __restrict__ wfc, const float* __restrict__ bfc,
                          float* __restrict__ out)
{
    const int t = threadIdx.x;
    if (t >= N_GRAPHS * OUT_DIM) return;
    const int g = t / OUT_DIM, o = t % OUT_DIM;
    float s = 0.f;
#pragma unroll 16
    for (int f = 0; f < D3; f++) s += pool[g * D3 + f] * wfc[f * OUT_DIM + o];
    out[g * OUT_DIM + o] = s / (gsum[g] + 1e-16f) + bfc[o];
}

// ---------------- launch ----------------
extern "C" void kernel_launch(void* const* d_in, const int* in_sizes, int n_in,
                              void* d_out, int out_size)
{
    const float* x     = (const float*)d_in[0];
    const int*   ei    = (const int*)d_in[1];
    const int*   batch = (const int*)d_in[2];
    const float* W[12] = { (const float*)d_in[3],  (const float*)d_in[5],
                           (const float*)d_in[7],  (const float*)d_in[9],
                           (const float*)d_in[11], (const float*)d_in[13],
                           (const float*)d_in[15], (const float*)d_in[17],
                           (const float*)d_in[19], (const float*)d_in[21],
                           (const float*)d_in[23], (const float*)d_in[25] };
    const float* Bv[12] = { (const float*)d_in[4],  (const float*)d_in[6],
                            (const float*)d_in[8],  (const float*)d_in[10],
                            (const float*)d_in[12], (const float*)d_in[14],
                            (const float*)d_in[16], (const float*)d_in[18],
                            (const float*)d_in[20], (const float*)d_in[22],
                            (const float*)d_in[24], (const float*)d_in[26] };
    const float* w_g  = (const float*)d_in[27]; const float* b_g  = (const float*)d_in[28];
    const float* w_fc = (const float*)d_in[29]; const float* b_fc = (const float*)d_in[30];
    float* out = (float*)d_out;

    float *qb, *skipb, *hA, *gateb, *gmaxb, *gsumb, *poolb, *biasb, *extrasb, *Mfullb, *Mbiasb;
    __half *kb, *vb, *x16b;
    __nv_bfloat16 *Ahi, *Alo, *Whi, *Wlo;
    int *degb, *ptrb, *fillb, *csrb;
    cudaGetSymbolAddress((void**)&qb,     g_q);
    cudaGetSymbolAddress((void**)&kb,     g_k);
    cudaGetSymbolAddress((void**)&vb,     g_v);
    cudaGetSymbolAddress((void**)&skipb,  g_skip);
    cudaGetSymbolAddress((void**)&hA,     g_hA);
    cudaGetSymbolAddress((void**)&extrasb,g_extras);
    cudaGetSymbolAddress((void**)&x16b,   g_x16);
    cudaGetSymbolAddress((void**)&Mfullb, g_Mfull);
    cudaGetSymbolAddress((void**)&Mbiasb, g_Mbias);
    cudaGetSymbolAddress((void**)&Ahi,    g_Ahi);
    cudaGetSymbolAddress((void**)&Alo,    g_Alo);
    cudaGetSymbolAddress((void**)&Whi,    g_Whi);
    cudaGetSymbolAddress((void**)&Wlo,    g_Wlo);
    cudaGetSymbolAddress((void**)&biasb,  g_bias);
    cudaGetSymbolAddress((void**)&degb,   g_deg);
    cudaGetSymbolAddress((void**)&ptrb,   g_ptr);
    cudaGetSymbolAddress((void**)&fillb,  g_fill);
    cudaGetSymbolAddress((void**)&csrb,   g_csr_src);
    cudaGetSymbolAddress((void**)&gateb,  g_gate);
    cudaGetSymbolAddress((void**)&gmaxb,  g_gmax);
    cudaGetSymbolAddress((void**)&gsumb,  g_gsum);
    cudaGetSymbolAddress((void**)&poolb,  g_pool);

    const int N = N_NODES, E = N_EDGES;

    // ---- region tables: 11 weight regions, 11 bias regions ----
    PackArgs P;
    long long wcum = 0;
    int bcum = 0;
    int ri = 0;
    auto addW = [&](const float* src, int K, int ncols, long long base, int ntot, int coff,
                    const float* bsrc, int boff) {
        P.wsrc[ri] = src; P.wcum[ri] = wcum; P.wncols[ri] = ncols;
        P.wdstBase[ri] = base; P.wntot[ri] = ntot; P.wcoff[ri] = coff;
        wcum += (long long)K * ncols;
        P.bsrc[ri] = bsrc; P.bcum[ri] = bcum; P.boff[ri] = boff;
        bcum += ncols;
        ri++;
    };
    // layer 1: Mfull (z+extras) | v | skip
    addW(Mfullb, F_IN, MCOLS, WBASE1, NTOT1, 0,            Mbiasb, BBASE1 + 0);
    addW(W[2],   F_IN, HEADS * D1, WBASE1, NTOT1, MCOLS,   Bv[2],  BBASE1 + MCOLS);
    addW(W[3],   F_IN, D1, WBASE1, NTOT1, MCOLS + HEADS * D1, Bv[3], BBASE1 + MCOLS + HEADS * D1);
    // layer 2: q k v s
    for (int p = 0; p < 4; p++) {
        const int ncols = (p < 3) ? HEADS * D2 : D2;
        const int coff = (p < 3) ? p * HEADS * D2 : 3 * HEADS * D2;
        addW(W[4 + p], D1, ncols, WBASE2, NTOT2, coff, Bv[4 + p], BBASE2 + coff);
    }
    // layer 3: q k v s
    for (int p = 0; p < 4; p++) {
        const int ncols = (p < 3) ? HEADS * D3 : D3;
        const int coff = (p < 3) ? p * HEADS * D3 : 3 * HEADS * D3;
        addW(W[8 + p], D2, ncols, WBASE3, NTOT3, coff, Bv[8 + p], BBASE3 + coff);
    }
    P.wcum[ri] = wcum;
    P.bcum[ri] = bcum;
    for (int r2 = ri; r2 < 12; r2++) { P.wcum[r2 + 1] = wcum; P.bcum[r2 + 1] = bcum; }
    P.x = x;

    const long long packTotal = wcum + NXTOT + bcum;
    const int gy = (N + 127) / 128;

    // epilogue tables
    EpiTab T1;   // z | extras | v | skip
    T1.start[0] = 0;            T1.f[0] = qb;      T1.h[0] = nullptr; T1.stride[0] = ZCOLS;
    T1.start[1] = ZCOLS;        T1.f[1] = extrasb; T1.h[1] = nullptr; T1.stride[1] = 128;
    T1.start[2] = MCOLS;        T1.f[2] = nullptr; T1.h[2] = vb;      T1.stride[2] = HEADS * D1;
    T1.start[3] = MCOLS + HEADS * D1; T1.f[3] = skipb; T1.h[3] = nullptr; T1.stride[3] = D1;
    EpiTab T2;
    T2.start[0] = 0;             T2.f[0] = qb;     T2.h[0] = nullptr; T2.stride[0] = HEADS * D2;
    T2.start[1] = HEADS * D2;    T2.f[1] = nullptr;T2.h[1] = kb;      T2.stride[1] = HEADS * D2;
    T2.start[2] = 2 * HEADS * D2;T2.f[2] = nullptr;T2.h[2] = vb;      T2.stride[2] = HEADS * D2;
    T2.start[3] = 3 * HEADS * D2;T2.f[3] = skipb;  T2.h[3] = nullptr; T2.stride[3] = D2;
    EpiTab T3;
    T3.start[0] = 0;             T3.f[0] = qb;     T3.h[0] = nullptr; T3.stride[0] = HEADS * D3;
    T3.start[1] = HEADS * D3;    T3.f[1] = nullptr;T3.h[1] = kb;      T3.stride[1] = HEADS * D3;
    T3.start[2] = 2 * HEADS * D3;T3.f[2] = nullptr;T3.h[2] = vb;      T3.stride[2] = HEADS * D3;
    T3.start[3] = 3 * HEADS * D3;T3.f[3] = skipb;  T3.h[3] = nullptr; T3.stride[3] = D3;

    // launch order: gemm_fused L1 is the 5th launch (ncu capture slot)
    make_m<<<MCOLS, 128>>>(W[0], W[1], Bv[0], Bv[1], Mfullb, Mbiasb);                   // 1
    pack_all<<<(int)((packTotal + 255) / 256), 256>>>(P, Whi, Wlo, Ahi, Alo, x16b,
                                                      biasb, wcum, NXTOT, bcum);        // 2
    cudaMemsetAsync(degb, 0, N * sizeof(int));                                          // 3
    count_deg<<<(E + 255) / 256, 256>>>(ei, degb, E);                                   // 4
    gemm_fused<<<dim3(NTOT1 / 128, gy), 256>>>(Ahi, Alo, Whi + WBASE1, Wlo + WBASE1,
                                               biasb + BBASE1, T1, N, NTOT1, F_IN);     // 5 <- profiled
    scan_deg<<<1, 1024>>>(degb, ptrb, fillb, N);                                        // 6
    fill_csr<<<(E + 255) / 256, 256>>>(ei, fillb, csrb, E);                             // 7
    attn1_kernel<<<N, 256>>>(qb, x16b, extrasb, vb, ptrb, csrb, skipb, Ahi, Alo);       // 8

    gemm_fused<<<dim3(NTOT2 / 128, gy), 256>>>(Ahi, Alo, Whi + WBASE2, Wlo + WBASE2,
                                               biasb + BBASE2, T2, N, NTOT2, D1);
    attn_kernel<D2, true><<<N, 256>>>(qb, kb, vb, ptrb, csrb, skipb, nullptr, Ahi, Alo);

    gemm_fused<<<dim3(NTOT3 / 128, gy), 256>>>(Ahi, Alo, Whi + WBASE3, Wlo + WBASE3,
                                               biasb + BBASE3, T3, N, NTOT3, D2);
    attn_kernel<D3, false><<<N, 256>>>(qb, kb, vb, ptrb, csrb, skipb, hA, nullptr, nullptr);

    // ---- pooling + fc ----
    init_gmax<<<1, 64>>>(gmaxb);
    cudaMemsetAsync(gsumb, 0, N_GRAPHS * sizeof(float));
    cudaMemsetAsync(poolb, 0, N_GRAPHS * D3 * sizeof(float));
    gate_kernel<<<(N * 32 + 255) / 256, 256>>>(hA, w_g, b_g, batch, gateb, gmaxb, N);
    exp_pool<<<N, D3>>>(hA, gateb, batch, gmaxb, gsumb, poolb);
    fc_kernel<<<1, 1024>>>(poolb, gsumb, w_fc, b_fc, out);
}

// round 11
// speedup vs baseline: 1.6570x; 1.2385x over previous
#include <cuda_runtime.h>
#include <cuda_bf16.h>
#include <cuda_fp16.h>
#include <mma.h>
#include <math.h>
#include <stdint.h>

using namespace nvcuda;

// ---------------- problem constants ----------------
#define N_NODES 10000
#define N_EDGES 80000
#define N_GRAPHS 64
#define HEADS 8
#define F_IN 128
#define D1 512
#define D2 256
#define D3 128
#define OUT_DIM 10

// layer-1 factored logits: z(1024) + extras(128)
#define ZCOLS (HEADS * F_IN)          // 1024
#define MCOLS (ZCOLS + 128)           // 1152

// fp16 (logit-path) weight buffer: L1 Mfull | L2 q|k | L3 q|k
#define F_N1 MCOLS                    // 1152
#define F_N2 (2 * HEADS * D2)         // 4096
#define F_N3 (2 * HEADS * D3)         // 2048
#define WF_BASE1 0LL
#define WF_BASE2 ((long long)F_IN * F_N1)
#define WF_BASE3 (WF_BASE2 + (long long)D1 * F_N2)
#define WF_TOTAL (WF_BASE3 + (long long)D2 * F_N3)

// bf16x3 (h-path) weight buffer: v|skip per layer
#define B_N1 (HEADS * D1 + D1)        // 4608
#define B_N2 (HEADS * D2 + D2)        // 2304
#define B_N3 (HEADS * D3 + D3)        // 1152
#define WB_BASE1 0LL
#define WB_BASE2 ((long long)F_IN * B_N1)
#define WB_BASE3 (WB_BASE2 + (long long)D1 * B_N2)
#define WB_TOTAL (WB_BASE3 + (long long)D2 * B_N3)

// bias layout: per layer [fp16-region | bf16-region]
#define BB1 0
#define BB2 (F_N1 + B_N1)                 // 5760
#define BB3 (BB2 + F_N2 + B_N2)           // 12160
#define BTOTAL (BB3 + F_N3 + B_N3)        // 15360
#define NXTOT (N_NODES * F_IN)

// ---------------- device scratch (static, no allocs) ----------------
__device__ float g_q[(size_t)N_NODES * (HEADS * D1)];      // q (L2/L3) or z (L1)
__device__ __half g_k[(size_t)N_NODES * (HEADS * D1)];
__device__ __half g_v[(size_t)N_NODES * (HEADS * D1)];
__device__ float g_skip[(size_t)N_NODES * D1];
__device__ float g_hA[(size_t)N_NODES * D1];

__device__ float g_extras[(size_t)N_NODES * 128];          // alpha(8) beta(8) pad
__device__ __half g_x16[(size_t)N_NODES * F_IN];           // x fp16 (L1 gemm_half A + edge gather)
__device__ __half g_Af16[(size_t)N_NODES * D1];            // h fp16 (L2/L3 gemm_half A)
__device__ float g_Mfull[F_IN * MCOLS];
__device__ float g_Mbias[MCOLS];

__device__ __nv_bfloat16 g_Ahi[(size_t)N_NODES * D1];
__device__ __nv_bfloat16 g_Alo[(size_t)N_NODES * D1];
__device__ __half g_WF[WF_TOTAL];
__device__ __nv_bfloat16 g_Whi[WB_TOTAL];
__device__ __nv_bfloat16 g_Wlo[WB_TOTAL];
__device__ float g_bias[BTOTAL];

__device__ int g_deg[N_NODES];
__device__ int g_ptr[N_NODES + 1];
__device__ int g_fill[N_NODES];
__device__ int g_csr_src[N_EDGES];

__device__ float g_gate[N_NODES];
__device__ float g_gmax[N_GRAPHS];
__device__ float g_gsum[N_GRAPHS];
__device__ float g_pool[N_GRAPHS * D3];

// ---------------- cp.async helpers ----------------
__device__ __forceinline__ void cp16(uint32_t dst, const void* src)
{
    asm volatile("cp.async.cg.shared.global [%0], [%1], 16;" :: "r"(dst), "l"(src));
}
__device__ __forceinline__ void cp_commit() { asm volatile("cp.async.commit_group;"); }
template <int Np>
__device__ __forceinline__ void cp_wait() { asm volatile("cp.async.wait_group %0;" :: "n"(Np)); }

// ---------------- layer-1 factorization precompute ----------------
__global__ void make_m(const float* __restrict__ wq, const float* __restrict__ wk,
                       const float* __restrict__ bq, const float* __restrict__ bk,
                       float* __restrict__ Mfull, float* __restrict__ Mbias)
{
    __shared__ float col[D1];
    __shared__ float red[128];
    const int j = blockIdx.x;
    const int tid = threadIdx.x;

    if (j >= 1040) {
        Mfull[tid * MCOLS + j] = 0.f;
        if (tid == 0) Mbias[j] = 0.f;
        return;
    }

    int h;
    const float* mat;
    if (j < ZCOLS)        { h = j >> 7;   mat = wq; }
    else if (j < 1032)    { h = j - 1024; mat = wq; }
    else                  { h = j - 1032; mat = wk; }
    const int base = h * D1;

    if (j < ZCOLS) {
        const int jj = j & 127;
        for (int c = tid; c < D1; c += 128) col[c] = wk[(size_t)jj * (HEADS * D1) + base + c];
    } else if (j < 1032) {
        for (int c = tid; c < D1; c += 128) col[c] = bk[base + c];
    } else {
        for (int c = tid; c < D1; c += 128) col[c] = bq[base + c];
    }
    __syncthreads();

    const float4* row4 = reinterpret_cast<const float4*>(mat + (size_t)tid * (HEADS * D1) + base);
    float acc = 0.f;
#pragma unroll 4
    for (int c = 0; c < D1 / 4; c++) {
        const float4 r = row4[c];
        acc += r.x * col[c * 4 + 0] + r.y * col[c * 4 + 1]
             + r.z * col[c * 4 + 2] + r.w * col[c * 4 + 3];
    }
    Mfull[tid * MCOLS + j] = acc;

    if (j >= ZCOLS && j < 1032) {
        float p = 0.f;
        for (int c = tid; c < D1; c += 128) p += bq[base + c] * bk[base + c];
        red[tid] = p;
        __syncthreads();
        if (tid < 64) red[tid] += red[tid + 64];
        __syncthreads();
        if (tid < 32) {
            float t = red[tid] + red[tid + 32];
#pragma unroll
            for (int o = 16; o > 0; o >>= 1) t += __shfl_down_sync(0xffffffffu, t, o);
            if (tid == 0) Mbias[j] = t;
        }
    } else {
        if (tid == 0) Mbias[j] = 0.f;
    }
}

// ---------------- one-shot packing ----------------
struct PackArgs {
    const float* wsrc[12];
    long long wcum[13];
    int wncols[12];
    long long wdstBase[12];
    int wntot[12];
    int wcoff[12];
    int wIsHalf[12];
    const float* bsrc[12];
    int bcum[13];
    int boff[12];
    const float* x;
};

__global__ void pack_all(PackArgs P, __half* __restrict__ WF,
                         __nv_bfloat16* __restrict__ Whi, __nv_bfloat16* __restrict__ Wlo,
                         __half* __restrict__ x16,
                         __nv_bfloat16* __restrict__ Ahi, __nv_bfloat16* __restrict__ Alo,
                         float* __restrict__ bias, long long wtotal, long long xtotal, int btotal)
{
    long long i = (long long)blockIdx.x * blockDim.x + threadIdx.x;
    if (i < wtotal) {
        int r = 0;
        while (i >= P.wcum[r + 1]) r++;
        const long long li = i - P.wcum[r];
        const int nc = P.wncols[r];
        const int k = (int)(li / nc), c = (int)(li % nc);
        const float v = P.wsrc[r][li];
        const long long di = P.wdstBase[r] + (long long)k * P.wntot[r] + P.wcoff[r] + c;
        if (P.wIsHalf[r]) {
            WF[di] = __float2half(v);
        } else {
            __nv_bfloat16 h = __float2bfloat16(v);
            Whi[di] = h;
            Wlo[di] = __float2bfloat16(v - __bfloat162float(h));
        }
        return;
    }
    i -= wtotal;
    if (i < xtotal) {
        const float v = P.x[i];
        __nv_bfloat16 h = __float2bfloat16(v);
        Ahi[i] = h;
        Alo[i] = __float2bfloat16(v - __bfloat162float(h));
        x16[i] = __float2half(v);
        return;
    }
    int j = (int)(i - xtotal);
    if (j < btotal) {
        int r = 0;
        while (j >= P.bcum[r + 1]) r++;
        bias[P.boff[r] + (j - P.bcum[r])] = P.bsrc[r][j - P.bcum[r]];
    }
}

// ---------------- epilogue routing table ----------------
struct EpiTab {
    float* f[4];
    __half* h[4];
    int stride[4];
    int start[4];
};

// ---------------- bf16x3 tensor-core GEMM (h-path: v|skip) ----------------
#define LDA 24
#define LDB 136
#define ASZ (128 * LDA)
#define BSZ (16 * LDB)
#define STAGE_E (2 * ASZ + 2 * BSZ)

__global__ __launch_bounds__(256, 2)
void gemm_fused(const __nv_bfloat16* __restrict__ Ahi, const __nv_bfloat16* __restrict__ Alo,
                const __nv_bfloat16* __restrict__ Bhi, const __nv_bfloat16* __restrict__ Blo,
                const float* __restrict__ bias, EpiTab T,
                int M, int N, int K)
{
    __shared__ __align__(16) __nv_bfloat16 sm[2 * STAGE_E];

    const int tid = threadIdx.x;
    const int warpId = tid >> 5;
    const int lane = tid & 31;
    const int wm = warpId >> 2;
    const int wn = warpId & 3;
    const int bm = blockIdx.y * 128;
    const int bn = blockIdx.x * 128;

    const int arow = tid >> 1, ac8 = (tid & 1) * 8;
    const int brow = tid >> 4, bc8 = (tid & 15) * 8;

    wmma::fragment<wmma::accumulator, 16, 16, 16, float> acc[4][2];
#pragma unroll
    for (int i = 0; i < 4; i++)
#pragma unroll
        for (int j = 0; j < 2; j++) wmma::fill_fragment(acc[i][j], 0.f);

    auto issue = [&](int kb, int s) {
        __nv_bfloat16* base = sm + s * STAGE_E;
        __nv_bfloat16* pAh = base + arow * LDA + ac8;
        __nv_bfloat16* pAl = pAh + ASZ;
        const int gr = bm + arow;
        if (gr < M) {
            const size_t off = (size_t)gr * K + kb + ac8;
            cp16((uint32_t)__cvta_generic_to_shared(pAh), Ahi + off);
            cp16((uint32_t)__cvta_generic_to_shared(pAl), Alo + off);
        } else {
            uint4 z = make_uint4(0, 0, 0, 0);
            *reinterpret_cast<uint4*>(pAh) = z;
            *reinterpret_cast<uint4*>(pAl) = z;
        }
        __nv_bfloat16* pBh = base + 2 * ASZ + brow * LDB + bc8;
        const size_t boff = (size_t)(kb + brow) * N + bn + bc8;
        cp16((uint32_t)__cvta_generic_to_shared(pBh), Bhi + boff);
        cp16((uint32_t)__cvta_generic_to_shared(pBh + BSZ), Blo + boff);
        cp_commit();
    };

    const int nk = K >> 4;
    issue(0, 0);

    for (int it = 0; it < nk; ++it) {
        const int s = it & 1;
        if (it + 1 < nk) { issue((it + 1) << 4, s ^ 1); cp_wait<1>(); }
        else             { cp_wait<0>(); }
        __syncthreads();

        const __nv_bfloat16* Ah = sm + s * STAGE_E;
        const __nv_bfloat16* Al = Ah + ASZ;
        const __nv_bfloat16* Bh = Ah + 2 * ASZ;
        const __nv_bfloat16* Bl = Bh + BSZ;

        wmma::fragment<wmma::matrix_a, 16, 16, 16, __nv_bfloat16, wmma::row_major> ah[4], al[4];
        wmma::fragment<wmma::matrix_b, 16, 16, 16, __nv_bfloat16, wmma::row_major> bh[2], bl[2];
#pragma unroll
        for (int i = 0; i < 4; i++) {
            wmma::load_matrix_sync(ah[i], Ah + (wm * 64 + i * 16) * LDA, LDA);
            wmma::load_matrix_sync(al[i], Al + (wm * 64 + i * 16) * LDA, LDA);
        }
#pragma unroll
        for (int j = 0; j < 2; j++) {
            wmma::load_matrix_sync(bh[j], Bh + wn * 32 + j * 16, LDB);
            wmma::load_matrix_sync(bl[j], Bl + wn * 32 + j * 16, LDB);
        }
#pragma unroll
        for (int i = 0; i < 4; i++)
#pragma unroll
            for (int j = 0; j < 2; j++) {
                wmma::mma_sync(acc[i][j], ah[i], bh[j], acc[i][j]);
                wmma::mma_sync(acc[i][j], ah[i], bl[j], acc[i][j]);
                wmma::mma_sync(acc[i][j], al[i], bh[j], acc[i][j]);
            }
        __syncthreads();
    }

    const int r = (bn >= T.start[3]) ? 3 : (bn >= T.start[2]) ? 2 : (bn >= T.start[1]) ? 1 : 0;
    float* fdst = T.f[r];
    __half* hdst = T.h[r];
    const int lcb = bn - T.start[r];
    const int stride = T.stride[r];

    float* wb = reinterpret_cast<float*>(sm) + warpId * 256;
#pragma unroll
    for (int i = 0; i < 4; i++)
#pragma unroll
        for (int j = 0; j < 2; j++) {
            wmma::store_matrix_sync(wb, acc[i][j], 16, wmma::mem_row_major);
            __syncwarp();
            const int r0 = bm + wm * 64 + i * 16;
            const int c0 = bn + wn * 32 + j * 16;
#pragma unroll
            for (int e = lane; e < 64; e += 32) {
                const int rr = e >> 2, c4 = (e & 3) * 4;
                if (r0 + rr >= M) continue;
                float4 vv = *reinterpret_cast<float4*>(wb + rr * 16 + c4);
                const int col = c0 + c4;
                vv.x += bias[col + 0];
                vv.y += bias[col + 1];
                vv.z += bias[col + 2];
                vv.w += bias[col + 3];
                const size_t o = (size_t)(r0 + rr) * stride + (lcb + (col - bn));
                if (fdst) {
                    *reinterpret_cast<float4*>(fdst + o) = vv;
                } else {
                    uint2 p;
                    *reinterpret_cast<__half2*>(&p.x) = __floats2half2_rn(vv.x, vv.y);
                    *reinterpret_cast<__half2*>(&p.y) = __floats2half2_rn(vv.z, vv.w);
                    *reinterpret_cast<uint2*>(hdst + o) = p;
                }
            }
            __syncwarp();
        }
}

// ---------------- fp16 single-pass GEMM (logit-path: z / q|k), BK=32 ----------------
#define LDAH 40
#define LDBH 136
#define ASZH (128 * LDAH)              // 5120 elems
#define BSZH (32 * LDBH)               // 4352 elems
#define STAGE_H (ASZH + BSZH)          // 9472 elems = 18944 B

__global__ __launch_bounds__(256, 2)
void gemm_half(const __half* __restrict__ A, const __half* __restrict__ B,
               const float* __restrict__ bias, EpiTab T,
               int M, int N, int K)
{
    __shared__ __align__(16) __half sm[2 * STAGE_H];

    const int tid = threadIdx.x;
    const int warpId = tid >> 5;
    const int lane = tid & 31;
    const int wm = warpId >> 2;
    const int wn = warpId & 3;
    const int bm = blockIdx.y * 128;
    const int bn = blockIdx.x * 128;

    const int ar = tid >> 1, ac = (tid & 1) * 16;
    const int br = tid >> 3, bc = (tid & 7) * 16;

    wmma::fragment<wmma::accumulator, 16, 16, 16, float> acc[4][2];
#pragma unroll
    for (int i = 0; i < 4; i++)
#pragma unroll
        for (int j = 0; j < 2; j++) wmma::fill_fragment(acc[i][j], 0.f);

    auto issue = [&](int kb, int s) {
        __half* base = sm + s * STAGE_H;
        __half* pA = base + ar * LDAH + ac;
        const int gr = bm + ar;
        if (gr < M) {
            const size_t off = (size_t)gr * K + kb + ac;
            cp16((uint32_t)__cvta_generic_to_shared(pA),     A + off);
            cp16((uint32_t)__cvta_generic_to_shared(pA + 8), A + off + 8);
        } else {
            uint4 z = make_uint4(0, 0, 0, 0);
            *reinterpret_cast<uint4*>(pA) = z;
            *reinterpret_cast<uint4*>(pA + 8) = z;
        }
        __half* pB = base + ASZH + br * LDBH + bc;
        const size_t boff = (size_t)(kb + br) * N + bn + bc;
        cp16((uint32_t)__cvta_generic_to_shared(pB),     B + boff);
        cp16((uint32_t)__cvta_generic_to_shared(pB + 8), B + boff + 8);
        cp_commit();
    };

    const int nk = K >> 5;
    issue(0, 0);

    for (int it = 0; it < nk; ++it) {
        const int s = it & 1;
        if (it + 1 < nk) { issue((it + 1) << 5, s ^ 1); cp_wait<1>(); }
        else             { cp_wait<0>(); }
        __syncthreads();

        const __half* As = sm + s * STAGE_H;
        const __half* Bs = As + ASZH;

#pragma unroll
        for (int kk = 0; kk < 2; kk++) {
            wmma::fragment<wmma::matrix_a, 16, 16, 16, __half, wmma::row_major> af[4];
            wmma::fragment<wmma::matrix_b, 16, 16, 16, __half, wmma::row_major> bf[2];
#pragma unroll
            for (int i = 0; i < 4; i++)
                wmma::load_matrix_sync(af[i], As + (wm * 64 + i * 16) * LDAH + kk * 16, LDAH);
#pragma unroll
            for (int j = 0; j < 2; j++)
                wmma::load_matrix_sync(bf[j], Bs + (kk * 16) * LDBH + wn * 32 + j * 16, LDBH);
#pragma unroll
            for (int i = 0; i < 4; i++)
#pragma unroll
                for (int j = 0; j < 2; j++)
                    wmma::mma_sync(acc[i][j], af[i], bf[j], acc[i][j]);
        }
        __syncthreads();
    }

    const int r = (bn >= T.start[3]) ? 3 : (bn >= T.start[2]) ? 2 : (bn >= T.start[1]) ? 1 : 0;
    float* fdst = T.f[r];
    __half* hdst = T.h[r];
    const int lcb = bn - T.start[r];
    const int stride = T.stride[r];

    float* wb = reinterpret_cast<float*>(sm) + warpId * 256;
#pragma unroll
    for (int i = 0; i < 4; i++)
#pragma unroll
        for (int j = 0; j < 2; j++) {
            wmma::store_matrix_sync(wb, acc[i][j], 16, wmma::mem_row_major);
            __syncwarp();
            const int r0 = bm + wm * 64 + i * 16;
            const int c0 = bn + wn * 32 + j * 16;
#pragma unroll
            for (int e = lane; e < 64; e += 32) {
                const int rr = e >> 2, c4 = (e & 3) * 4;
                if (r0 + rr >= M) continue;
                float4 vv = *reinterpret_cast<float4*>(wb + rr * 16 + c4);
                const int col = c0 + c4;
                vv.x += bias[col + 0];
                vv.y += bias[col + 1];
                vv.z += bias[col + 2];
                vv.w += bias[col + 3];
                const size_t o = (size_t)(r0 + rr) * stride + (lcb + (col - bn));
                if (fdst) {
                    *reinterpret_cast<float4*>(fdst + o) = vv;
                } else {
                    uint2 p;
                    *reinterpret_cast<__half2*>(&p.x) = __floats2half2_rn(vv.x, vv.y);
                    *reinterpret_cast<__half2*>(&p.y) = __floats2half2_rn(vv.z, vv.w);
                    *reinterpret_cast<uint2*>(hdst + o) = p;
                }
            }
            __syncwarp();
        }
}

// ---------------- CSR build ----------------
__global__ void count_deg(const int* __restrict__ ei, int* __restrict__ deg, int E)
{
    int e = blockIdx.x * blockDim.x + threadIdx.x;
    if (e < E) atomicAdd(&deg[ei[E + e]], 1);
}

__global__ void scan_deg(const int* __restrict__ deg, int* __restrict__ ptr,
                         int* __restrict__ fill, int n)
{
    constexpr int PER = 10;
    const int tid = threadIdx.x;
    const int lane = tid & 31, wid = tid >> 5;
    const int base = tid * PER;

    int vals[PER];
    int s = 0;
#pragma unroll
    for (int i = 0; i < PER; i++) {
        const int idx = base + i;
        vals[i] = (idx < n) ? deg[idx] : 0;
        s += vals[i];
    }
    int sc = s;
#pragma unroll
    for (int o = 1; o < 32; o <<= 1) {
        int t = __shfl_up_sync(0xffffffffu, sc, o);
        if (lane >= o) sc += t;
    }
    __shared__ int wsum[32];
    if (lane == 31) wsum[wid] = sc;
    __syncthreads();
    if (wid == 0) {
        int w = wsum[lane];
#pragma unroll
        for (int o = 1; o < 32; o <<= 1) {
            int t = __shfl_up_sync(0xffffffffu, w, o);
            if (lane >= o) w += t;
        }
        wsum[lane] = w;
    }
    __syncthreads();
    int run = (sc - s) + (wid > 0 ? wsum[wid - 1] : 0);
#pragma unroll
    for (int i = 0; i < PER; i++) {
        const int idx = base + i;
        if (idx < n) { ptr[idx] = run; fill[idx] = run; }
        run += vals[i];
    }
    if (tid == 1023) ptr[n] = run;
}

__global__ void fill_csr(const int* __restrict__ ei, int* __restrict__ fill,
                         int* __restrict__ csr_src, int E)
{
    int e = blockIdx.x * blockDim.x + threadIdx.x;
    if (e < E) {
        const int d = ei[E + e];
        const int pos = atomicAdd(&fill[d], 1);
        csr_src[pos] = ei[e];
    }
}

// ---------------- layer-1 attention (factored logits) ----------------
__global__ void attn1_kernel(const float* __restrict__ z, const __half* __restrict__ x16,
                             const float* __restrict__ ex, const __half* __restrict__ v,
                             const int* __restrict__ ptr, const int* __restrict__ csr_src,
                             const float* __restrict__ skip,
                             __half* __restrict__ outF16,
                             __nv_bfloat16* __restrict__ outHi, __nv_bfloat16* __restrict__ outLo)
{
    constexpr int C = D1;
    constexpr int F4 = C / 128;
    __shared__ float red[HEADS * C];

    const int dst  = blockIdx.x;
    const int warp = threadIdx.x >> 5;
    const int lane = threadIdx.x & 31;
    const float scale = rsqrtf((float)C);

    const int beg = ptr[dst], end = ptr[dst + 1];

    const float4 zr = reinterpret_cast<const float4*>(z + (size_t)dst * ZCOLS + warp * F_IN)[lane];
    const float alpha = ex[(size_t)dst * 128 + warp];

    float4 acc[F4];
#pragma unroll
    for (int i = 0; i < F4; i++) acc[i] = make_float4(0.f, 0.f, 0.f, 0.f);
    float m = -INFINITY, s = 0.f;

    for (int j = beg; j < end; j++) {
        const int src = csr_src[j];
        const uint2 xx = reinterpret_cast<const uint2*>(x16 + (size_t)src * F_IN)[lane];
        const float2 x0 = __half22float2(*reinterpret_cast<const __half2*>(&xx.x));
        const float2 x1 = __half22float2(*reinterpret_cast<const __half2*>(&xx.y));
        float d = zr.x * x0.x + zr.y * x0.y + zr.z * x1.x + zr.w * x1.y;
#pragma unroll
        for (int o = 16; o > 0; o >>= 1) d += __shfl_xor_sync(0xffffffffu, d, o);
        const float beta = ex[(size_t)src * 128 + 8 + warp];
        const float a = (d + alpha + beta) * scale;
        const float mn = fmaxf(m, a);
        const float corr = expf(m - mn);
        const float w = expf(a - mn);
        s = s * corr + w;
        m = mn;
        const uint2* vrow = reinterpret_cast<const uint2*>(v + (size_t)src * (HEADS * C) + warp * C);
#pragma unroll
        for (int i = 0; i < F4; i++) {
            const uint2 vvp = vrow[lane + 32 * i];
            const float2 v0 = __half22float2(*reinterpret_cast<const __half2*>(&vvp.x));
            const float2 v1 = __half22float2(*reinterpret_cast<const __half2*>(&vvp.y));
            acc[i].x = acc[i].x * corr + w * v0.x;
            acc[i].y = acc[i].y * corr + w * v0.y;
            acc[i].z = acc[i].z * corr + w * v1.x;
            acc[i].w = acc[i].w * corr + w * v1.y;
        }
    }

    const float inv = (end > beg) ? (1.f / (s + 1e-16f)) : 0.f;
#pragma unroll
    for (int i = 0; i < F4; i++) {
        float4 o = make_float4(acc[i].x * inv, acc[i].y * inv, acc[i].z * inv, acc[i].w * inv);
        *reinterpret_cast<float4*>(&red[warp * C + i * 128 + lane * 4]) = o;
    }
    __syncthreads();

    for (int f = threadIdx.x; f < C; f += blockDim.x) {
        float t = 0.f;
#pragma unroll
        for (int h = 0; h < HEADS; h++) t += red[h * C + f];
        t = t * (1.f / HEADS) + skip[(size_t)dst * C + f];
        t = (t > 0.f) ? t : expm1f(t);
        const size_t idx = (size_t)dst * C + f;
        __nv_bfloat16 hh = __float2bfloat16(t);
        outHi[idx] = hh;
        outLo[idx] = __float2bfloat16(t - __bfloat162float(hh));
        outF16[idx] = __float2half(t);
    }
}

// ---------------- layers 2/3 attention ----------------
template <int C, bool SPLIT>
__global__ void attn_kernel(const float* __restrict__ q, const __half* __restrict__ k,
                            const __half* __restrict__ v, const int* __restrict__ ptr,
                            const int* __restrict__ csr_src, const float* __restrict__ skip,
                            float* __restrict__ out, __half* __restrict__ outF16,
                            __nv_bfloat16* __restrict__ outHi, __nv_bfloat16* __restrict__ outLo)
{
    constexpr int H = HEADS;
    constexpr int F4 = C / 128;
    __shared__ float red[H * C];

    const int dst  = blockIdx.x;
    const int warp = threadIdx.x >> 5;
    const int lane = threadIdx.x & 31;
    const float scale = rsqrtf((float)C);
    const size_t HC = (size_t)H * C;

    const int beg = ptr[dst], end = ptr[dst + 1];

    const float4* qrow = reinterpret_cast<const float4*>(q + (size_t)dst * HC + warp * C);
    float4 qr[F4], acc[F4];
#pragma unroll
    for (int i = 0; i < F4; i++) {
        qr[i] = qrow[lane + 32 * i];
        acc[i] = make_float4(0.f, 0.f, 0.f, 0.f);
    }
    float m = -INFINITY, s = 0.f;

    for (int j = beg; j < end; j++) {
        const int src = csr_src[j];
        const uint2* krow = reinterpret_cast<const uint2*>(k + (size_t)src * HC + warp * C);
        const uint2* vrow = reinterpret_cast<const uint2*>(v + (size_t)src * HC + warp * C);
        float d = 0.f;
#pragma unroll
        for (int i = 0; i < F4; i++) {
            const uint2 kk = krow[lane + 32 * i];
            const float2 k0 = __half22float2(*reinterpret_cast<const __half2*>(&kk.x));
            const float2 k1 = __half22float2(*reinterpret_cast<const __half2*>(&kk.y));
            d += qr[i].x * k0.x + qr[i].y * k0.y + qr[i].z * k1.x + qr[i].w * k1.y;
        }
#pragma unroll
        for (int o = 16; o > 0; o >>= 1) d += __shfl_xor_sync(0xffffffffu, d, o);
        const float a = d * scale;
        const float mn = fmaxf(m, a);
        const float corr = expf(m - mn);
        const float w = expf(a - mn);
        s = s * corr + w;
        m = mn;
#pragma unroll
        for (int i = 0; i < F4; i++) {
            const uint2 vvp = vrow[lane + 32 * i];
            const float2 v0 = __half22float2(*reinterpret_cast<const __half2*>(&vvp.x));
            const float2 v1 = __half22float2(*reinterpret_cast<const __half2*>(&vvp.y));
            acc[i].x = acc[i].x * corr + w * v0.x;
            acc[i].y = acc[i].y * corr + w * v0.y;
            acc[i].z = acc[i].z * corr + w * v1.x;
            acc[i].w = acc[i].w * corr + w * v1.y;
        }
    }

    const float inv = (end > beg) ? (1.f / (s + 1e-16f)) : 0.f;
#pragma unroll
    for (int i = 0; i < F4; i++) {
        float4 o = make_float4(acc[i].x * inv, acc[i].y * inv, acc[i].z * inv, acc[i].w * inv);
        *reinterpret_cast<float4*>(&red[warp * C + i * 128 + lane * 4]) = o;
    }
    __syncthreads();

    for (int f = threadIdx.x; f < C; f += blockDim.x) {
        float t = 0.f;
#pragma unroll
        for (int h = 0; h < H; h++) t += red[h * C + f];
        t = t * (1.f / H) + skip[(size_t)dst * C + f];
        t = (t > 0.f) ? t : expm1f(t);
        const size_t idx = (size_t)dst * C + f;
        if constexpr (SPLIT) {
            __nv_bfloat16 hh = __float2bfloat16(t);
            outHi[idx] = hh;
            outLo[idx] = __float2bfloat16(t - __bfloat162float(hh));
            outF16[idx] = __float2half(t);
        } else {
            out[idx] = t;
        }
    }
}

// ---------------- global attention pooling ----------------
__global__ void init_gmax(float* gmax)
{
    if (threadIdx.x < N_GRAPHS) gmax[threadIdx.x] = -INFINITY;
}

__global__ void gate_kernel(const float* __restrict__ h, const float* __restrict__ wg,
                            const float* __restrict__ bg, const int* __restrict__ batch,
                            float* __restrict__ gate, float* __restrict__ gmax, int n)
{
    const int node = (blockIdx.x * blockDim.x + threadIdx.x) >> 5;
    const int lane = threadIdx.x & 31;
    if (node >= n) return;
    const float* row = h + (size_t)node * D3;
    float d = 0.f;
#pragma unroll
    for (int i = 0; i < D3 / 32; i++) d += row[lane + 32 * i] * wg[lane + 32 * i];
#pragma unroll
    for (int o = 16; o > 0; o >>= 1) d += __shfl_xor_sync(0xffffffffu, d, o);
    if (lane == 0) {
        d += bg[0];
        gate[node] = d;
        float* addr = &gmax[batch[node]];
        if (d >= 0.f) atomicMax((int*)addr, __float_as_int(d));
        else          atomicMin((unsigned int*)addr, __float_as_uint(d));
    }
}

__global__ void exp_pool(const float* __restrict__ h, const float* __restrict__ gate,
                         const int* __restrict__ batch, const float* __restrict__ gmax,
                         float* __restrict__ gsum, float* __restrict__ pool)
{
    const int node = blockIdx.x;
    const int f = threadIdx.x;
    const int b = batch[node];
    const float e = expf(gate[node] - gmax[b]);
    if (f == 0) atomicAdd(&gsum[b], e);
    atomicAdd(&pool[b * D3 + f], e * h[(size_t)node * D3 + f]);
}

__global__ void fc_kernel(const float* __restrict__ pool, const float* __restrict__ gsum,
                          const float* __restrict__ wfc, const float* __restrict__ bfc,
                          float* __restrict__ out)
{
    const int t = threadIdx.x;
    if (t >= N_GRAPHS * OUT_DIM) return;
    const int g = t / OUT_DIM, o = t % OUT_DIM;
    float s = 0.f;
#pragma unroll 16
    for (int f = 0; f < D3; f++) s += pool[g * D3 + f] * wfc[f * OUT_DIM + o];
    out[g * OUT_DIM + o] = s / (gsum[g] + 1e-16f) + bfc[o];
}

// ---------------- launch ----------------
extern "C" void kernel_launch(void* const* d_in, const int* in_sizes, int n_in,
                              void* d_out, int out_size)
{
    const float* x     = (const float*)d_in[0];
    const int*   ei    = (const int*)d_in[1];
    const int*   batch = (const int*)d_in[2];
    const float* W[12] = { (const float*)d_in[3],  (const float*)d_in[5],
                           (const float*)d_in[7],  (const float*)d_in[9],
                           (const float*)d_in[11], (const float*)d_in[13],
                           (const float*)d_in[15], (const float*)d_in[17],
                           (const float*)d_in[19], (const float*)d_in[21],
                           (const float*)d_in[23], (const float*)d_in[25] };
    const float* Bv[12] = { (const float*)d_in[4],  (const float*)d_in[6],
                            (const float*)d_in[8],  (const float*)d_in[10],
                            (const float*)d_in[12], (const float*)d_in[14],
                            (const float*)d_in[16], (const float*)d_in[18],
                            (const float*)d_in[20], (const float*)d_in[22],
                            (const float*)d_in[24], (const float*)d_in[26] };
    const float* w_g  = (const float*)d_in[27]; const float* b_g  = (const float*)d_in[28];
    const float* w_fc = (const float*)d_in[29]; const float* b_fc = (const float*)d_in[30];
    float* out = (float*)d_out;

    float *qb, *skipb, *hA, *gateb, *gmaxb, *gsumb, *poolb, *biasb, *extrasb, *Mfullb, *Mbiasb;
    __half *kb, *vb, *x16b, *Af16b, *WFb;
    __nv_bfloat16 *Ahi, *Alo, *Whi, *Wlo;
    int *degb, *ptrb, *fillb, *csrb;
    cudaGetSymbolAddress((void**)&qb,     g_q);
    cudaGetSymbolAddress((void**)&kb,     g_k);
    cudaGetSymbolAddress((void**)&vb,     g_v);
    cudaGetSymbolAddress((void**)&skipb,  g_skip);
    cudaGetSymbolAddress((void**)&hA,     g_hA);
    cudaGetSymbolAddress((void**)&extrasb,g_extras);
    cudaGetSymbolAddress((void**)&x16b,   g_x16);
    cudaGetSymbolAddress((void**)&Af16b,  g_Af16);
    cudaGetSymbolAddress((void**)&Mfullb, g_Mfull);
    cudaGetSymbolAddress((void**)&Mbiasb, g_Mbias);
    cudaGetSymbolAddress((void**)&Ahi,    g_Ahi);
    cudaGetSymbolAddress((void**)&Alo,    g_Alo);
    cudaGetSymbolAddress((void**)&WFb,    g_WF);
    cudaGetSymbolAddress((void**)&Whi,    g_Whi);
    cudaGetSymbolAddress((void**)&Wlo,    g_Wlo);
    cudaGetSymbolAddress((void**)&biasb,  g_bias);
    cudaGetSymbolAddress((void**)&degb,   g_deg);
    cudaGetSymbolAddress((void**)&ptrb,   g_ptr);
    cudaGetSymbolAddress((void**)&fillb,  g_fill);
    cudaGetSymbolAddress((void**)&csrb,   g_csr_src);
    cudaGetSymbolAddress((void**)&gateb,  g_gate);
    cudaGetSymbolAddress((void**)&gmaxb,  g_gmax);
    cudaGetSymbolAddress((void**)&gsumb,  g_gsum);
    cudaGetSymbolAddress((void**)&poolb,  g_pool);

    const int N = N_NODES, E = N_EDGES;

    // ---- pack regions ----
    PackArgs P;
    long long wcum = 0;
    int bcum = 0;
    int ri = 0;
    auto addW = [&](const float* src, int K, int ncols, long long base, int ntot, int coff,
                    int isHalf, const float* bsrc, int boff) {
        P.wsrc[ri] = src; P.wcum[ri] = wcum; P.wncols[ri] = ncols;
        P.wdstBase[ri] = base; P.wntot[ri] = ntot; P.wcoff[ri] = coff;
        P.wIsHalf[ri] = isHalf;
        wcum += (long long)K * ncols;
        P.bsrc[ri] = bsrc; P.bcum[ri] = bcum; P.boff[ri] = boff;
        bcum += ncols;
        ri++;
    };
    // L1: Mfull -> fp16 | v,skip -> bf16
    addW(Mfullb, F_IN, F_N1, WF_BASE1, F_N1, 0, 1, Mbiasb, BB1);
    addW(W[2], F_IN, HEADS * D1, WB_BASE1, B_N1, 0, 0, Bv[2], BB1 + F_N1);
    addW(W[3], F_IN, D1, WB_BASE1, B_N1, HEADS * D1, 0, Bv[3], BB1 + F_N1 + HEADS * D1);
    // L2: q,k -> fp16 | v,skip -> bf16
    addW(W[4], D1, HEADS * D2, WF_BASE2, F_N2, 0, 1, Bv[4], BB2);
    addW(W[5], D1, HEADS * D2, WF_BASE2, F_N2, HEADS * D2, 1, Bv[5], BB2 + HEADS * D2);
    addW(W[6], D1, HEADS * D2, WB_BASE2, B_N2, 0, 0, Bv[6], BB2 + F_N2);
    addW(W[7], D1, D2, WB_BASE2, B_N2, HEADS * D2, 0, Bv[7], BB2 + F_N2 + HEADS * D2);
    // L3
    addW(W[8], D2, HEADS * D3, WF_BASE3, F_N3, 0, 1, Bv[8], BB3);
    addW(W[9], D2, HEADS * D3, WF_BASE3, F_N3, HEADS * D3, 1, Bv[9], BB3 + HEADS * D3);
    addW(W[10], D2, HEADS * D3, WB_BASE3, B_N3, 0, 0, Bv[10], BB3 + F_N3);
    addW(W[11], D2, D3, WB_BASE3, B_N3, HEADS * D3, 0, Bv[11], BB3 + F_N3 + HEADS * D3);
    P.wcum[ri] = wcum;
    P.bcum[ri] = bcum;
    for (int r2 = ri; r2 < 12; r2++) { P.wcum[r2 + 1] = wcum; P.bcum[r2 + 1] = bcum; }
    P.x = x;

    const long long packTotal = wcum + NXTOT + bcum;
    const int gy = (N + 127) / 128;
    const int BIG = 0x40000000;

    // epilogue tables
    EpiTab T1F;  // z | extras
    T1F.start[0] = 0;     T1F.f[0] = qb;      T1F.h[0] = nullptr; T1F.stride[0] = ZCOLS;
    T1F.start[1] = ZCOLS; T1F.f[1] = extrasb; T1F.h[1] = nullptr; T1F.stride[1] = 128;
    T1F.start[2] = BIG; T1F.start[3] = BIG; T1F.f[2] = T1F.f[3] = nullptr; T1F.h[2] = T1F.h[3] = nullptr;
    T1F.stride[2] = T1F.stride[3] = 1;
    EpiTab T1B;  // v | skip
    T1B.start[0] = 0;          T1B.f[0] = nullptr; T1B.h[0] = vb;    T1B.stride[0] = HEADS * D1;
    T1B.start[1] = HEADS * D1; T1B.f[1] = skipb;   T1B.h[1] = nullptr; T1B.stride[1] = D1;
    T1B.start[2] = BIG; T1B.start[3] = BIG; T1B.f[2] = T1B.f[3] = nullptr; T1B.h[2] = T1B.h[3] = nullptr;
    T1B.stride[2] = T1B.stride[3] = 1;
    EpiTab T2F;  // q | k
    T2F.start[0] = 0;          T2F.f[0] = qb;      T2F.h[0] = nullptr; T2F.stride[0] = HEADS * D2;
    T2F.start[1] = HEADS * D2; T2F.f[1] = nullptr; T2F.h[1] = kb;      T2F.stride[1] = HEADS * D2;
    T2F.start[2] = BIG; T2F.start[3] = BIG; T2F.f[2] = T2F.f[3] = nullptr; T2F.h[2] = T2F.h[3] = nullptr;
    T2F.stride[2] = T2F.stride[3] = 1;
    EpiTab T2B;  // v | skip
    T2B.start[0] = 0;          T2B.f[0] = nullptr; T2B.h[0] = vb;    T2B.stride[0] = HEADS * D2;
    T2B.start[1] = HEADS * D2; T2B.f[1] = skipb;   T2B.h[1] = nullptr; T2B.stride[1] = D2;
    T2B.start[2] = BIG; T2B.start[3] = BIG; T2B.f[2] = T2B.f[3] = nullptr; T2B.h[2] = T2B.h[3] = nullptr;
    T2B.stride[2] = T2B.stride[3] = 1;
    EpiTab T3F;
    T3F.start[0] = 0;          T3F.f[0] = qb;      T3F.h[0] = nullptr; T3F.stride[0] = HEADS * D3;
    T3F.start[1] = HEADS * D3; T3F.f[1] = nullptr; T3F.h[1] = kb;      T3F.stride[1] = HEADS * D3;
    T3F.start[2] = BIG; T3F.start[3] = BIG; T3F.f[2] = T3F.f[3] = nullptr; T3F.h[2] = T3F.h[3] = nullptr;
    T3F.stride[2] = T3F.stride[3] = 1;
    EpiTab T3B;
    T3B.start[0] = 0;          T3B.f[0] = nullptr; T3B.h[0] = vb;    T3B.stride[0] = HEADS * D3;
    T3B.start[1] = HEADS * D3; T3B.f[1] = skipb;   T3B.h[1] = nullptr; T3B.stride[1] = D3;
    T3B.start[2] = BIG; T3B.start[3] = BIG; T3B.f[2] = T3B.f[3] = nullptr; T3B.h[2] = T3B.h[3] = nullptr;
    T3B.stride[2] = T3B.stride[3] = 1;

    // launch order: gemm_fused L1 (bf16 v|skip) at slot 5 (ncu capture)
    make_m<<<MCOLS, 128>>>(W[0], W[1], Bv[0], Bv[1], Mfullb, Mbiasb);                   // 1
    pack_all<<<(int)((packTotal + 255) / 256), 256>>>(P, WFb, Whi, Wlo, x16b, Ahi, Alo,
                                                      biasb, wcum, NXTOT, bcum);        // 2
    cudaMemsetAsync(degb, 0, N * sizeof(int));                                          // 3
    count_deg<<<(E + 255) / 256, 256>>>(ei, degb, E);                                   // 4
    gemm_fused<<<dim3(B_N1 / 128, gy), 256>>>(Ahi, Alo, Whi + WB_BASE1, Wlo + WB_BASE1,
                                              biasb + BB1 + F_N1, T1B, N, B_N1, F_IN);  // 5 <- profiled
    gemm_half<<<dim3(F_N1 / 128, gy), 256>>>(x16b, WFb + WF_BASE1,
                                             biasb + BB1, T1F, N, F_N1, F_IN);          // 6
    scan_deg<<<1, 1024>>>(degb, ptrb, fillb, N);                                        // 7
    fill_csr<<<(E + 255) / 256, 256>>>(ei, fillb, csrb, E);                             // 8
    attn1_kernel<<<N, 256>>>(qb, x16b, extrasb, vb, ptrb, csrb, skipb,
                             Af16b, Ahi, Alo);                                          // 9

    gemm_half<<<dim3(F_N2 / 128, gy), 256>>>(Af16b, WFb + WF_BASE2,
                                             biasb + BB2, T2F, N, F_N2, D1);
    gemm_fused<<<dim3(B_N2 / 128, gy), 256>>>(Ahi, Alo, Whi + WB_BASE2, Wlo + WB_BASE2,
                                              biasb + BB2 + F_N2, T2B, N, B_N2, D1);
    attn_kernel<D2, true><<<N, 256>>>(qb, kb, vb, ptrb, csrb, skipb,
                                      nullptr, Af16b, Ahi, Alo);

    gemm_half<<<dim3(F_N3 / 128, gy), 256>>>(Af16b, WFb + WF_BASE3,
                                             biasb + BB3, T3F, N, F_N3, D2);
    gemm_fused<<<dim3(B_N3 / 128, gy), 256>>>(Ahi, Alo, Whi + WB_BASE3, Wlo + WB_BASE3,
                                              biasb + BB3 + F_N3, T3B, N, B_N3, D2);
    attn_kernel<D3, false><<<N, 256>>>(qb, kb, vb, ptrb, csrb, skipb,
                                       hA, nullptr, nullptr, nullptr);

    // ---- pooling + fc ----
    init_gmax<<<1, 64>>>(gmaxb);
    cudaMemsetAsync(gsumb, 0, N_GRAPHS * sizeof(float));
    cudaMemsetAsync(poolb, 0, N_GRAPHS * D3 * sizeof(float));
    gate_kernel<<<(N * 32 + 255) / 256, 256>>>(hA, w_g, b_g, batch, gateb, gmaxb, N);
    exp_pool<<<N, D3>>>(hA, gateb, batch, gmaxb, gsumb, poolb);
    fc_kernel<<<1, 1024>>>(poolb, gsumb, w_fc, b_fc, out);
}

// round 12
// speedup vs baseline: 2.0083x; 1.2120x over previous
#include <cuda_runtime.h>
#include <cuda_bf16.h>
#include <cuda_fp16.h>
#include <mma.h>
#include <math.h>
#include <stdint.h>

using namespace nvcuda;

// ---------------- problem constants ----------------
#define N_NODES 10000
#define N_EDGES 80000
#define N_GRAPHS 64
#define HEADS 8
#define F_IN 128
#define D1 512
#define D2 256
#define D3 128
#define OUT_DIM 10

// layer-1 factored logits: z(1024) + extras(128)
#define ZCOLS (HEADS * F_IN)          // 1024
#define MCOLS (ZCOLS + 128)           // 1152

// fp16 GEMM buffer: L1 [Mfull|v] | L2 [q|k|v] | L3 [q|k|v]
#define F_N1 (MCOLS + HEADS * D1)     // 5248
#define F_N2 (3 * HEADS * D2)         // 6144
#define F_N3 (3 * HEADS * D3)         // 3072
#define WF_BASE1 0LL
#define WF_BASE2 ((long long)F_IN * F_N1)
#define WF_BASE3 (WF_BASE2 + (long long)D1 * F_N2)
#define WF_TOTAL (WF_BASE3 + (long long)D2 * F_N3)

// bf16x3 buffer: skip only per layer
#define B_N1 D1                       // 512
#define B_N2 D2                       // 256
#define B_N3 D3                       // 128
#define WB_BASE1 0LL
#define WB_BASE2 ((long long)F_IN * B_N1)
#define WB_BASE3 (WB_BASE2 + (long long)D1 * B_N2)
#define WB_TOTAL (WB_BASE3 + (long long)D2 * B_N3)

// bias layout: per layer [fp16-region | skip]
#define BB1 0
#define BB2 (F_N1 + B_N1)                 // 5760
#define BB3 (BB2 + F_N2 + B_N2)           // 12160
#define BTOTAL (BB3 + F_N3 + B_N3)        // 15360
#define NXTOT (N_NODES * F_IN)

// ---------------- device scratch (static, no allocs) ----------------
__device__ float g_q[(size_t)N_NODES * (HEADS * D1)];      // q (L2/L3) or z (L1)
__device__ __half g_k[(size_t)N_NODES * (HEADS * D1)];
__device__ __half g_v[(size_t)N_NODES * (HEADS * D1)];
__device__ float g_skip[(size_t)N_NODES * D1];
__device__ float g_hA[(size_t)N_NODES * D1];

__device__ float g_extras[(size_t)N_NODES * 128];          // alpha(8) beta(8) pad
__device__ __half g_x16[(size_t)N_NODES * F_IN];
__device__ __half g_Af16[(size_t)N_NODES * D1];
__device__ float g_Mfull[F_IN * MCOLS];
__device__ float g_Mbias[MCOLS];

__device__ __nv_bfloat16 g_Ahi[(size_t)N_NODES * D1];
__device__ __nv_bfloat16 g_Alo[(size_t)N_NODES * D1];
__device__ __half g_WF[WF_TOTAL];
__device__ __nv_bfloat16 g_Whi[WB_TOTAL];
__device__ __nv_bfloat16 g_Wlo[WB_TOTAL];
__device__ float g_bias[BTOTAL];

__device__ int g_deg[N_NODES];
__device__ int g_ptr[N_NODES + 1];
__device__ int g_fill[N_NODES];
__device__ int g_csr_src[N_EDGES];

__device__ float g_gate[N_NODES];
__device__ float g_gmax[N_GRAPHS];
__device__ float g_gsum[N_GRAPHS];
__device__ float g_pool[N_GRAPHS * D3];

// ---------------- cp.async helpers ----------------
__device__ __forceinline__ void cp16(uint32_t dst, const void* src)
{
    asm volatile("cp.async.cg.shared.global [%0], [%1], 16;" :: "r"(dst), "l"(src));
}
__device__ __forceinline__ void cp_commit() { asm volatile("cp.async.commit_group;"); }
template <int Np>
__device__ __forceinline__ void cp_wait() { asm volatile("cp.async.wait_group %0;" :: "n"(Np)); }

// ---------------- layer-1 factorization precompute ----------------
__global__ void make_m(const float* __restrict__ wq, const float* __restrict__ wk,
                       const float* __restrict__ bq, const float* __restrict__ bk,
                       float* __restrict__ Mfull, float* __restrict__ Mbias)
{
    __shared__ float col[D1];
    __shared__ float red[128];
    const int j = blockIdx.x;
    const int tid = threadIdx.x;

    if (j >= 1040) {
        Mfull[tid * MCOLS + j] = 0.f;
        if (tid == 0) Mbias[j] = 0.f;
        return;
    }

    int h;
    const float* mat;
    if (j < ZCOLS)        { h = j >> 7;   mat = wq; }
    else if (j < 1032)    { h = j - 1024; mat = wq; }
    else                  { h = j - 1032; mat = wk; }
    const int base = h * D1;

    if (j < ZCOLS) {
        const int jj = j & 127;
        for (int c = tid; c < D1; c += 128) col[c] = wk[(size_t)jj * (HEADS * D1) + base + c];
    } else if (j < 1032) {
        for (int c = tid; c < D1; c += 128) col[c] = bk[base + c];
    } else {
        for (int c = tid; c < D1; c += 128) col[c] = bq[base + c];
    }
    __syncthreads();

    const float4* row4 = reinterpret_cast<const float4*>(mat + (size_t)tid * (HEADS * D1) + base);
    float acc = 0.f;
#pragma unroll 4
    for (int c = 0; c < D1 / 4; c++) {
        const float4 r = row4[c];
        acc += r.x * col[c * 4 + 0] + r.y * col[c * 4 + 1]
             + r.z * col[c * 4 + 2] + r.w * col[c * 4 + 3];
    }
    Mfull[tid * MCOLS + j] = acc;

    if (j >= ZCOLS && j < 1032) {
        float p = 0.f;
        for (int c = tid; c < D1; c += 128) p += bq[base + c] * bk[base + c];
        red[tid] = p;
        __syncthreads();
        if (tid < 64) red[tid] += red[tid + 64];
        __syncthreads();
        if (tid < 32) {
            float t = red[tid] + red[tid + 32];
#pragma unroll
            for (int o = 16; o > 0; o >>= 1) t += __shfl_down_sync(0xffffffffu, t, o);
            if (tid == 0) Mbias[j] = t;
        }
    } else {
        if (tid == 0) Mbias[j] = 0.f;
    }
}

// ---------------- one-shot packing ----------------
struct PackArgs {
    const float* wsrc[12];
    long long wcum[13];
    int wncols[12];
    long long wdstBase[12];
    int wntot[12];
    int wcoff[12];
    int wIsHalf[12];
    const float* bsrc[12];
    int bcum[13];
    int boff[12];
    const float* x;
};

__global__ void pack_all(PackArgs P, __half* __restrict__ WF,
                         __nv_bfloat16* __restrict__ Whi, __nv_bfloat16* __restrict__ Wlo,
                         __half* __restrict__ x16,
                         __nv_bfloat16* __restrict__ Ahi, __nv_bfloat16* __restrict__ Alo,
                         float* __restrict__ bias, long long wtotal, long long xtotal, int btotal)
{
    long long i = (long long)blockIdx.x * blockDim.x + threadIdx.x;
    if (i < wtotal) {
        int r = 0;
        while (i >= P.wcum[r + 1]) r++;
        const long long li = i - P.wcum[r];
        const int nc = P.wncols[r];
        const int k = (int)(li / nc), c = (int)(li % nc);
        const float v = P.wsrc[r][li];
        const long long di = P.wdstBase[r] + (long long)k * P.wntot[r] + P.wcoff[r] + c;
        if (P.wIsHalf[r]) {
            WF[di] = __float2half(v);
        } else {
            __nv_bfloat16 h = __float2bfloat16(v);
            Whi[di] = h;
            Wlo[di] = __float2bfloat16(v - __bfloat162float(h));
        }
        return;
    }
    i -= wtotal;
    if (i < xtotal) {
        const float v = P.x[i];
        __nv_bfloat16 h = __float2bfloat16(v);
        Ahi[i] = h;
        Alo[i] = __float2bfloat16(v - __bfloat162float(h));
        x16[i] = __float2half(v);
        return;
    }
    int j = (int)(i - xtotal);
    if (j < btotal) {
        int r = 0;
        while (j >= P.bcum[r + 1]) r++;
        bias[P.boff[r] + (j - P.bcum[r])] = P.bsrc[r][j - P.bcum[r]];
    }
}

// ---------------- epilogue routing table ----------------
struct EpiTab {
    float* f[4];
    __half* h[4];
    int stride[4];
    int start[4];
};

// ---------------- bf16x3 tensor-core GEMM (skip path) ----------------
#define LDA 24
#define LDB 136
#define ASZ (128 * LDA)
#define BSZ (16 * LDB)
#define STAGE_E (2 * ASZ + 2 * BSZ)

__global__ __launch_bounds__(256, 2)
void gemm_fused(const __nv_bfloat16* __restrict__ Ahi, const __nv_bfloat16* __restrict__ Alo,
                const __nv_bfloat16* __restrict__ Bhi, const __nv_bfloat16* __restrict__ Blo,
                const float* __restrict__ bias, EpiTab T,
                int M, int N, int K)
{
    __shared__ __align__(16) __nv_bfloat16 sm[2 * STAGE_E];

    const int tid = threadIdx.x;
    const int warpId = tid >> 5;
    const int lane = tid & 31;
    const int wm = warpId >> 2;
    const int wn = warpId & 3;
    const int bm = blockIdx.y * 128;
    const int bn = blockIdx.x * 128;

    const int arow = tid >> 1, ac8 = (tid & 1) * 8;
    const int brow = tid >> 4, bc8 = (tid & 15) * 8;

    wmma::fragment<wmma::accumulator, 16, 16, 16, float> acc[4][2];
#pragma unroll
    for (int i = 0; i < 4; i++)
#pragma unroll
        for (int j = 0; j < 2; j++) wmma::fill_fragment(acc[i][j], 0.f);

    auto issue = [&](int kb, int s) {
        __nv_bfloat16* base = sm + s * STAGE_E;
        __nv_bfloat16* pAh = base + arow * LDA + ac8;
        __nv_bfloat16* pAl = pAh + ASZ;
        const int gr = bm + arow;
        if (gr < M) {
            const size_t off = (size_t)gr * K + kb + ac8;
            cp16((uint32_t)__cvta_generic_to_shared(pAh), Ahi + off);
            cp16((uint32_t)__cvta_generic_to_shared(pAl), Alo + off);
        } else {
            uint4 z = make_uint4(0, 0, 0, 0);
            *reinterpret_cast<uint4*>(pAh) = z;
            *reinterpret_cast<uint4*>(pAl) = z;
        }
        __nv_bfloat16* pBh = base + 2 * ASZ + brow * LDB + bc8;
        const size_t boff = (size_t)(kb + brow) * N + bn + bc8;
        cp16((uint32_t)__cvta_generic_to_shared(pBh), Bhi + boff);
        cp16((uint32_t)__cvta_generic_to_shared(pBh + BSZ), Blo + boff);
        cp_commit();
    };

    const int nk = K >> 4;
    issue(0, 0);

    for (int it = 0; it < nk; ++it) {
        const int s = it & 1;
        if (it + 1 < nk) { issue((it + 1) << 4, s ^ 1); cp_wait<1>(); }
        else             { cp_wait<0>(); }
        __syncthreads();

        const __nv_bfloat16* Ah = sm + s * STAGE_E;
        const __nv_bfloat16* Al = Ah + ASZ;
        const __nv_bfloat16* Bh = Ah + 2 * ASZ;
        const __nv_bfloat16* Bl = Bh + BSZ;

        wmma::fragment<wmma::matrix_a, 16, 16, 16, __nv_bfloat16, wmma::row_major> ah[4], al[4];
        wmma::fragment<wmma::matrix_b, 16, 16, 16, __nv_bfloat16, wmma::row_major> bh[2], bl[2];
#pragma unroll
        for (int i = 0; i < 4; i++) {
            wmma::load_matrix_sync(ah[i], Ah + (wm * 64 + i * 16) * LDA, LDA);
            wmma::load_matrix_sync(al[i], Al + (wm * 64 + i * 16) * LDA, LDA);
        }
#pragma unroll
        for (int j = 0; j < 2; j++) {
            wmma::load_matrix_sync(bh[j], Bh + wn * 32 + j * 16, LDB);
            wmma::load_matrix_sync(bl[j], Bl + wn * 32 + j * 16, LDB);
        }
#pragma unroll
        for (int i = 0; i < 4; i++)
#pragma unroll
            for (int j = 0; j < 2; j++) {
                wmma::mma_sync(acc[i][j], ah[i], bh[j], acc[i][j]);
                wmma::mma_sync(acc[i][j], ah[i], bl[j], acc[i][j]);
                wmma::mma_sync(acc[i][j], al[i], bh[j], acc[i][j]);
            }
        __syncthreads();
    }

    const int r = (bn >= T.start[3]) ? 3 : (bn >= T.start[2]) ? 2 : (bn >= T.start[1]) ? 1 : 0;
    float* fdst = T.f[r];
    __half* hdst = T.h[r];
    const int lcb = bn - T.start[r];
    const int stride = T.stride[r];

    float* wb = reinterpret_cast<float*>(sm) + warpId * 256;
#pragma unroll
    for (int i = 0; i < 4; i++)
#pragma unroll
        for (int j = 0; j < 2; j++) {
            wmma::store_matrix_sync(wb, acc[i][j], 16, wmma::mem_row_major);
            __syncwarp();
            const int r0 = bm + wm * 64 + i * 16;
            const int c0 = bn + wn * 32 + j * 16;
#pragma unroll
            for (int e = lane; e < 64; e += 32) {
                const int rr = e >> 2, c4 = (e & 3) * 4;
                if (r0 + rr >= M) continue;
                float4 vv = *reinterpret_cast<float4*>(wb + rr * 16 + c4);
                const int col = c0 + c4;
                vv.x += bias[col + 0];
                vv.y += bias[col + 1];
                vv.z += bias[col + 2];
                vv.w += bias[col + 3];
                const size_t o = (size_t)(r0 + rr) * stride + (lcb + (col - bn));
                if (fdst) {
                    *reinterpret_cast<float4*>(fdst + o) = vv;
                } else {
                    uint2 p;
                    *reinterpret_cast<__half2*>(&p.x) = __floats2half2_rn(vv.x, vv.y);
                    *reinterpret_cast<__half2*>(&p.y) = __floats2half2_rn(vv.z, vv.w);
                    *reinterpret_cast<uint2*>(hdst + o) = p;
                }
            }
            __syncwarp();
        }
}

// ---------------- fp16 single-pass GEMM (q|k|v / z|extras|v), BK=32 ----------------
#define LDAH 40
#define LDBH 136
#define ASZH (128 * LDAH)
#define BSZH (32 * LDBH)
#define STAGE_H (ASZH + BSZH)

__global__ __launch_bounds__(256, 2)
void gemm_half(const __half* __restrict__ A, const __half* __restrict__ B,
               const float* __restrict__ bias, EpiTab T,
               int M, int N, int K)
{
    __shared__ __align__(16) __half sm[2 * STAGE_H];

    const int tid = threadIdx.x;
    const int warpId = tid >> 5;
    const int lane = tid & 31;
    const int wm = warpId >> 2;
    const int wn = warpId & 3;
    const int bm = blockIdx.y * 128;
    const int bn = blockIdx.x * 128;

    const int ar = tid >> 1, ac = (tid & 1) * 16;
    const int br = tid >> 3, bc = (tid & 7) * 16;

    wmma::fragment<wmma::accumulator, 16, 16, 16, float> acc[4][2];
#pragma unroll
    for (int i = 0; i < 4; i++)
#pragma unroll
        for (int j = 0; j < 2; j++) wmma::fill_fragment(acc[i][j], 0.f);

    auto issue = [&](int kb, int s) {
        __half* base = sm + s * STAGE_H;
        __half* pA = base + ar * LDAH + ac;
        const int gr = bm + ar;
        if (gr < M) {
            const size_t off = (size_t)gr * K + kb + ac;
            cp16((uint32_t)__cvta_generic_to_shared(pA),     A + off);
            cp16((uint32_t)__cvta_generic_to_shared(pA + 8), A + off + 8);
        } else {
            uint4 z = make_uint4(0, 0, 0, 0);
            *reinterpret_cast<uint4*>(pA) = z;
            *reinterpret_cast<uint4*>(pA + 8) = z;
        }
        __half* pB = base + ASZH + br * LDBH + bc;
        const size_t boff = (size_t)(kb + br) * N + bn + bc;
        cp16((uint32_t)__cvta_generic_to_shared(pB),     B + boff);
        cp16((uint32_t)__cvta_generic_to_shared(pB + 8), B + boff + 8);
        cp_commit();
    };

    const int nk = K >> 5;
    issue(0, 0);

    for (int it = 0; it < nk; ++it) {
        const int s = it & 1;
        if (it + 1 < nk) { issue((it + 1) << 5, s ^ 1); cp_wait<1>(); }
        else             { cp_wait<0>(); }
        __syncthreads();

        const __half* As = sm + s * STAGE_H;
        const __half* Bs = As + ASZH;

#pragma unroll
        for (int kk = 0; kk < 2; kk++) {
            wmma::fragment<wmma::matrix_a, 16, 16, 16, __half, wmma::row_major> af[4];
            wmma::fragment<wmma::matrix_b, 16, 16, 16, __half, wmma::row_major> bf[2];
#pragma unroll
            for (int i = 0; i < 4; i++)
                wmma::load_matrix_sync(af[i], As + (wm * 64 + i * 16) * LDAH + kk * 16, LDAH);
#pragma unroll
            for (int j = 0; j < 2; j++)
                wmma::load_matrix_sync(bf[j], Bs + (kk * 16) * LDBH + wn * 32 + j * 16, LDBH);
#pragma unroll
            for (int i = 0; i < 4; i++)
#pragma unroll
                for (int j = 0; j < 2; j++)
                    wmma::mma_sync(acc[i][j], af[i], bf[j], acc[i][j]);
        }
        __syncthreads();
    }

    const int r = (bn >= T.start[3]) ? 3 : (bn >= T.start[2]) ? 2 : (bn >= T.start[1]) ? 1 : 0;
    float* fdst = T.f[r];
    __half* hdst = T.h[r];
    const int lcb = bn - T.start[r];
    const int stride = T.stride[r];

    float* wb = reinterpret_cast<float*>(sm) + warpId * 256;
#pragma unroll
    for (int i = 0; i < 4; i++)
#pragma unroll
        for (int j = 0; j < 2; j++) {
            wmma::store_matrix_sync(wb, acc[i][j], 16, wmma::mem_row_major);
            __syncwarp();
            const int r0 = bm + wm * 64 + i * 16;
            const int c0 = bn + wn * 32 + j * 16;
#pragma unroll
            for (int e = lane; e < 64; e += 32) {
                const int rr = e >> 2, c4 = (e & 3) * 4;
                if (r0 + rr >= M) continue;
                float4 vv = *reinterpret_cast<float4*>(wb + rr * 16 + c4);
                const int col = c0 + c4;
                vv.x += bias[col + 0];
                vv.y += bias[col + 1];
                vv.z += bias[col + 2];
                vv.w += bias[col + 3];
                const size_t o = (size_t)(r0 + rr) * stride + (lcb + (col - bn));
                if (fdst) {
                    *reinterpret_cast<float4*>(fdst + o) = vv;
                } else {
                    uint2 p;
                    *reinterpret_cast<__half2*>(&p.x) = __floats2half2_rn(vv.x, vv.y);
                    *reinterpret_cast<__half2*>(&p.y) = __floats2half2_rn(vv.z, vv.w);
                    *reinterpret_cast<uint2*>(hdst + o) = p;
                }
            }
            __syncwarp();
        }
}

// ---------------- CSR build ----------------
__global__ void count_deg(const int* __restrict__ ei, int* __restrict__ deg, int E)
{
    int e = blockIdx.x * blockDim.x + threadIdx.x;
    if (e < E) atomicAdd(&deg[ei[E + e]], 1);
}

__global__ void scan_deg(const int* __restrict__ deg, int* __restrict__ ptr,
                         int* __restrict__ fill, int n)
{
    constexpr int PER = 10;
    const int tid = threadIdx.x;
    const int lane = tid & 31, wid = tid >> 5;
    const int base = tid * PER;

    int vals[PER];
    int s = 0;
#pragma unroll
    for (int i = 0; i < PER; i++) {
        const int idx = base + i;
        vals[i] = (idx < n) ? deg[idx] : 0;
        s += vals[i];
    }
    int sc = s;
#pragma unroll
    for (int o = 1; o < 32; o <<= 1) {
        int t = __shfl_up_sync(0xffffffffu, sc, o);
        if (lane >= o) sc += t;
    }
    __shared__ int wsum[32];
    if (lane == 31) wsum[wid] = sc;
    __syncthreads();
    if (wid == 0) {
        int w = wsum[lane];
#pragma unroll
        for (int o = 1; o < 32; o <<= 1) {
            int t = __shfl_up_sync(0xffffffffu, w, o);
            if (lane >= o) w += t;
        }
        wsum[lane] = w;
    }
    __syncthreads();
    int run = (sc - s) + (wid > 0 ? wsum[wid - 1] : 0);
#pragma unroll
    for (int i = 0; i < PER; i++) {
        const int idx = base + i;
        if (idx < n) { ptr[idx] = run; fill[idx] = run; }
        run += vals[i];
    }
    if (tid == 1023) ptr[n] = run;
}

__global__ void fill_csr(const int* __restrict__ ei, int* __restrict__ fill,
                         int* __restrict__ csr_src, int E)
{
    int e = blockIdx.x * blockDim.x + threadIdx.x;
    if (e < E) {
        const int d = ei[E + e];
        const int pos = atomicAdd(&fill[d], 1);
        csr_src[pos] = ei[e];
    }
}

// ---------------- layer-1 attention (factored logits) ----------------
__global__ void attn1_kernel(const float* __restrict__ z, const __half* __restrict__ x16,
                             const float* __restrict__ ex, const __half* __restrict__ v,
                             const int* __restrict__ ptr, const int* __restrict__ csr_src,
                             const float* __restrict__ skip,
                             __half* __restrict__ outF16,
                             __nv_bfloat16* __restrict__ outHi, __nv_bfloat16* __restrict__ outLo)
{
    constexpr int C = D1;
    constexpr int F4 = C / 128;
    __shared__ float red[HEADS * C];

    const int dst  = blockIdx.x;
    const int warp = threadIdx.x >> 5;
    const int lane = threadIdx.x & 31;
    const float scale = rsqrtf((float)C);

    const int beg = ptr[dst], end = ptr[dst + 1];

    const float4 zr = reinterpret_cast<const float4*>(z + (size_t)dst * ZCOLS + warp * F_IN)[lane];
    const float alpha = ex[(size_t)dst * 128 + warp];

    float4 acc[F4];
#pragma unroll
    for (int i = 0; i < F4; i++) acc[i] = make_float4(0.f, 0.f, 0.f, 0.f);
    float m = -INFINITY, s = 0.f;

    for (int j = beg; j < end; j++) {
        const int src = csr_src[j];
        const uint2 xx = reinterpret_cast<const uint2*>(x16 + (size_t)src * F_IN)[lane];
        const float2 x0 = __half22float2(*reinterpret_cast<const __half2*>(&xx.x));
        const float2 x1 = __half22float2(*reinterpret_cast<const __half2*>(&xx.y));
        float d = zr.x * x0.x + zr.y * x0.y + zr.z * x1.x + zr.w * x1.y;
#pragma unroll
        for (int o = 16; o > 0; o >>= 1) d += __shfl_xor_sync(0xffffffffu, d, o);
        const float beta = ex[(size_t)src * 128 + 8 + warp];
        const float a = (d + alpha + beta) * scale;
        const float mn = fmaxf(m, a);
        const float corr = expf(m - mn);
        const float w = expf(a - mn);
        s = s * corr + w;
        m = mn;
        const uint2* vrow = reinterpret_cast<const uint2*>(v + (size_t)src * (HEADS * C) + warp * C);
#pragma unroll
        for (int i = 0; i < F4; i++) {
            const uint2 vvp = vrow[lane + 32 * i];
            const float2 v0 = __half22float2(*reinterpret_cast<const __half2*>(&vvp.x));
            const float2 v1 = __half22float2(*reinterpret_cast<const __half2*>(&vvp.y));
            acc[i].x = acc[i].x * corr + w * v0.x;
            acc[i].y = acc[i].y * corr + w * v0.y;
            acc[i].z = acc[i].z * corr + w * v1.x;
            acc[i].w = acc[i].w * corr + w * v1.y;
        }
    }

    const float inv = (end > beg) ? (1.f / (s + 1e-16f)) : 0.f;
#pragma unroll
    for (int i = 0; i < F4; i++) {
        float4 o = make_float4(acc[i].x * inv, acc[i].y * inv, acc[i].z * inv, acc[i].w * inv);
        *reinterpret_cast<float4*>(&red[warp * C + i * 128 + lane * 4]) = o;
    }
    __syncthreads();

    for (int f = threadIdx.x; f < C; f += blockDim.x) {
        float t = 0.f;
#pragma unroll
        for (int h = 0; h < HEADS; h++) t += red[h * C + f];
        t = t * (1.f / HEADS) + skip[(size_t)dst * C + f];
        t = (t > 0.f) ? t : expm1f(t);
        const size_t idx = (size_t)dst * C + f;
        __nv_bfloat16 hh = __float2bfloat16(t);
        outHi[idx] = hh;
        outLo[idx] = __float2bfloat16(t - __bfloat162float(hh));
        outF16[idx] = __float2half(t);
    }
}

// ---------------- layers 2/3 attention ----------------
template <int C, bool SPLIT>
__global__ void attn_kernel(const float* __restrict__ q, const __half* __restrict__ k,
                            const __half* __restrict__ v, const int* __restrict__ ptr,
                            const int* __restrict__ csr_src, const float* __restrict__ skip,
                            float* __restrict__ out, __half* __restrict__ outF16,
                            __nv_bfloat16* __restrict__ outHi, __nv_bfloat16* __restrict__ outLo)
{
    constexpr int H = HEADS;
    constexpr int F4 = C / 128;
    __shared__ float red[H * C];

    const int dst  = blockIdx.x;
    const int warp = threadIdx.x >> 5;
    const int lane = threadIdx.x & 31;
    const float scale = rsqrtf((float)C);
    const size_t HC = (size_t)H * C;

    const int beg = ptr[dst], end = ptr[dst + 1];

    const float4* qrow = reinterpret_cast<const float4*>(q + (size_t)dst * HC + warp * C);
    float4 qr[F4], acc[F4];
#pragma unroll
    for (int i = 0; i < F4; i++) {
        qr[i] = qrow[lane + 32 * i];
        acc[i] = make_float4(0.f, 0.f, 0.f, 0.f);
    }
    float m = -INFINITY, s = 0.f;

    for (int j = beg; j < end; j++) {
        const int src = csr_src[j];
        const uint2* krow = reinterpret_cast<const uint2*>(k + (size_t)src * HC + warp * C);
        const uint2* vrow = reinterpret_cast<const uint2*>(v + (size_t)src * HC + warp * C);
        float d = 0.f;
#pragma unroll
        for (int i = 0; i < F4; i++) {
            const uint2 kk = krow[lane + 32 * i];
            const float2 k0 = __half22float2(*reinterpret_cast<const __half2*>(&kk.x));
            const float2 k1 = __half22float2(*reinterpret_cast<const __half2*>(&kk.y));
            d += qr[i].x * k0.x + qr[i].y * k0.y + qr[i].z * k1.x + qr[i].w * k1.y;
        }
#pragma unroll
        for (int o = 16; o > 0; o >>= 1) d += __shfl_xor_sync(0xffffffffu, d, o);
        const float a = d * scale;
        const float mn = fmaxf(m, a);
        const float corr = expf(m - mn);
        const float w = expf(a - mn);
        s = s * corr + w;
        m = mn;
#pragma unroll
        for (int i = 0; i < F4; i++) {
            const uint2 vvp = vrow[lane + 32 * i];
            const float2 v0 = __half22float2(*reinterpret_cast<const __half2*>(&vvp.x));
            const float2 v1 = __half22float2(*reinterpret_cast<const __half2*>(&vvp.y));
            acc[i].x = acc[i].x * corr + w * v0.x;
            acc[i].y = acc[i].y * corr + w * v0.y;
            acc[i].z = acc[i].z * corr + w * v1.x;
            acc[i].w = acc[i].w * corr + w * v1.y;
        }
    }

    const float inv = (end > beg) ? (1.f / (s + 1e-16f)) : 0.f;
#pragma unroll
    for (int i = 0; i < F4; i++) {
        float4 o = make_float4(acc[i].x * inv, acc[i].y * inv, acc[i].z * inv, acc[i].w * inv);
        *reinterpret_cast<float4*>(&red[warp * C + i * 128 + lane * 4]) = o;
    }
    __syncthreads();

    for (int f = threadIdx.x; f < C; f += blockDim.x) {
        float t = 0.f;
#pragma unroll
        for (int h = 0; h < H; h++) t += red[h * C + f];
        t = t * (1.f / H) + skip[(size_t)dst * C + f];
        t = (t > 0.f) ? t : expm1f(t);
        const size_t idx = (size_t)dst * C + f;
        if constexpr (SPLIT) {
            __nv_bfloat16 hh = __float2bfloat16(t);
            outHi[idx] = hh;
            outLo[idx] = __float2bfloat16(t - __bfloat162float(hh));
            outF16[idx] = __float2half(t);
        } else {
            out[idx] = t;
        }
    }
}

// ---------------- global attention pooling ----------------
__global__ void init_gmax(float* gmax)
{
    if (threadIdx.x < N_GRAPHS) gmax[threadIdx.x] = -INFINITY;
}

__global__ void gate_kernel(const float* __restrict__ h, const float* __restrict__ wg,
                            const float* __restrict__ bg, const int* __restrict__ batch,
                            float* __restrict__ gate, float* __restrict__ gmax, int n)
{
    const int node = (blockIdx.x * blockDim.x + threadIdx.x) >> 5;
    const int lane = threadIdx.x & 31;
    if (node >= n) return;
    const float* row = h + (size_t)node * D3;
    float d = 0.f;
#pragma unroll
    for (int i = 0; i < D3 / 32; i++) d += row[lane + 32 * i] * wg[lane + 32 * i];
#pragma unroll
    for (int o = 16; o > 0; o >>= 1) d += __shfl_xor_sync(0xffffffffu, d, o);
    if (lane == 0) {
        d += bg[0];
        gate[node] = d;
        float* addr = &gmax[batch[node]];
        if (d >= 0.f) atomicMax((int*)addr, __float_as_int(d));
        else          atomicMin((unsigned int*)addr, __float_as_uint(d));
    }
}

__global__ void exp_pool(const float* __restrict__ h, const float* __restrict__ gate,
                         const int* __restrict__ batch, const float* __restrict__ gmax,
                         float* __restrict__ gsum, float* __restrict__ pool)
{
    const int node = blockIdx.x;
    const int f = threadIdx.x;
    const int b = batch[node];
    const float e = expf(gate[node] - gmax[b]);
    if (f == 0) atomicAdd(&gsum[b], e);
    atomicAdd(&pool[b * D3 + f], e * h[(size_t)node * D3 + f]);
}

__global__ void fc_kernel(const float* __restrict__ pool, const float* __restrict__ gsum,
                          const float* __restrict__ wfc, const float* __restrict__ bfc,
                          float* __restrict__ out)
{
    const int t = threadIdx.x;
    if (t >= N_GRAPHS * OUT_DIM) return;
    const int g = t / OUT_DIM, o = t % OUT_DIM;
    float s = 0.f;
#pragma unroll 16
    for (int f = 0; f < D3; f++) s += pool[g * D3 + f] * wfc[f * OUT_DIM + o];
    out[g * OUT_DIM + o] = s / (gsum[g] + 1e-16f) + bfc[o];
}

// ---------------- launch ----------------
extern "C" void kernel_launch(void* const* d_in, const int* in_sizes, int n_in,
                              void* d_out, int out_size)
{
    const float* x     = (const float*)d_in[0];
    const int*   ei    = (const int*)d_in[1];
    const int*   batch = (const int*)d_in[2];
    const float* W[12] = { (const float*)d_in[3],  (const float*)d_in[5],
                           (const float*)d_in[7],  (const float*)d_in[9],
                           (const float*)d_in[11], (const float*)d_in[13],
                           (const float*)d_in[15], (const float*)d_in[17],
                           (const float*)d_in[19], (const float*)d_in[21],
                           (const float*)d_in[23], (const float*)d_in[25] };
    const float* Bv[12] = { (const float*)d_in[4],  (const float*)d_in[6],
                            (const float*)d_in[8],  (const float*)d_in[10],
                            (const float*)d_in[12], (const float*)d_in[14],
                            (const float*)d_in[16], (const float*)d_in[18],
                            (const float*)d_in[20], (const float*)d_in[22],
                            (const float*)d_in[24], (const float*)d_in[26] };
    const float* w_g  = (const float*)d_in[27]; const float* b_g  = (const float*)d_in[28];
    const float* w_fc = (const float*)d_in[29]; const float* b_fc = (const float*)d_in[30];
    float* out = (float*)d_out;

    float *qb, *skipb, *hA, *gateb, *gmaxb, *gsumb, *poolb, *biasb, *extrasb, *Mfullb, *Mbiasb;
    __half *kb, *vb, *x16b, *Af16b, *WFb;
    __nv_bfloat16 *Ahi, *Alo, *Whi, *Wlo;
    int *degb, *ptrb, *fillb, *csrb;
    cudaGetSymbolAddress((void**)&qb,     g_q);
    cudaGetSymbolAddress((void**)&kb,     g_k);
    cudaGetSymbolAddress((void**)&vb,     g_v);
    cudaGetSymbolAddress((void**)&skipb,  g_skip);
    cudaGetSymbolAddress((void**)&hA,     g_hA);
    cudaGetSymbolAddress((void**)&extrasb,g_extras);
    cudaGetSymbolAddress((void**)&x16b,   g_x16);
    cudaGetSymbolAddress((void**)&Af16b,  g_Af16);
    cudaGetSymbolAddress((void**)&Mfullb, g_Mfull);
    cudaGetSymbolAddress((void**)&Mbiasb, g_Mbias);
    cudaGetSymbolAddress((void**)&Ahi,    g_Ahi);
    cudaGetSymbolAddress((void**)&Alo,    g_Alo);
    cudaGetSymbolAddress((void**)&WFb,    g_WF);
    cudaGetSymbolAddress((void**)&Whi,    g_Whi);
    cudaGetSymbolAddress((void**)&Wlo,    g_Wlo);
    cudaGetSymbolAddress((void**)&biasb,  g_bias);
    cudaGetSymbolAddress((void**)&degb,   g_deg);
    cudaGetSymbolAddress((void**)&ptrb,   g_ptr);
    cudaGetSymbolAddress((void**)&fillb,  g_fill);
    cudaGetSymbolAddress((void**)&csrb,   g_csr_src);
    cudaGetSymbolAddress((void**)&gateb,  g_gate);
    cudaGetSymbolAddress((void**)&gmaxb,  g_gmax);
    cudaGetSymbolAddress((void**)&gsumb,  g_gsum);
    cudaGetSymbolAddress((void**)&poolb,  g_pool);

    const int N = N_NODES, E = N_EDGES;

    // ---- pack regions ----
    PackArgs P;
    long long wcum = 0;
    int bcum = 0;
    int ri = 0;
    auto addW = [&](const float* src, int K, int ncols, long long base, int ntot, int coff,
                    int isHalf, const float* bsrc, int boff) {
        P.wsrc[ri] = src; P.wcum[ri] = wcum; P.wncols[ri] = ncols;
        P.wdstBase[ri] = base; P.wntot[ri] = ntot; P.wcoff[ri] = coff;
        P.wIsHalf[ri] = isHalf;
        wcum += (long long)K * ncols;
        P.bsrc[ri] = bsrc; P.bcum[ri] = bcum; P.boff[ri] = boff;
        bcum += ncols;
        ri++;
    };
    // L1: [Mfull | v] fp16 ; skip bf16
    addW(Mfullb, F_IN, MCOLS, WF_BASE1, F_N1, 0, 1, Mbiasb, BB1);
    addW(W[2], F_IN, HEADS * D1, WF_BASE1, F_N1, MCOLS, 1, Bv[2], BB1 + MCOLS);
    addW(W[3], F_IN, D1, WB_BASE1, B_N1, 0, 0, Bv[3], BB1 + F_N1);
    // L2: [q|k|v] fp16 ; skip bf16
    addW(W[4], D1, HEADS * D2, WF_BASE2, F_N2, 0, 1, Bv[4], BB2);
    addW(W[5], D1, HEADS * D2, WF_BASE2, F_N2, HEADS * D2, 1, Bv[5], BB2 + HEADS * D2);
    addW(W[6], D1, HEADS * D2, WF_BASE2, F_N2, 2 * HEADS * D2, 1, Bv[6], BB2 + 2 * HEADS * D2);
    addW(W[7], D1, D2, WB_BASE2, B_N2, 0, 0, Bv[7], BB2 + F_N2);
    // L3
    addW(W[8], D2, HEADS * D3, WF_BASE3, F_N3, 0, 1, Bv[8], BB3);
    addW(W[9], D2, HEADS * D3, WF_BASE3, F_N3, HEADS * D3, 1, Bv[9], BB3 + HEADS * D3);
    addW(W[10], D2, HEADS * D3, WF_BASE3, F_N3, 2 * HEADS * D3, 1, Bv[10], BB3 + 2 * HEADS * D3);
    addW(W[11], D2, D3, WB_BASE3, B_N3, 0, 0, Bv[11], BB3 + F_N3);
    P.wcum[ri] = wcum;
    P.bcum[ri] = bcum;
    for (int r2 = ri; r2 < 12; r2++) { P.wcum[r2 + 1] = wcum; P.bcum[r2 + 1] = bcum; }
    P.x = x;

    const long long packTotal = wcum + NXTOT + bcum;
    const int gy = (N + 127) / 128;
    const int BIG = 0x40000000;

    // epilogue tables
    EpiTab T1F;  // z | extras | v
    T1F.start[0] = 0;     T1F.f[0] = qb;      T1F.h[0] = nullptr; T1F.stride[0] = ZCOLS;
    T1F.start[1] = ZCOLS; T1F.f[1] = extrasb; T1F.h[1] = nullptr; T1F.stride[1] = 128;
    T1F.start[2] = MCOLS; T1F.f[2] = nullptr; T1F.h[2] = vb;      T1F.stride[2] = HEADS * D1;
    T1F.start[3] = BIG;   T1F.f[3] = nullptr; T1F.h[3] = nullptr; T1F.stride[3] = 1;
    EpiTab T1B;  // skip
    T1B.start[0] = 0; T1B.f[0] = skipb; T1B.h[0] = nullptr; T1B.stride[0] = D1;
    T1B.start[1] = T1B.start[2] = T1B.start[3] = BIG;
    T1B.f[1] = T1B.f[2] = T1B.f[3] = nullptr; T1B.h[1] = T1B.h[2] = T1B.h[3] = nullptr;
    T1B.stride[1] = T1B.stride[2] = T1B.stride[3] = 1;
    EpiTab T2F;  // q | k | v
    T2F.start[0] = 0;              T2F.f[0] = qb;      T2F.h[0] = nullptr; T2F.stride[0] = HEADS * D2;
    T2F.start[1] = HEADS * D2;     T2F.f[1] = nullptr; T2F.h[1] = kb;      T2F.stride[1] = HEADS * D2;
    T2F.start[2] = 2 * HEADS * D2; T2F.f[2] = nullptr; T2F.h[2] = vb;      T2F.stride[2] = HEADS * D2;
    T2F.start[3] = BIG;            T2F.f[3] = nullptr; T2F.h[3] = nullptr; T2F.stride[3] = 1;
    EpiTab T2B;
    T2B.start[0] = 0; T2B.f[0] = skipb; T2B.h[0] = nullptr; T2B.stride[0] = D2;
    T2B.start[1] = T2B.start[2] = T2B.start[3] = BIG;
    T2B.f[1] = T2B.f[2] = T2B.f[3] = nullptr; T2B.h[1] = T2B.h[2] = T2B.h[3] = nullptr;
    T2B.stride[1] = T2B.stride[2] = T2B.stride[3] = 1;
    EpiTab T3F;
    T3F.start[0] = 0;              T3F.f[0] = qb;      T3F.h[0] = nullptr; T3F.stride[0] = HEADS * D3;
    T3F.start[1] = HEADS * D3;     T3F.f[1] = nullptr; T3F.h[1] = kb;      T3F.stride[1] = HEADS * D3;
    T3F.start[2] = 2 * HEADS * D3; T3F.f[2] = nullptr; T3F.h[2] = vb;      T3F.stride[2] = HEADS * D3;
    T3F.start[3] = BIG;            T3F.f[3] = nullptr; T3F.h[3] = nullptr; T3F.stride[3] = 1;
    EpiTab T3B;
    T3B.start[0] = 0; T3B.f[0] = skipb; T3B.h[0] = nullptr; T3B.stride[0] = D3;
    T3B.start[1] = T3B.start[2] = T3B.start[3] = BIG;
    T3B.f[1] = T3B.f[2] = T3B.f[3] = nullptr; T3B.h[1] = T3B.h[2] = T3B.h[3] = nullptr;
    T3B.stride[1] = T3B.stride[2] = T3B.stride[3] = 1;

    // launch order: gemm_half L1 at slot 5 (ncu capture)
    make_m<<<MCOLS, 128>>>(W[0], W[1], Bv[0], Bv[1], Mfullb, Mbiasb);                   // 1
    pack_all<<<(int)((packTotal + 255) / 256), 256>>>(P, WFb, Whi, Wlo, x16b, Ahi, Alo,
                                                      biasb, wcum, NXTOT, bcum);        // 2
    cudaMemsetAsync(degb, 0, N * sizeof(int));                                          // 3
    count_deg<<<(E + 255) / 256, 256>>>(ei, degb, E);                                   // 4
    gemm_half<<<dim3(F_N1 / 128, gy), 256>>>(x16b, WFb + WF_BASE1,
                                             biasb + BB1, T1F, N, F_N1, F_IN);          // 5 <- profiled
    gemm_fused<<<dim3(B_N1 / 128, gy), 256>>>(Ahi, Alo, Whi + WB_BASE1, Wlo + WB_BASE1,
                                              biasb + BB1 + F_N1, T1B, N, B_N1, F_IN);  // 6
    scan_deg<<<1, 1024>>>(degb, ptrb, fillb, N);                                        // 7
    fill_csr<<<(E + 255) / 256, 256>>>(ei, fillb, csrb, E);                             // 8
    attn1_kernel<<<N, 256>>>(qb, x16b, extrasb, vb, ptrb, csrb, skipb,
                             Af16b, Ahi, Alo);                                          // 9

    gemm_half<<<dim3(F_N2 / 128, gy), 256>>>(Af16b, WFb + WF_BASE2,
                                             biasb + BB2, T2F, N, F_N2, D1);
    gemm_fused<<<dim3(B_N2 / 128, gy), 256>>>(Ahi, Alo, Whi + WB_BASE2, Wlo + WB_BASE2,
                                              biasb + BB2 + F_N2, T2B, N, B_N2, D1);
    attn_kernel<D2, true><<<N, 256>>>(qb, kb, vb, ptrb, csrb, skipb,
                                      nullptr, Af16b, Ahi, Alo);

    gemm_half<<<dim3(F_N3 / 128, gy), 256>>>(Af16b, WFb + WF_BASE3,
                                             biasb + BB3, T3F, N, F_N3, D2);
    gemm_fused<<<dim3(B_N3 / 128, gy), 256>>>(Ahi, Alo, Whi + WB_BASE3, Wlo + WB_BASE3,
                                              biasb + BB3 + F_N3, T3B, N, B_N3, D2);
    attn_kernel<D3, false><<<N, 256>>>(qb, kb, vb, ptrb, csrb, skipb,
                                       hA, nullptr, nullptr, nullptr);

    // ---- pooling + fc ----
    init_gmax<<<1, 64>>>(gmaxb);
    cudaMemsetAsync(gsumb, 0, N_GRAPHS * sizeof(float));
    cudaMemsetAsync(poolb, 0, N_GRAPHS * D3 * sizeof(float));
    gate_kernel<<<(N * 32 + 255) / 256, 256>>>(hA, w_g, b_g, batch, gateb, gmaxb, N);
    exp_pool<<<N, D3>>>(hA, gateb, batch, gmaxb, gsumb, poolb);
    fc_kernel<<<1, 1024>>>(poolb, gsumb, w_fc, b_fc, out);
}

// round 13
// speedup vs baseline: 2.1516x; 1.0713x over previous
#include <cuda_runtime.h>
#include <cuda_fp16.h>
#include <mma.h>
#include <math.h>
#include <stdint.h>

using namespace nvcuda;

// ---------------- problem constants ----------------
#define N_NODES 10000
#define N_EDGES 80000
#define N_GRAPHS 64
#define HEADS 8
#define F_IN 128
#define D1 512
#define D2 256
#define D3 128
#define OUT_DIM 10

// layer-1 factored logits: z(1024) + extras(128)
#define ZCOLS (HEADS * F_IN)          // 1024
#define MCOLS (ZCOLS + 128)           // 1152

// one fp16 GEMM per layer: L1 [Mfull|v|skip], L2/L3 [q|k|v|skip]
#define F_N1 (MCOLS + HEADS * D1 + D1)   // 5760
#define F_N2 (3 * HEADS * D2 + D2)       // 6400
#define F_N3 (3 * HEADS * D3 + D3)       // 3200
#define WF_BASE1 0LL
#define WF_BASE2 ((long long)F_IN * F_N1)
#define WF_BASE3 (WF_BASE2 + (long long)D1 * F_N2)
#define WF_TOTAL (WF_BASE3 + (long long)D2 * F_N3)

#define BB1 0
#define BB2 F_N1                      // 5760
#define BB3 (BB2 + F_N2)              // 12160
#define BTOTAL (BB3 + F_N3)           // 15360
#define NXTOT (N_NODES * F_IN)

// ---------------- device scratch (static, no allocs) ----------------
__device__ float g_q[(size_t)N_NODES * (HEADS * D1)];      // q (L2/L3) or z (L1)
__device__ __half g_k[(size_t)N_NODES * (HEADS * D1)];
__device__ __half g_v[(size_t)N_NODES * (HEADS * D1)];
__device__ float g_skip[(size_t)N_NODES * D1];
__device__ float g_hA[(size_t)N_NODES * D1];

__device__ float g_extras[(size_t)N_NODES * 128];          // alpha(8) beta(8) pad
__device__ __half g_x16[(size_t)N_NODES * F_IN];
__device__ __half g_Af16[(size_t)N_NODES * D1];
__device__ float g_Mfull[F_IN * MCOLS];
__device__ float g_Mbias[MCOLS];

__device__ __half g_WF[WF_TOTAL];
__device__ float g_bias[BTOTAL];

__device__ int g_deg[N_NODES];
__device__ int g_ptr[N_NODES + 1];
__device__ int g_fill[N_NODES];
__device__ int g_csr_src[N_EDGES];

__device__ float g_gate[N_NODES];
__device__ float g_gmax[N_GRAPHS];
__device__ float g_gsum[N_GRAPHS];
__device__ float g_pool[N_GRAPHS * D3];

// ---------------- cp.async helpers ----------------
__device__ __forceinline__ void cp16(uint32_t dst, const void* src)
{
    asm volatile("cp.async.cg.shared.global [%0], [%1], 16;" :: "r"(dst), "l"(src));
}
__device__ __forceinline__ void cp_commit() { asm volatile("cp.async.commit_group;"); }
template <int Np>
__device__ __forceinline__ void cp_wait() { asm volatile("cp.async.wait_group %0;" :: "n"(Np)); }

// ---------------- layer-1 factorization precompute ----------------
__global__ void make_m(const float* __restrict__ wq, const float* __restrict__ wk,
                       const float* __restrict__ bq, const float* __restrict__ bk,
                       float* __restrict__ Mfull, float* __restrict__ Mbias)
{
    __shared__ float col[D1];
    __shared__ float red[128];
    const int j = blockIdx.x;
    const int tid = threadIdx.x;

    if (j >= 1040) {
        Mfull[tid * MCOLS + j] = 0.f;
        if (tid == 0) Mbias[j] = 0.f;
        return;
    }

    int h;
    const float* mat;
    if (j < ZCOLS)        { h = j >> 7;   mat = wq; }
    else if (j < 1032)    { h = j - 1024; mat = wq; }
    else                  { h = j - 1032; mat = wk; }
    const int base = h * D1;

    if (j < ZCOLS) {
        const int jj = j & 127;
        for (int c = tid; c < D1; c += 128) col[c] = wk[(size_t)jj * (HEADS * D1) + base + c];
    } else if (j < 1032) {
        for (int c = tid; c < D1; c += 128) col[c] = bk[base + c];
    } else {
        for (int c = tid; c < D1; c += 128) col[c] = bq[base + c];
    }
    __syncthreads();

    const float4* row4 = reinterpret_cast<const float4*>(mat + (size_t)tid * (HEADS * D1) + base);
    float acc = 0.f;
#pragma unroll 4
    for (int c = 0; c < D1 / 4; c++) {
        const float4 r = row4[c];
        acc += r.x * col[c * 4 + 0] + r.y * col[c * 4 + 1]
             + r.z * col[c * 4 + 2] + r.w * col[c * 4 + 3];
    }
    Mfull[tid * MCOLS + j] = acc;

    if (j >= ZCOLS && j < 1032) {
        float p = 0.f;
        for (int c = tid; c < D1; c += 128) p += bq[base + c] * bk[base + c];
        red[tid] = p;
        __syncthreads();
        if (tid < 64) red[tid] += red[tid + 64];
        __syncthreads();
        if (tid < 32) {
            float t = red[tid] + red[tid + 32];
#pragma unroll
            for (int o = 16; o > 0; o >>= 1) t += __shfl_down_sync(0xffffffffu, t, o);
            if (tid == 0) Mbias[j] = t;
        }
    } else {
        if (tid == 0) Mbias[j] = 0.f;
    }
}

// ---------------- one-shot packing (all fp16 weights) ----------------
struct PackArgs {
    const float* wsrc[12];
    long long wcum[13];
    int wncols[12];
    long long wdstBase[12];
    int wntot[12];
    int wcoff[12];
    const float* bsrc[12];
    int bcum[13];
    int boff[12];
    const float* x;
};

__global__ void pack_all(PackArgs P, __half* __restrict__ WF, __half* __restrict__ x16,
                         float* __restrict__ bias, long long wtotal, long long xtotal, int btotal)
{
    long long i = (long long)blockIdx.x * blockDim.x + threadIdx.x;
    if (i < wtotal) {
        int r = 0;
        while (i >= P.wcum[r + 1]) r++;
        const long long li = i - P.wcum[r];
        const int nc = P.wncols[r];
        const int k = (int)(li / nc), c = (int)(li % nc);
        const long long di = P.wdstBase[r] + (long long)k * P.wntot[r] + P.wcoff[r] + c;
        WF[di] = __float2half(P.wsrc[r][li]);
        return;
    }
    i -= wtotal;
    if (i < xtotal) {
        x16[i] = __float2half(P.x[i]);
        return;
    }
    int j = (int)(i - xtotal);
    if (j < btotal) {
        int r = 0;
        while (j >= P.bcum[r + 1]) r++;
        bias[P.boff[r] + (j - P.bcum[r])] = P.bsrc[r][j - P.bcum[r]];
    }
}

// ---------------- epilogue routing table ----------------
struct EpiTab {
    float* f[4];
    __half* h[4];
    int stride[4];
    int start[4];
};

// ---------------- fp16 single-pass GEMM, BK=32 ----------------
#define LDAH 40
#define LDBH 136
#define ASZH (128 * LDAH)
#define BSZH (32 * LDBH)
#define STAGE_H (ASZH + BSZH)

__global__ __launch_bounds__(256, 2)
void gemm_half(const __half* __restrict__ A, const __half* __restrict__ B,
               const float* __restrict__ bias, EpiTab T,
               int M, int N, int K)
{
    __shared__ __align__(16) __half sm[2 * STAGE_H];

    const int tid = threadIdx.x;
    const int warpId = tid >> 5;
    const int lane = tid & 31;
    const int wm = warpId >> 2;
    const int wn = warpId & 3;
    const int bm = blockIdx.y * 128;
    const int bn = blockIdx.x * 128;

    const int ar = tid >> 1, ac = (tid & 1) * 16;
    const int br = tid >> 3, bc = (tid & 7) * 16;

    wmma::fragment<wmma::accumulator, 16, 16, 16, float> acc[4][2];
#pragma unroll
    for (int i = 0; i < 4; i++)
#pragma unroll
        for (int j = 0; j < 2; j++) wmma::fill_fragment(acc[i][j], 0.f);

    auto issue = [&](int kb, int s) {
        __half* base = sm + s * STAGE_H;
        __half* pA = base + ar * LDAH + ac;
        const int gr = bm + ar;
        if (gr < M) {
            const size_t off = (size_t)gr * K + kb + ac;
            cp16((uint32_t)__cvta_generic_to_shared(pA),     A + off);
            cp16((uint32_t)__cvta_generic_to_shared(pA + 8), A + off + 8);
        } else {
            uint4 z = make_uint4(0, 0, 0, 0);
            *reinterpret_cast<uint4*>(pA) = z;
            *reinterpret_cast<uint4*>(pA + 8) = z;
        }
        __half* pB = base + ASZH + br * LDBH + bc;
        const size_t boff = (size_t)(kb + br) * N + bn + bc;
        cp16((uint32_t)__cvta_generic_to_shared(pB),     B + boff);
        cp16((uint32_t)__cvta_generic_to_shared(pB + 8), B + boff + 8);
        cp_commit();
    };

    const int nk = K >> 5;
    issue(0, 0);

    for (int it = 0; it < nk; ++it) {
        const int s = it & 1;
        if (it + 1 < nk) { issue((it + 1) << 5, s ^ 1); cp_wait<1>(); }
        else             { cp_wait<0>(); }
        __syncthreads();

        const __half* As = sm + s * STAGE_H;
        const __half* Bs = As + ASZH;

#pragma unroll
        for (int kk = 0; kk < 2; kk++) {
            wmma::fragment<wmma::matrix_a, 16, 16, 16, __half, wmma::row_major> af[4];
            wmma::fragment<wmma::matrix_b, 16, 16, 16, __half, wmma::row_major> bf[2];
#pragma unroll
            for (int i = 0; i < 4; i++)
                wmma::load_matrix_sync(af[i], As + (wm * 64 + i * 16) * LDAH + kk * 16, LDAH);
#pragma unroll
            for (int j = 0; j < 2; j++)
                wmma::load_matrix_sync(bf[j], Bs + (kk * 16) * LDBH + wn * 32 + j * 16, LDBH);
#pragma unroll
            for (int i = 0; i < 4; i++)
#pragma unroll
                for (int j = 0; j < 2; j++)
                    wmma::mma_sync(acc[i][j], af[i], bf[j], acc[i][j]);
        }
        __syncthreads();
    }

    const int r = (bn >= T.start[3]) ? 3 : (bn >= T.start[2]) ? 2 : (bn >= T.start[1]) ? 1 : 0;
    float* fdst = T.f[r];
    __half* hdst = T.h[r];
    const int lcb = bn - T.start[r];
    const int stride = T.stride[r];

    float* wb = reinterpret_cast<float*>(sm) + warpId * 256;
#pragma unroll
    for (int i = 0; i < 4; i++)
#pragma unroll
        for (int j = 0; j < 2; j++) {
            wmma::store_matrix_sync(wb, acc[i][j], 16, wmma::mem_row_major);
            __syncwarp();
            const int r0 = bm + wm * 64 + i * 16;
            const int c0 = bn + wn * 32 + j * 16;
#pragma unroll
            for (int e = lane; e < 64; e += 32) {
                const int rr = e >> 2, c4 = (e & 3) * 4;
                if (r0 + rr >= M) continue;
                float4 vv = *reinterpret_cast<float4*>(wb + rr * 16 + c4);
                const int col = c0 + c4;
                vv.x += bias[col + 0];
                vv.y += bias[col + 1];
                vv.z += bias[col + 2];
                vv.w += bias[col + 3];
                const size_t o = (size_t)(r0 + rr) * stride + (lcb + (col - bn));
                if (fdst) {
                    *reinterpret_cast<float4*>(fdst + o) = vv;
                } else {
                    uint2 p;
                    *reinterpret_cast<__half2*>(&p.x) = __floats2half2_rn(vv.x, vv.y);
                    *reinterpret_cast<__half2*>(&p.y) = __floats2half2_rn(vv.z, vv.w);
                    *reinterpret_cast<uint2*>(hdst + o) = p;
                }
            }
            __syncwarp();
        }
}

// ---------------- CSR build ----------------
__global__ void count_deg(const int* __restrict__ ei, int* __restrict__ deg, int E)
{
    int e = blockIdx.x * blockDim.x + threadIdx.x;
    if (e < E) atomicAdd(&deg[ei[E + e]], 1);
}

__global__ void scan_deg(const int* __restrict__ deg, int* __restrict__ ptr,
                         int* __restrict__ fill, int n)
{
    constexpr int PER = 10;
    const int tid = threadIdx.x;
    const int lane = tid & 31, wid = tid >> 5;
    const int base = tid * PER;

    int vals[PER];
    int s = 0;
#pragma unroll
    for (int i = 0; i < PER; i++) {
        const int idx = base + i;
        vals[i] = (idx < n) ? deg[idx] : 0;
        s += vals[i];
    }
    int sc = s;
#pragma unroll
    for (int o = 1; o < 32; o <<= 1) {
        int t = __shfl_up_sync(0xffffffffu, sc, o);
        if (lane >= o) sc += t;
    }
    __shared__ int wsum[32];
    if (lane == 31) wsum[wid] = sc;
    __syncthreads();
    if (wid == 0) {
        int w = wsum[lane];
#pragma unroll
        for (int o = 1; o < 32; o <<= 1) {
            int t = __shfl_up_sync(0xffffffffu, w, o);
            if (lane >= o) w += t;
        }
        wsum[lane] = w;
    }
    __syncthreads();
    int run = (sc - s) + (wid > 0 ? wsum[wid - 1] : 0);
#pragma unroll
    for (int i = 0; i < PER; i++) {
        const int idx = base + i;
        if (idx < n) { ptr[idx] = run; fill[idx] = run; }
        run += vals[i];
    }
    if (tid == 1023) ptr[n] = run;
}

__global__ void fill_csr(const int* __restrict__ ei, int* __restrict__ fill,
                         int* __restrict__ csr_src, int E)
{
    int e = blockIdx.x * blockDim.x + threadIdx.x;
    if (e < E) {
        const int d = ei[E + e];
        const int pos = atomicAdd(&fill[d], 1);
        csr_src[pos] = ei[e];
    }
}

// ---------------- layer-1 attention (factored logits, pipelined gather) ----------------
__global__ void attn1_kernel(const float* __restrict__ z, const __half* __restrict__ x16,
                             const float* __restrict__ ex, const __half* __restrict__ v,
                             const int* __restrict__ ptr, const int* __restrict__ csr_src,
                             const float* __restrict__ skip,
                             __half* __restrict__ outF16)
{
    constexpr int C = D1;
    constexpr int F4 = C / 128;
    __shared__ float red[HEADS * C];

    const int dst  = blockIdx.x;
    const int warp = threadIdx.x >> 5;
    const int lane = threadIdx.x & 31;
    const float scale = rsqrtf((float)C);

    const int beg = ptr[dst], end = ptr[dst + 1];

    const float4 zr = reinterpret_cast<const float4*>(z + (size_t)dst * ZCOLS + warp * F_IN)[lane];
    const float alpha = ex[(size_t)dst * 128 + warp];

    float4 acc[F4];
#pragma unroll
    for (int i = 0; i < F4; i++) acc[i] = make_float4(0.f, 0.f, 0.f, 0.f);
    float m = -INFINITY, s = 0.f;

    // pipelined gather: preload edge j's data, prefetch j+1 before computing j
    int srcc = (beg < end) ? csr_src[beg] : 0;
    uint2 xc = make_uint2(0, 0);
    uint2 vc[F4];
    float betac = 0.f;
    if (beg < end) {
        xc = reinterpret_cast<const uint2*>(x16 + (size_t)srcc * F_IN)[lane];
        const uint2* vrow = reinterpret_cast<const uint2*>(v + (size_t)srcc * (HEADS * C) + warp * C);
#pragma unroll
        for (int i = 0; i < F4; i++) vc[i] = vrow[lane + 32 * i];
        betac = ex[(size_t)srcc * 128 + 8 + warp];
    }

    for (int j = beg; j < end; j++) {
        uint2 xn = make_uint2(0, 0);
        uint2 vn[F4];
        float betan = 0.f;
        if (j + 1 < end) {
            const int srcn = csr_src[j + 1];
            xn = reinterpret_cast<const uint2*>(x16 + (size_t)srcn * F_IN)[lane];
            const uint2* vrow = reinterpret_cast<const uint2*>(v + (size_t)srcn * (HEADS * C) + warp * C);
#pragma unroll
            for (int i = 0; i < F4; i++) vn[i] = vrow[lane + 32 * i];
            betan = ex[(size_t)srcn * 128 + 8 + warp];
        }

        const float2 x0 = __half22float2(*reinterpret_cast<const __half2*>(&xc.x));
        const float2 x1 = __half22float2(*reinterpret_cast<const __half2*>(&xc.y));
        float d = zr.x * x0.x + zr.y * x0.y + zr.z * x1.x + zr.w * x1.y;
#pragma unroll
        for (int o = 16; o > 0; o >>= 1) d += __shfl_xor_sync(0xffffffffu, d, o);
        const float a = (d + alpha + betac) * scale;
        const float mn = fmaxf(m, a);
        const float corr = expf(m - mn);
        const float w = expf(a - mn);
        s = s * corr + w;
        m = mn;
#pragma unroll
        for (int i = 0; i < F4; i++) {
            const float2 v0 = __half22float2(*reinterpret_cast<const __half2*>(&vc[i].x));
            const float2 v1 = __half22float2(*reinterpret_cast<const __half2*>(&vc[i].y));
            acc[i].x = acc[i].x * corr + w * v0.x;
            acc[i].y = acc[i].y * corr + w * v0.y;
            acc[i].z = acc[i].z * corr + w * v1.x;
            acc[i].w = acc[i].w * corr + w * v1.y;
        }

        xc = xn;
        betac = betan;
#pragma unroll
        for (int i = 0; i < F4; i++) vc[i] = vn[i];
    }

    const float inv = (end > beg) ? (1.f / (s + 1e-16f)) : 0.f;
#pragma unroll
    for (int i = 0; i < F4; i++) {
        float4 o = make_float4(acc[i].x * inv, acc[i].y * inv, acc[i].z * inv, acc[i].w * inv);
        *reinterpret_cast<float4*>(&red[warp * C + i * 128 + lane * 4]) = o;
    }
    __syncthreads();

    for (int f = threadIdx.x; f < C; f += blockDim.x) {
        float t = 0.f;
#pragma unroll
        for (int h = 0; h < HEADS; h++) t += red[h * C + f];
        t = t * (1.f / HEADS) + skip[(size_t)dst * C + f];
        t = (t > 0.f) ? t : expm1f(t);
        outF16[(size_t)dst * C + f] = __float2half(t);
    }
}

// ---------------- layers 2/3 attention (pipelined gather) ----------------
template <int C, bool F16OUT>
__global__ void attn_kernel(const float* __restrict__ q, const __half* __restrict__ k,
                            const __half* __restrict__ v, const int* __restrict__ ptr,
                            const int* __restrict__ csr_src, const float* __restrict__ skip,
                            float* __restrict__ out, __half* __restrict__ outF16)
{
    constexpr int H = HEADS;
    constexpr int F4 = C / 128;
    __shared__ float red[H * C];

    const int dst  = blockIdx.x;
    const int warp = threadIdx.x >> 5;
    const int lane = threadIdx.x & 31;
    const float scale = rsqrtf((float)C);
    const size_t HC = (size_t)H * C;

    const int beg = ptr[dst], end = ptr[dst + 1];

    const float4* qrow = reinterpret_cast<const float4*>(q + (size_t)dst * HC + warp * C);
    float4 qr[F4], acc[F4];
#pragma unroll
    for (int i = 0; i < F4; i++) {
        qr[i] = qrow[lane + 32 * i];
        acc[i] = make_float4(0.f, 0.f, 0.f, 0.f);
    }
    float m = -INFINITY, s = 0.f;

    uint2 kc[F4], vc[F4];
    if (beg < end) {
        const int srcc = csr_src[beg];
        const uint2* krow = reinterpret_cast<const uint2*>(k + (size_t)srcc * HC + warp * C);
        const uint2* vrow = reinterpret_cast<const uint2*>(v + (size_t)srcc * HC + warp * C);
#pragma unroll
        for (int i = 0; i < F4; i++) { kc[i] = krow[lane + 32 * i]; vc[i] = vrow[lane + 32 * i]; }
    }

    for (int j = beg; j < end; j++) {
        uint2 kn[F4], vn[F4];
        if (j + 1 < end) {
            const int srcn = csr_src[j + 1];
            const uint2* krow = reinterpret_cast<const uint2*>(k + (size_t)srcn * HC + warp * C);
            const uint2* vrow = reinterpret_cast<const uint2*>(v + (size_t)srcn * HC + warp * C);
#pragma unroll
            for (int i = 0; i < F4; i++) { kn[i] = krow[lane + 32 * i]; vn[i] = vrow[lane + 32 * i]; }
        }

        float d = 0.f;
#pragma unroll
        for (int i = 0; i < F4; i++) {
            const float2 k0 = __half22float2(*reinterpret_cast<const __half2*>(&kc[i].x));
            const float2 k1 = __half22float2(*reinterpret_cast<const __half2*>(&kc[i].y));
            d += qr[i].x * k0.x + qr[i].y * k0.y + qr[i].z * k1.x + qr[i].w * k1.y;
        }
#pragma unroll
        for (int o = 16; o > 0; o >>= 1) d += __shfl_xor_sync(0xffffffffu, d, o);
        const float a = d * scale;
        const float mn = fmaxf(m, a);
        const float corr = expf(m - mn);
        const float w = expf(a - mn);
        s = s * corr + w;
        m = mn;
#pragma unroll
        for (int i = 0; i < F4; i++) {
            const float2 v0 = __half22float2(*reinterpret_cast<const __half2*>(&vc[i].x));
            const float2 v1 = __half22float2(*reinterpret_cast<const __half2*>(&vc[i].y));
            acc[i].x = acc[i].x * corr + w * v0.x;
            acc[i].y = acc[i].y * corr + w * v0.y;
            acc[i].z = acc[i].z * corr + w * v1.x;
            acc[i].w = acc[i].w * corr + w * v1.y;
        }

#pragma unroll
        for (int i = 0; i < F4; i++) { kc[i] = kn[i]; vc[i] = vn[i]; }
    }

    const float inv = (end > beg) ? (1.f / (s + 1e-16f)) : 0.f;
#pragma unroll
    for (int i = 0; i < F4; i++) {
        float4 o = make_float4(acc[i].x * inv, acc[i].y * inv, acc[i].z * inv, acc[i].w * inv);
        *reinterpret_cast<float4*>(&red[warp * C + i * 128 + lane * 4]) = o;
    }
    __syncthreads();

    for (int f = threadIdx.x; f < C; f += blockDim.x) {
        float t = 0.f;
#pragma unroll
        for (int h = 0; h < H; h++) t += red[h * C + f];
        t = t * (1.f / H) + skip[(size_t)dst * C + f];
        t = (t > 0.f) ? t : expm1f(t);
        const size_t idx = (size_t)dst * C + f;
        if constexpr (F16OUT) outF16[idx] = __float2half(t);
        else                  out[idx] = t;
    }
}

// ---------------- global attention pooling ----------------
__global__ void init_gmax(float* gmax)
{
    if (threadIdx.x < N_GRAPHS) gmax[threadIdx.x] = -INFINITY;
}

__global__ void gate_kernel(const float* __restrict__ h, const float* __restrict__ wg,
                            const float* __restrict__ bg, const int* __restrict__ batch,
                            float* __restrict__ gate, float* __restrict__ gmax, int n)
{
    const int node = (blockIdx.x * blockDim.x + threadIdx.x) >> 5;
    const int lane = threadIdx.x & 31;
    if (node >= n) return;
    const float* row = h + (size_t)node * D3;
    float d = 0.f;
#pragma unroll
    for (int i = 0; i < D3 / 32; i++) d += row[lane + 32 * i] * wg[lane + 32 * i];
#pragma unroll
    for (int o = 16; o > 0; o >>= 1) d += __shfl_xor_sync(0xffffffffu, d, o);
    if (lane == 0) {
        d += bg[0];
        gate[node] = d;
        float* addr = &gmax[batch[node]];
        if (d >= 0.f) atomicMax((int*)addr, __float_as_int(d));
        else          atomicMin((unsigned int*)addr, __float_as_uint(d));
    }
}

__global__ void exp_pool(const float* __restrict__ h, const float* __restrict__ gate,
                         const int* __restrict__ batch, const float* __restrict__ gmax,
                         float* __restrict__ gsum, float* __restrict__ pool)
{
    const int node = blockIdx.x;
    const int f = threadIdx.x;
    const int b = batch[node];
    const float e = expf(gate[node] - gmax[b]);
    if (f == 0) atomicAdd(&gsum[b], e);
    atomicAdd(&pool[b * D3 + f], e * h[(size_t)node * D3 + f]);
}

__global__ void fc_kernel(const float* __restrict__ pool, const float* __restrict__ gsum,
                          const float* __restrict__ wfc, const float* __restrict__ bfc,
                          float* __restrict__ out)
{
    const int t = threadIdx.x;
    if (t >= N_GRAPHS * OUT_DIM) return;
    const int g = t / OUT_DIM, o = t % OUT_DIM;
    float s = 0.f;
#pragma unroll 16
    for (int f = 0; f < D3; f++) s += pool[g * D3 + f] * wfc[f * OUT_DIM + o];
    out[g * OUT_DIM + o] = s / (gsum[g] + 1e-16f) + bfc[o];
}

// ---------------- launch ----------------
extern "C" void kernel_launch(void* const* d_in, const int* in_sizes, int n_in,
                              void* d_out, int out_size)
{
    const float* x     = (const float*)d_in[0];
    const int*   ei    = (const int*)d_in[1];
    const int*   batch = (const int*)d_in[2];
    const float* W[12] = { (const float*)d_in[3],  (const float*)d_in[5],
                           (const float*)d_in[7],  (const float*)d_in[9],
                           (const float*)d_in[11], (const float*)d_in[13],
                           (const float*)d_in[15], (const float*)d_in[17],
                           (const float*)d_in[19], (const float*)d_in[21],
                           (const float*)d_in[23], (const float*)d_in[25] };
    const float* Bv[12] = { (const float*)d_in[4],  (const float*)d_in[6],
                            (const float*)d_in[8],  (const float*)d_in[10],
                            (const float*)d_in[12], (const float*)d_in[14],
                            (const float*)d_in[16], (const float*)d_in[18],
                            (const float*)d_in[20], (const float*)d_in[22],
                            (const float*)d_in[24], (const float*)d_in[26] };
    const float* w_g  = (const float*)d_in[27]; const float* b_g  = (const float*)d_in[28];
    const float* w_fc = (const float*)d_in[29]; const float* b_fc = (const float*)d_in[30];
    float* out = (float*)d_out;

    float *qb, *skipb, *hA, *gateb, *gmaxb, *gsumb, *poolb, *biasb, *extrasb, *Mfullb, *Mbiasb;
    __half *kb, *vb, *x16b, *Af16b, *WFb;
    int *degb, *ptrb, *fillb, *csrb;
    cudaGetSymbolAddress((void**)&qb,     g_q);
    cudaGetSymbolAddress((void**)&kb,     g_k);
    cudaGetSymbolAddress((void**)&vb,     g_v);
    cudaGetSymbolAddress((void**)&skipb,  g_skip);
    cudaGetSymbolAddress((void**)&hA,     g_hA);
    cudaGetSymbolAddress((void**)&extrasb,g_extras);
    cudaGetSymbolAddress((void**)&x16b,   g_x16);
    cudaGetSymbolAddress((void**)&Af16b,  g_Af16);
    cudaGetSymbolAddress((void**)&Mfullb, g_Mfull);
    cudaGetSymbolAddress((void**)&Mbiasb, g_Mbias);
    cudaGetSymbolAddress((void**)&WFb,    g_WF);
    cudaGetSymbolAddress((void**)&biasb,  g_bias);
    cudaGetSymbolAddress((void**)&degb,   g_deg);
    cudaGetSymbolAddress((void**)&ptrb,   g_ptr);
    cudaGetSymbolAddress((void**)&fillb,  g_fill);
    cudaGetSymbolAddress((void**)&csrb,   g_csr_src);
    cudaGetSymbolAddress((void**)&gateb,  g_gate);
    cudaGetSymbolAddress((void**)&gmaxb,  g_gmax);
    cudaGetSymbolAddress((void**)&gsumb,  g_gsum);
    cudaGetSymbolAddress((void**)&poolb,  g_pool);

    const int N = N_NODES, E = N_EDGES;

    // ---- pack regions (all fp16 weights) ----
    PackArgs P;
    long long wcum = 0;
    int bcum = 0;
    int ri = 0;
    auto addW = [&](const float* src, int K, int ncols, long long base, int ntot, int coff,
                    const float* bsrc, int boff) {
        P.wsrc[ri] = src; P.wcum[ri] = wcum; P.wncols[ri] = ncols;
        P.wdstBase[ri] = base; P.wntot[ri] = ntot; P.wcoff[ri] = coff;
        wcum += (long long)K * ncols;
        P.bsrc[ri] = bsrc; P.bcum[ri] = bcum; P.boff[ri] = boff;
        bcum += ncols;
        ri++;
    };
    // L1: [Mfull | v | skip]
    addW(Mfullb, F_IN, MCOLS, WF_BASE1, F_N1, 0, Mbiasb, BB1);
    addW(W[2], F_IN, HEADS * D1, WF_BASE1, F_N1, MCOLS, Bv[2], BB1 + MCOLS);
    addW(W[3], F_IN, D1, WF_BASE1, F_N1, MCOLS + HEADS * D1, Bv[3], BB1 + MCOLS + HEADS * D1);
    // L2: [q|k|v|skip]
    for (int p = 0; p < 4; p++) {
        const int ncols = (p < 3) ? HEADS * D2 : D2;
        const int coff = (p < 3) ? p * HEADS * D2 : 3 * HEADS * D2;
        addW(W[4 + p], D1, ncols, WF_BASE2, F_N2, coff, Bv[4 + p], BB2 + coff);
    }
    // L3
    for (int p = 0; p < 4; p++) {
        const int ncols = (p < 3) ? HEADS * D3 : D3;
        const int coff = (p < 3) ? p * HEADS * D3 : 3 * HEADS * D3;
        addW(W[8 + p], D2, ncols, WF_BASE3, F_N3, coff, Bv[8 + p], BB3 + coff);
    }
    P.wcum[ri] = wcum;
    P.bcum[ri] = bcum;
    for (int r2 = ri; r2 < 12; r2++) { P.wcum[r2 + 1] = wcum; P.bcum[r2 + 1] = bcum; }
    P.x = x;

    const long long packTotal = wcum + NXTOT + bcum;
    const int gy = (N + 127) / 128;

    // epilogue tables
    EpiTab T1;  // z | extras | v | skip
    T1.start[0] = 0;     T1.f[0] = qb;      T1.h[0] = nullptr; T1.stride[0] = ZCOLS;
    T1.start[1] = ZCOLS; T1.f[1] = extrasb; T1.h[1] = nullptr; T1.stride[1] = 128;
    T1.start[2] = MCOLS; T1.f[2] = nullptr; T1.h[2] = vb;      T1.stride[2] = HEADS * D1;
    T1.start[3] = MCOLS + HEADS * D1; T1.f[3] = skipb; T1.h[3] = nullptr; T1.stride[3] = D1;
    EpiTab T2;  // q | k | v | skip
    T2.start[0] = 0;              T2.f[0] = qb;      T2.h[0] = nullptr; T2.stride[0] = HEADS * D2;
    T2.start[1] = HEADS * D2;     T2.f[1] = nullptr; T2.h[1] = kb;      T2.stride[1] = HEADS * D2;
    T2.start[2] = 2 * HEADS * D2; T2.f[2] = nullptr; T2.h[2] = vb;      T2.stride[2] = HEADS * D2;
    T2.start[3] = 3 * HEADS * D2; T2.f[3] = skipb;   T2.h[3] = nullptr; T2.stride[3] = D2;
    EpiTab T3;
    T3.start[0] = 0;              T3.f[0] = qb;      T3.h[0] = nullptr; T3.stride[0] = HEADS * D3;
    T3.start[1] = HEADS * D3;     T3.f[1] = nullptr; T3.h[1] = kb;      T3.stride[1] = HEADS * D3;
    T3.start[2] = 2 * HEADS * D3; T3.f[2] = nullptr; T3.h[2] = vb;      T3.stride[2] = HEADS * D3;
    T3.start[3] = 3 * HEADS * D3; T3.f[3] = skipb;   T3.h[3] = nullptr; T3.stride[3] = D3;

    // launch order: gemm_half L1 at slot 5 (ncu capture)
    make_m<<<MCOLS, 128>>>(W[0], W[1], Bv[0], Bv[1], Mfullb, Mbiasb);                   // 1
    pack_all<<<(int)((packTotal + 255) / 256), 256>>>(P, WFb, x16b, biasb,
                                                      wcum, NXTOT, bcum);               // 2
    cudaMemsetAsync(degb, 0, N * sizeof(int));                                          // 3
    count_deg<<<(E + 255) / 256, 256>>>(ei, degb, E);                                   // 4
    gemm_half<<<dim3(F_N1 / 128, gy), 256>>>(x16b, WFb + WF_BASE1,
                                             biasb + BB1, T1, N, F_N1, F_IN);           // 5 <- profiled
    scan_deg<<<1, 1024>>>(degb, ptrb, fillb, N);                                        // 6
    fill_csr<<<(E + 255) / 256, 256>>>(ei, fillb, csrb, E);                             // 7
    attn1_kernel<<<N, 256>>>(qb, x16b, extrasb, vb, ptrb, csrb, skipb, Af16b);          // 8

    gemm_half<<<dim3(F_N2 / 128, gy), 256>>>(Af16b, WFb + WF_BASE2,
                                             biasb + BB2, T2, N, F_N2, D1);
    attn_kernel<D2, true><<<N, 256>>>(qb, kb, vb, ptrb, csrb, skipb, nullptr, Af16b);

    gemm_half<<<dim3(F_N3 / 128, gy), 256>>>(Af16b, WFb + WF_BASE3,
                                             biasb + BB3, T3, N, F_N3, D2);
    attn_kernel<D3, false><<<N, 256>>>(qb, kb, vb, ptrb, csrb, skipb, hA, nullptr);

    // ---- pooling + fc ----
    init_gmax<<<1, 64>>>(gmaxb);
    cudaMemsetAsync(gsumb, 0, N_GRAPHS * sizeof(float));
    cudaMemsetAsync(poolb, 0, N_GRAPHS * D3 * sizeof(float));
    gate_kernel<<<(N * 32 + 255) / 256, 256>>>(hA, w_g, b_g, batch, gateb, gmaxb, N);
    exp_pool<<<N, D3>>>(hA, gateb, batch, gmaxb, gsumb, poolb);
    fc_kernel<<<1, 1024>>>(poolb, gsumb, w_fc, b_fc, out);
}

// round 14
// speedup vs baseline: 2.2321x; 1.0374x over previous
#include <cuda_runtime.h>
#include <cuda_fp16.h>
#include <mma.h>
#include <math.h>
#include <stdint.h>

using namespace nvcuda;

// ---------------- problem constants ----------------
#define N_NODES 10000
#define N_EDGES 80000
#define N_GRAPHS 64
#define HEADS 8
#define F_IN 128
#define D1 512
#define D2 256
#define D3 128
#define OUT_DIM 10

// layer-1 factored logits: z(1024) + extras(128)
#define ZCOLS (HEADS * F_IN)          // 1024
#define MCOLS (ZCOLS + 128)           // 1152

// one fp16 GEMM per layer: L1 [Mfull|v|skip], L2/L3 [q|k|v|skip]
#define F_N1 (MCOLS + HEADS * D1 + D1)   // 5760
#define F_N2 (3 * HEADS * D2 + D2)       // 6400
#define F_N3 (3 * HEADS * D3 + D3)       // 3200
#define WF_BASE1 0LL
#define WF_BASE2 ((long long)F_IN * F_N1)
#define WF_BASE3 (WF_BASE2 + (long long)D1 * F_N2)
#define WF_TOTAL (WF_BASE3 + (long long)D2 * F_N3)

#define BB1 0
#define BB2 F_N1
#define BB3 (BB2 + F_N2)
#define BTOTAL (BB3 + F_N3)
#define NXTOT (N_NODES * F_IN)

// ---------------- device scratch (static, no allocs) ----------------
__device__ float g_q[(size_t)N_NODES * (HEADS * D1)];
__device__ __half g_k[(size_t)N_NODES * (HEADS * D1)];
__device__ __half g_v[(size_t)N_NODES * (HEADS * D1)];
__device__ float g_skip[(size_t)N_NODES * D1];
__device__ float g_hA[(size_t)N_NODES * D1];

__device__ float g_extras[(size_t)N_NODES * 128];
__device__ __half g_x16[(size_t)N_NODES * F_IN];
__device__ __half g_Af16[(size_t)N_NODES * D1];
__device__ float g_Mfull[F_IN * MCOLS];
__device__ float g_Mbias[MCOLS];

__device__ __half g_WF[WF_TOTAL];
__device__ float g_bias[BTOTAL];

__device__ int g_deg[N_NODES];
__device__ int g_ptr[N_NODES + 1];
__device__ int g_fill[N_NODES];
__device__ int g_csr_src[N_EDGES];

__device__ float g_gate[N_NODES];
__device__ float g_gmax[N_GRAPHS];
__device__ float g_gsum[N_GRAPHS];
__device__ float g_pool[N_GRAPHS * D3];

// ---------------- cp.async helpers ----------------
__device__ __forceinline__ void cp16(uint32_t dst, const void* src)
{
    asm volatile("cp.async.cg.shared.global [%0], [%1], 16;" :: "r"(dst), "l"(src));
}
__device__ __forceinline__ void cp_commit() { asm volatile("cp.async.commit_group;"); }
template <int Np>
__device__ __forceinline__ void cp_wait() { asm volatile("cp.async.wait_group %0;" :: "n"(Np)); }

// ---------------- layer-1 factorization precompute ----------------
__global__ void make_m(const float* __restrict__ wq, const float* __restrict__ wk,
                       const float* __restrict__ bq, const float* __restrict__ bk,
                       float* __restrict__ Mfull, float* __restrict__ Mbias)
{
    __shared__ float col[D1];
    __shared__ float red[128];
    const int j = blockIdx.x;
    const int tid = threadIdx.x;

    if (j >= 1040) {
        Mfull[tid * MCOLS + j] = 0.f;
        if (tid == 0) Mbias[j] = 0.f;
        return;
    }

    int h;
    const float* mat;
    if (j < ZCOLS)        { h = j >> 7;   mat = wq; }
    else if (j < 1032)    { h = j - 1024; mat = wq; }
    else                  { h = j - 1032; mat = wk; }
    const int base = h * D1;

    if (j < ZCOLS) {
        const int jj = j & 127;
        for (int c = tid; c < D1; c += 128) col[c] = wk[(size_t)jj * (HEADS * D1) + base + c];
    } else if (j < 1032) {
        for (int c = tid; c < D1; c += 128) col[c] = bk[base + c];
    } else {
        for (int c = tid; c < D1; c += 128) col[c] = bq[base + c];
    }
    __syncthreads();

    const float4* row4 = reinterpret_cast<const float4*>(mat + (size_t)tid * (HEADS * D1) + base);
    float acc = 0.f;
#pragma unroll 4
    for (int c = 0; c < D1 / 4; c++) {
        const float4 r = row4[c];
        acc += r.x * col[c * 4 + 0] + r.y * col[c * 4 + 1]
             + r.z * col[c * 4 + 2] + r.w * col[c * 4 + 3];
    }
    Mfull[tid * MCOLS + j] = acc;

    if (j >= ZCOLS && j < 1032) {
        float p = 0.f;
        for (int c = tid; c < D1; c += 128) p += bq[base + c] * bk[base + c];
        red[tid] = p;
        __syncthreads();
        if (tid < 64) red[tid] += red[tid + 64];
        __syncthreads();
        if (tid < 32) {
            float t = red[tid] + red[tid + 32];
#pragma unroll
            for (int o = 16; o > 0; o >>= 1) t += __shfl_down_sync(0xffffffffu, t, o);
            if (tid == 0) Mbias[j] = t;
        }
    } else {
        if (tid == 0) Mbias[j] = 0.f;
    }
}

// ---------------- one-shot packing (all fp16 weights) ----------------
struct PackArgs {
    const float* wsrc[12];
    long long wcum[13];
    int wncols[12];
    long long wdstBase[12];
    int wntot[12];
    int wcoff[12];
    const float* bsrc[12];
    int bcum[13];
    int boff[12];
    const float* x;
};

__global__ void pack_all(PackArgs P, __half* __restrict__ WF, __half* __restrict__ x16,
                         float* __restrict__ bias, long long wtotal, long long xtotal, int btotal)
{
    long long i = (long long)blockIdx.x * blockDim.x + threadIdx.x;
    if (i < wtotal) {
        int r = 0;
        while (i >= P.wcum[r + 1]) r++;
        const long long li = i - P.wcum[r];
        const int nc = P.wncols[r];
        const int k = (int)(li / nc), c = (int)(li % nc);
        const long long di = P.wdstBase[r] + (long long)k * P.wntot[r] + P.wcoff[r] + c;
        WF[di] = __float2half(P.wsrc[r][li]);
        return;
    }
    i -= wtotal;
    if (i < xtotal) {
        x16[i] = __float2half(P.x[i]);
        return;
    }
    int j = (int)(i - xtotal);
    if (j < btotal) {
        int r = 0;
        while (j >= P.bcum[r + 1]) r++;
        bias[P.boff[r] + (j - P.bcum[r])] = P.bsrc[r][j - P.bcum[r]];
    }
}

// ---------------- epilogue routing table ----------------
struct EpiTab {
    float* f[4];
    __half* h[4];
    int stride[4];
    int start[4];
};

// ---------------- fp16 single-pass GEMM, BK=32 ----------------
#define LDAH 40
#define LDBH 136
#define ASZH (128 * LDAH)
#define BSZH (32 * LDBH)
#define STAGE_H (ASZH + BSZH)

__global__ __launch_bounds__(256, 2)
void gemm_half(const __half* __restrict__ A, const __half* __restrict__ B,
               const float* __restrict__ bias, EpiTab T,
               int M, int N, int K)
{
    __shared__ __align__(16) __half sm[2 * STAGE_H];

    const int tid = threadIdx.x;
    const int warpId = tid >> 5;
    const int lane = tid & 31;
    const int wm = warpId >> 2;
    const int wn = warpId & 3;
    const int bm = blockIdx.y * 128;
    const int bn = blockIdx.x * 128;

    const int ar = tid >> 1, ac = (tid & 1) * 16;
    const int br = tid >> 3, bc = (tid & 7) * 16;

    wmma::fragment<wmma::accumulator, 16, 16, 16, float> acc[4][2];
#pragma unroll
    for (int i = 0; i < 4; i++)
#pragma unroll
        for (int j = 0; j < 2; j++) wmma::fill_fragment(acc[i][j], 0.f);

    auto issue = [&](int kb, int s) {
        __half* base = sm + s * STAGE_H;
        __half* pA = base + ar * LDAH + ac;
        const int gr = bm + ar;
        if (gr < M) {
            const size_t off = (size_t)gr * K + kb + ac;
            cp16((uint32_t)__cvta_generic_to_shared(pA),     A + off);
            cp16((uint32_t)__cvta_generic_to_shared(pA + 8), A + off + 8);
        } else {
            uint4 z = make_uint4(0, 0, 0, 0);
            *reinterpret_cast<uint4*>(pA) = z;
            *reinterpret_cast<uint4*>(pA + 8) = z;
        }
        __half* pB = base + ASZH + br * LDBH + bc;
        const size_t boff = (size_t)(kb + br) * N + bn + bc;
        cp16((uint32_t)__cvta_generic_to_shared(pB),     B + boff);
        cp16((uint32_t)__cvta_generic_to_shared(pB + 8), B + boff + 8);
        cp_commit();
    };

    const int nk = K >> 5;
    issue(0, 0);

    for (int it = 0; it < nk; ++it) {
        const int s = it & 1;
        if (it + 1 < nk) { issue((it + 1) << 5, s ^ 1); cp_wait<1>(); }
        else             { cp_wait<0>(); }
        __syncthreads();

        const __half* As = sm + s * STAGE_H;
        const __half* Bs = As + ASZH;

#pragma unroll
        for (int kk = 0; kk < 2; kk++) {
            wmma::fragment<wmma::matrix_a, 16, 16, 16, __half, wmma::row_major> af[4];
            wmma::fragment<wmma::matrix_b, 16, 16, 16, __half, wmma::row_major> bf[2];
#pragma unroll
            for (int i = 0; i < 4; i++)
                wmma::load_matrix_sync(af[i], As + (wm * 64 + i * 16) * LDAH + kk * 16, LDAH);
#pragma unroll
            for (int j = 0; j < 2; j++)
                wmma::load_matrix_sync(bf[j], Bs + (kk * 16) * LDBH + wn * 32 + j * 16, LDBH);
#pragma unroll
            for (int i = 0; i < 4; i++)
#pragma unroll
                for (int j = 0; j < 2; j++)
                    wmma::mma_sync(acc[i][j], af[i], bf[j], acc[i][j]);
        }
        __syncthreads();
    }

    const int r = (bn >= T.start[3]) ? 3 : (bn >= T.start[2]) ? 2 : (bn >= T.start[1]) ? 1 : 0;
    float* fdst = T.f[r];
    __half* hdst = T.h[r];
    const int lcb = bn - T.start[r];
    const int stride = T.stride[r];

    float* wb = reinterpret_cast<float*>(sm) + warpId * 256;
#pragma unroll
    for (int i = 0; i < 4; i++)
#pragma unroll
        for (int j = 0; j < 2; j++) {
            wmma::store_matrix_sync(wb, acc[i][j], 16, wmma::mem_row_major);
            __syncwarp();
            const int r0 = bm + wm * 64 + i * 16;
            const int c0 = bn + wn * 32 + j * 16;
#pragma unroll
            for (int e = lane; e < 64; e += 32) {
                const int rr = e >> 2, c4 = (e & 3) * 4;
                if (r0 + rr >= M) continue;
                float4 vv = *reinterpret_cast<float4*>(wb + rr * 16 + c4);
                const int col = c0 + c4;
                vv.x += bias[col + 0];
                vv.y += bias[col + 1];
                vv.z += bias[col + 2];
                vv.w += bias[col + 3];
                const size_t o = (size_t)(r0 + rr) * stride + (lcb + (col - bn));
                if (fdst) {
                    *reinterpret_cast<float4*>(fdst + o) = vv;
                } else {
                    uint2 p;
                    *reinterpret_cast<__half2*>(&p.x) = __floats2half2_rn(vv.x, vv.y);
                    *reinterpret_cast<__half2*>(&p.y) = __floats2half2_rn(vv.z, vv.w);
                    *reinterpret_cast<uint2*>(hdst + o) = p;
                }
            }
            __syncwarp();
        }
}

// ---------------- CSR build ----------------
__global__ void count_deg(const int* __restrict__ ei, int* __restrict__ deg, int E)
{
    int e = blockIdx.x * blockDim.x + threadIdx.x;
    if (e < E) atomicAdd(&deg[ei[E + e]], 1);
}

__global__ void scan_deg(const int* __restrict__ deg, int* __restrict__ ptr,
                         int* __restrict__ fill, int n)
{
    constexpr int PER = 10;
    const int tid = threadIdx.x;
    const int lane = tid & 31, wid = tid >> 5;
    const int base = tid * PER;

    int vals[PER];
    int s = 0;
#pragma unroll
    for (int i = 0; i < PER; i++) {
        const int idx = base + i;
        vals[i] = (idx < n) ? deg[idx] : 0;
        s += vals[i];
    }
    int sc = s;
#pragma unroll
    for (int o = 1; o < 32; o <<= 1) {
        int t = __shfl_up_sync(0xffffffffu, sc, o);
        if (lane >= o) sc += t;
    }
    __shared__ int wsum[32];
    if (lane == 31) wsum[wid] = sc;
    __syncthreads();
    if (wid == 0) {
        int w = wsum[lane];
#pragma unroll
        for (int o = 1; o < 32; o <<= 1) {
            int t = __shfl_up_sync(0xffffffffu, w, o);
            if (lane >= o) w += t;
        }
        wsum[lane] = w;
    }
    __syncthreads();
    int run = (sc - s) + (wid > 0 ? wsum[wid - 1] : 0);
#pragma unroll
    for (int i = 0; i < PER; i++) {
        const int idx = base + i;
        if (idx < n) { ptr[idx] = run; fill[idx] = run; }
        run += vals[i];
    }
    if (tid == 1023) ptr[n] = run;
}

__global__ void fill_csr(const int* __restrict__ ei, int* __restrict__ fill,
                         int* __restrict__ csr_src, int E)
{
    int e = blockIdx.x * blockDim.x + threadIdx.x;
    if (e < E) {
        const int d = ei[E + e];
        const int pos = atomicAdd(&fill[d], 1);
        csr_src[pos] = ei[e];
    }
}

// ---------------- layer-1 attention (factored logits, unroll-2 softmax) ----------------
struct Edge1 { uint2 x; uint2 v[4]; float beta; };

__global__ void attn1_kernel(const float* __restrict__ z, const __half* __restrict__ x16,
                             const float* __restrict__ ex, const __half* __restrict__ v,
                             const int* __restrict__ ptr, const int* __restrict__ csr_src,
                             const float* __restrict__ skip,
                             __half* __restrict__ outF16)
{
    constexpr int C = D1;
    constexpr int F4 = C / 128;
    __shared__ float red[HEADS * C];

    const int dst  = blockIdx.x;
    const int warp = threadIdx.x >> 5;
    const int lane = threadIdx.x & 31;
    const float scale = rsqrtf((float)C);

    const int beg = ptr[dst], end = ptr[dst + 1];

    const float4 zr = reinterpret_cast<const float4*>(z + (size_t)dst * ZCOLS + warp * F_IN)[lane];
    const float alpha = ex[(size_t)dst * 128 + warp];

    float4 acc[F4];
#pragma unroll
    for (int i = 0; i < F4; i++) acc[i] = make_float4(0.f, 0.f, 0.f, 0.f);
    float m = -INFINITY, s = 0.f;

    auto load1 = [&](Edge1& E, int e) {
        const int src = csr_src[e];
        E.x = reinterpret_cast<const uint2*>(x16 + (size_t)src * F_IN)[lane];
        const uint2* vrow = reinterpret_cast<const uint2*>(v + (size_t)src * (HEADS * C) + warp * C);
#pragma unroll
        for (int i = 0; i < F4; i++) E.v[i] = vrow[lane + 32 * i];
        E.beta = ex[(size_t)src * 128 + 8 + warp];
    };
    auto dotx = [&](const uint2& xx) {
        const float2 x0 = __half22float2(*reinterpret_cast<const __half2*>(&xx.x));
        const float2 x1 = __half22float2(*reinterpret_cast<const __half2*>(&xx.y));
        return zr.x * x0.x + zr.y * x0.y + zr.z * x1.x + zr.w * x1.y;
    };

    Edge1 c0, c1, n0, n1;
    if (beg < end) {
        load1(c0, beg);
        load1(c1, (beg + 1 < end) ? beg + 1 : end - 1);
    }

    for (int j = beg; j < end; j += 2) {
        if (j + 2 < end) {
            load1(n0, j + 2);
            load1(n1, (j + 3 < end) ? j + 3 : end - 1);
        }
        float d1 = dotx(c0.x);
        float d2 = dotx(c1.x);
#pragma unroll
        for (int o = 16; o > 0; o >>= 1) {
            d1 += __shfl_xor_sync(0xffffffffu, d1, o);
            d2 += __shfl_xor_sync(0xffffffffu, d2, o);
        }
        const float a1 = (d1 + alpha + c0.beta) * scale;
        const float a2 = (j + 1 < end) ? (d2 + alpha + c1.beta) * scale : -INFINITY;
        const float mn = fmaxf(m, fmaxf(a1, a2));
        const float corr = expf(m - mn);
        const float w1 = expf(a1 - mn);
        const float w2 = expf(a2 - mn);
        s = s * corr + w1 + w2;
        m = mn;
#pragma unroll
        for (int i = 0; i < F4; i++) {
            const float2 u0 = __half22float2(*reinterpret_cast<const __half2*>(&c0.v[i].x));
            const float2 u1 = __half22float2(*reinterpret_cast<const __half2*>(&c0.v[i].y));
            const float2 w0 = __half22float2(*reinterpret_cast<const __half2*>(&c1.v[i].x));
            const float2 w1v = __half22float2(*reinterpret_cast<const __half2*>(&c1.v[i].y));
            acc[i].x = acc[i].x * corr + w1 * u0.x + w2 * w0.x;
            acc[i].y = acc[i].y * corr + w1 * u0.y + w2 * w0.y;
            acc[i].z = acc[i].z * corr + w1 * u1.x + w2 * w1v.x;
            acc[i].w = acc[i].w * corr + w1 * u1.y + w2 * w1v.y;
        }
        c0 = n0;
        c1 = n1;
    }

    const float inv = (end > beg) ? (1.f / (s + 1e-16f)) : 0.f;
#pragma unroll
    for (int i = 0; i < F4; i++) {
        float4 o = make_float4(acc[i].x * inv, acc[i].y * inv, acc[i].z * inv, acc[i].w * inv);
        *reinterpret_cast<float4*>(&red[warp * C + i * 128 + lane * 4]) = o;
    }
    __syncthreads();

    for (int f = threadIdx.x; f < C; f += blockDim.x) {
        float t = 0.f;
#pragma unroll
        for (int h = 0; h < HEADS; h++) t += red[h * C + f];
        t = t * (1.f / HEADS) + skip[(size_t)dst * C + f];
        t = (t > 0.f) ? t : expm1f(t);
        outF16[(size_t)dst * C + f] = __float2half(t);
    }
}

// ---------------- layers 2/3 attention (unroll-2; optional fused gate) ----------------
template <int C, bool F16OUT>
__global__ void attn_kernel(const float* __restrict__ q, const __half* __restrict__ k,
                            const __half* __restrict__ v, const int* __restrict__ ptr,
                            const int* __restrict__ csr_src, const float* __restrict__ skip,
                            float* __restrict__ out, __half* __restrict__ outF16,
                            const float* __restrict__ wg, const float* __restrict__ bg,
                            const int* __restrict__ batch, float* __restrict__ gate,
                            float* __restrict__ gmax)
{
    constexpr int H = HEADS;
    constexpr int F4 = C / 128;
    __shared__ float red[H * C];

    const int dst  = blockIdx.x;
    const int warp = threadIdx.x >> 5;
    const int lane = threadIdx.x & 31;
    const float scale = rsqrtf((float)C);
    const size_t HC = (size_t)H * C;

    const int beg = ptr[dst], end = ptr[dst + 1];

    const float4* qrow = reinterpret_cast<const float4*>(q + (size_t)dst * HC + warp * C);
    float4 qr[F4], acc[F4];
#pragma unroll
    for (int i = 0; i < F4; i++) {
        qr[i] = qrow[lane + 32 * i];
        acc[i] = make_float4(0.f, 0.f, 0.f, 0.f);
    }
    float m = -INFINITY, s = 0.f;

    struct EdgeC { uint2 k[F4]; uint2 v[F4]; };
    auto loadE = [&](EdgeC& E, int e) {
        const int src = csr_src[e];
        const uint2* krow = reinterpret_cast<const uint2*>(k + (size_t)src * HC + warp * C);
        const uint2* vrow = reinterpret_cast<const uint2*>(v + (size_t)src * HC + warp * C);
#pragma unroll
        for (int i = 0; i < F4; i++) { E.k[i] = krow[lane + 32 * i]; E.v[i] = vrow[lane + 32 * i]; }
    };
    auto dotk = [&](const EdgeC& E) {
        float d = 0.f;
#pragma unroll
        for (int i = 0; i < F4; i++) {
            const float2 k0 = __half22float2(*reinterpret_cast<const __half2*>(&E.k[i].x));
            const float2 k1 = __half22float2(*reinterpret_cast<const __half2*>(&E.k[i].y));
            d += qr[i].x * k0.x + qr[i].y * k0.y + qr[i].z * k1.x + qr[i].w * k1.y;
        }
        return d;
    };

    EdgeC c0, c1, n0, n1;
    if (beg < end) {
        loadE(c0, beg);
        loadE(c1, (beg + 1 < end) ? beg + 1 : end - 1);
    }

    for (int j = beg; j < end; j += 2) {
        if (j + 2 < end) {
            loadE(n0, j + 2);
            loadE(n1, (j + 3 < end) ? j + 3 : end - 1);
        }
        float d1 = dotk(c0);
        float d2 = dotk(c1);
#pragma unroll
        for (int o = 16; o > 0; o >>= 1) {
            d1 += __shfl_xor_sync(0xffffffffu, d1, o);
            d2 += __shfl_xor_sync(0xffffffffu, d2, o);
        }
        const float a1 = d1 * scale;
        const float a2 = (j + 1 < end) ? d2 * scale : -INFINITY;
        const float mn = fmaxf(m, fmaxf(a1, a2));
        const float corr = expf(m - mn);
        const float w1 = expf(a1 - mn);
        const float w2 = expf(a2 - mn);
        s = s * corr + w1 + w2;
        m = mn;
#pragma unroll
        for (int i = 0; i < F4; i++) {
            const float2 u0 = __half22float2(*reinterpret_cast<const __half2*>(&c0.v[i].x));
            const float2 u1 = __half22float2(*reinterpret_cast<const __half2*>(&c0.v[i].y));
            const float2 w0 = __half22float2(*reinterpret_cast<const __half2*>(&c1.v[i].x));
            const float2 w1v = __half22float2(*reinterpret_cast<const __half2*>(&c1.v[i].y));
            acc[i].x = acc[i].x * corr + w1 * u0.x + w2 * w0.x;
            acc[i].y = acc[i].y * corr + w1 * u0.y + w2 * w0.y;
            acc[i].z = acc[i].z * corr + w1 * u1.x + w2 * w1v.x;
            acc[i].w = acc[i].w * corr + w1 * u1.y + w2 * w1v.y;
        }
        c0 = n0;
        c1 = n1;
    }

    const float inv = (end > beg) ? (1.f / (s + 1e-16f)) : 0.f;
#pragma unroll
    for (int i = 0; i < F4; i++) {
        float4 o = make_float4(acc[i].x * inv, acc[i].y * inv, acc[i].z * inv, acc[i].w * inv);
        *reinterpret_cast<float4*>(&red[warp * C + i * 128 + lane * 4]) = o;
    }
    __syncthreads();

    float part = 0.f;
    for (int f = threadIdx.x; f < C; f += blockDim.x) {
        float t = 0.f;
#pragma unroll
        for (int h = 0; h < H; h++) t += red[h * C + f];
        t = t * (1.f / H) + skip[(size_t)dst * C + f];
        t = (t > 0.f) ? t : expm1f(t);
        const size_t idx = (size_t)dst * C + f;
        if constexpr (F16OUT) {
            outF16[idx] = __float2half(t);
        } else {
            out[idx] = t;
            part += t * wg[f];
        }
    }

    if constexpr (!F16OUT) {
        // fused gate dot + segment max
        __syncthreads();
        red[threadIdx.x] = part;
        __syncthreads();
#pragma unroll
        for (int off = 128; off > 0; off >>= 1) {
            if (threadIdx.x < off) red[threadIdx.x] += red[threadIdx.x + off];
            __syncthreads();
        }
        if (threadIdx.x == 0) {
            const float d = red[0] + bg[0];
            gate[dst] = d;
            float* addr = &gmax[batch[dst]];
            if (d >= 0.f) atomicMax((int*)addr, __float_as_int(d));
            else          atomicMin((unsigned int*)addr, __float_as_uint(d));
        }
    }
}

// ---------------- global attention pooling ----------------
__global__ void init_gmax(float* gmax)
{
    if (threadIdx.x < N_GRAPHS) gmax[threadIdx.x] = -INFINITY;
}

__global__ void exp_pool(const float* __restrict__ h, const float* __restrict__ gate,
                         const int* __restrict__ batch, const float* __restrict__ gmax,
                         float* __restrict__ gsum, float* __restrict__ pool)
{
    const int node = blockIdx.x;
    const int f = threadIdx.x;
    const int b = batch[node];
    const float e = expf(gate[node] - gmax[b]);
    if (f == 0) atomicAdd(&gsum[b], e);
    atomicAdd(&pool[b * D3 + f], e * h[(size_t)node * D3 + f]);
}

__global__ void fc_kernel(const float* __restrict__ pool, const float* __restrict__ gsum,
                          const float* __restrict__ wfc, const float* __restrict__ bfc,
                          float* __restrict__ out)
{
    const int t = threadIdx.x;
    if (t >= N_GRAPHS * OUT_DIM) return;
    const int g = t / OUT_DIM, o = t % OUT_DIM;
    float s = 0.f;
#pragma unroll 16
    for (int f = 0; f < D3; f++) s += pool[g * D3 + f] * wfc[f * OUT_DIM + o];
    out[g * OUT_DIM + o] = s / (gsum[g] + 1e-16f) + bfc[o];
}

// ---------------- launch ----------------
extern "C" void kernel_launch(void* const* d_in, const int* in_sizes, int n_in,
                              void* d_out, int out_size)
{
    const float* x     = (const float*)d_in[0];
    const int*   ei    = (const int*)d_in[1];
    const int*   batch = (const int*)d_in[2];
    const float* W[12] = { (const float*)d_in[3],  (const float*)d_in[5],
                           (const float*)d_in[7],  (const float*)d_in[9],
                           (const float*)d_in[11], (const float*)d_in[13],
                           (const float*)d_in[15], (const float*)d_in[17],
                           (const float*)d_in[19], (const float*)d_in[21],
                           (const float*)d_in[23], (const float*)d_in[25] };
    const float* Bv[12] = { (const float*)d_in[4],  (const float*)d_in[6],
                            (const float*)d_in[8],  (const float*)d_in[10],
                            (const float*)d_in[12], (const float*)d_in[14],
                            (const float*)d_in[16], (const float*)d_in[18],
                            (const float*)d_in[20], (const float*)d_in[22],
                            (const float*)d_in[24], (const float*)d_in[26] };
    const float* w_g  = (const float*)d_in[27]; const float* b_g  = (const float*)d_in[28];
    const float* w_fc = (const float*)d_in[29]; const float* b_fc = (const float*)d_in[30];
    float* out = (float*)d_out;

    float *qb, *skipb, *hA, *gateb, *gmaxb, *gsumb, *poolb, *biasb, *extrasb, *Mfullb, *Mbiasb;
    __half *kb, *vb, *x16b, *Af16b, *WFb;
    int *degb, *ptrb, *fillb, *csrb;
    cudaGetSymbolAddress((void**)&qb,     g_q);
    cudaGetSymbolAddress((void**)&kb,     g_k);
    cudaGetSymbolAddress((void**)&vb,     g_v);
    cudaGetSymbolAddress((void**)&skipb,  g_skip);
    cudaGetSymbolAddress((void**)&hA,     g_hA);
    cudaGetSymbolAddress((void**)&extrasb,g_extras);
    cudaGetSymbolAddress((void**)&x16b,   g_x16);
    cudaGetSymbolAddress((void**)&Af16b,  g_Af16);
    cudaGetSymbolAddress((void**)&Mfullb, g_Mfull);
    cudaGetSymbolAddress((void**)&Mbiasb, g_Mbias);
    cudaGetSymbolAddress((void**)&WFb,    g_WF);
    cudaGetSymbolAddress((void**)&biasb,  g_bias);
    cudaGetSymbolAddress((void**)&degb,   g_deg);
    cudaGetSymbolAddress((void**)&ptrb,   g_ptr);
    cudaGetSymbolAddress((void**)&fillb,  g_fill);
    cudaGetSymbolAddress((void**)&csrb,   g_csr_src);
    cudaGetSymbolAddress((void**)&gateb,  g_gate);
    cudaGetSymbolAddress((void**)&gmaxb,  g_gmax);
    cudaGetSymbolAddress((void**)&gsumb,  g_gsum);
    cudaGetSymbolAddress((void**)&poolb,  g_pool);

    const int N = N_NODES, E = N_EDGES;

    // ---- pack regions (all fp16 weights) ----
    PackArgs P;
    long long wcum = 0;
    int bcum = 0;
    int ri = 0;
    auto addW = [&](const float* src, int K, int ncols, long long base, int ntot, int coff,
                    const float* bsrc, int boff) {
        P.wsrc[ri] = src; P.wcum[ri] = wcum; P.wncols[ri] = ncols;
        P.wdstBase[ri] = base; P.wntot[ri] = ntot; P.wcoff[ri] = coff;
        wcum += (long long)K * ncols;
        P.bsrc[ri] = bsrc; P.bcum[ri] = bcum; P.boff[ri] = boff;
        bcum += ncols;
        ri++;
    };
    addW(Mfullb, F_IN, MCOLS, WF_BASE1, F_N1, 0, Mbiasb, BB1);
    addW(W[2], F_IN, HEADS * D1, WF_BASE1, F_N1, MCOLS, Bv[2], BB1 + MCOLS);
    addW(W[3], F_IN, D1, WF_BASE1, F_N1, MCOLS + HEADS * D1, Bv[3], BB1 + MCOLS + HEADS * D1);
    for (int p = 0; p < 4; p++) {
        const int ncols = (p < 3) ? HEADS * D2 : D2;
        const int coff = (p < 3) ? p * HEADS * D2 : 3 * HEADS * D2;
        addW(W[4 + p], D1, ncols, WF_BASE2, F_N2, coff, Bv[4 + p], BB2 + coff);
    }
    for (int p = 0; p < 4; p++) {
        const int ncols = (p < 3) ? HEADS * D3 : D3;
        const int coff = (p < 3) ? p * HEADS * D3 : 3 * HEADS * D3;
        addW(W[8 + p], D2, ncols, WF_BASE3, F_N3, coff, Bv[8 + p], BB3 + coff);
    }
    P.wcum[ri] = wcum;
    P.bcum[ri] = bcum;
    for (int r2 = ri; r2 < 12; r2++) { P.wcum[r2 + 1] = wcum; P.bcum[r2 + 1] = bcum; }
    P.x = x;

    const long long packTotal = wcum + NXTOT + bcum;
    const int gy = (N + 127) / 128;

    // epilogue tables
    EpiTab T1;  // z | extras | v | skip
    T1.start[0] = 0;     T1.f[0] = qb;      T1.h[0] = nullptr; T1.stride[0] = ZCOLS;
    T1.start[1] = ZCOLS; T1.f[1] = extrasb; T1.h[1] = nullptr; T1.stride[1] = 128;
    T1.start[2] = MCOLS; T1.f[2] = nullptr; T1.h[2] = vb;      T1.stride[2] = HEADS * D1;
    T1.start[3] = MCOLS + HEADS * D1; T1.f[3] = skipb; T1.h[3] = nullptr; T1.stride[3] = D1;
    EpiTab T2;  // q | k | v | skip
    T2.start[0] = 0;              T2.f[0] = qb;      T2.h[0] = nullptr; T2.stride[0] = HEADS * D2;
    T2.start[1] = HEADS * D2;     T2.f[1] = nullptr; T2.h[1] = kb;      T2.stride[1] = HEADS * D2;
    T2.start[2] = 2 * HEADS * D2; T2.f[2] = nullptr; T2.h[2] = vb;      T2.stride[2] = HEADS * D2;
    T2.start[3] = 3 * HEADS * D2; T2.f[3] = skipb;   T2.h[3] = nullptr; T2.stride[3] = D2;
    EpiTab T3;
    T3.start[0] = 0;              T3.f[0] = qb;      T3.h[0] = nullptr; T3.stride[0] = HEADS * D3;
    T3.start[1] = HEADS * D3;     T3.f[1] = nullptr; T3.h[1] = kb;      T3.stride[1] = HEADS * D3;
    T3.start[2] = 2 * HEADS * D3; T3.f[2] = nullptr; T3.h[2] = vb;      T3.stride[2] = HEADS * D3;
    T3.start[3] = 3 * HEADS * D3; T3.f[3] = skipb;   T3.h[3] = nullptr; T3.stride[3] = D3;

    // launch order: gemm_half L1 at slot 5 (ncu capture)
    make_m<<<MCOLS, 128>>>(W[0], W[1], Bv[0], Bv[1], Mfullb, Mbiasb);                   // 1
    pack_all<<<(int)((packTotal + 255) / 256), 256>>>(P, WFb, x16b, biasb,
                                                      wcum, NXTOT, bcum);               // 2
    cudaMemsetAsync(degb, 0, N * sizeof(int));                                          // 3
    count_deg<<<(E + 255) / 256, 256>>>(ei, degb, E);                                   // 4
    gemm_half<<<dim3(F_N1 / 128, gy), 256>>>(x16b, WFb + WF_BASE1,
                                             biasb + BB1, T1, N, F_N1, F_IN);           // 5 <- profiled
    scan_deg<<<1, 1024>>>(degb, ptrb, fillb, N);                                        // 6
    fill_csr<<<(E + 255) / 256, 256>>>(ei, fillb, csrb, E);                             // 7
    attn1_kernel<<<N, 256>>>(qb, x16b, extrasb, vb, ptrb, csrb, skipb, Af16b);          // 8

    gemm_half<<<dim3(F_N2 / 128, gy), 256>>>(Af16b, WFb + WF_BASE2,
                                             biasb + BB2, T2, N, F_N2, D1);
    attn_kernel<D2, true><<<N, 256>>>(qb, kb, vb, ptrb, csrb, skipb, nullptr, Af16b,
                                      nullptr, nullptr, nullptr, nullptr, nullptr);

    gemm_half<<<dim3(F_N3 / 128, gy), 256>>>(Af16b, WFb + WF_BASE3,
                                             biasb + BB3, T3, N, F_N3, D2);
    init_gmax<<<1, 64>>>(gmaxb);
    cudaMemsetAsync(gsumb, 0, N_GRAPHS * sizeof(float));
    cudaMemsetAsync(poolb, 0, N_GRAPHS * D3 * sizeof(float));
    attn_kernel<D3, false><<<N, 256>>>(qb, kb, vb, ptrb, csrb, skipb, hA, nullptr,
                                       w_g, b_g, batch, gateb, gmaxb);

    // ---- pooling + fc ----
    exp_pool<<<N, D3>>>(hA, gateb, batch, gmaxb, gsumb, poolb);
    fc_kernel<<<1, 1024>>>(poolb, gsumb, w_fc, b_fc, out);
}

// round 15
// speedup vs baseline: 2.3388x; 1.0478x over previous
#include <cuda_runtime.h>
#include <cuda_fp16.h>
#include <mma.h>
#include <math.h>
#include <stdint.h>

using namespace nvcuda;

// ---------------- problem constants ----------------
#define N_NODES 10000
#define N_EDGES 80000
#define N_GRAPHS 64
#define HEADS 8
#define F_IN 128
#define D1 512
#define D2 256
#define D3 128
#define OUT_DIM 10

#define ZCOLS (HEADS * F_IN)          // 1024
#define MCOLS (ZCOLS + 128)           // 1152

#define F_N1 (MCOLS + HEADS * D1 + D1)   // 5760
#define F_N2 (3 * HEADS * D2 + D2)       // 6400
#define F_N3 (3 * HEADS * D3 + D3)       // 3200
#define WF_BASE1 0LL
#define WF_BASE2 ((long long)F_IN * F_N1)
#define WF_BASE3 (WF_BASE2 + (long long)D1 * F_N2)
#define WF_TOTAL (WF_BASE3 + (long long)D2 * F_N3)

#define BB1 0
#define BB2 F_N1
#define BB3 (BB2 + F_N2)
#define BTOTAL (BB3 + F_N3)
#define NXTOT (N_NODES * F_IN)
#define QKTOT (2 * F_IN * HEADS * D1)    // 1048576

// ---------------- device scratch (static, no allocs) ----------------
__device__ float g_q[(size_t)N_NODES * (HEADS * D1)];
__device__ __half g_k[(size_t)N_NODES * (HEADS * D1)];
__device__ __half g_v[(size_t)N_NODES * (HEADS * D1)];
__device__ float g_skip[(size_t)N_NODES * D1];
__device__ float g_hA[(size_t)N_NODES * D1];

__device__ float g_extras[(size_t)N_NODES * 128];
__device__ __half g_x16[(size_t)N_NODES * F_IN];
__device__ __half g_Af16[(size_t)N_NODES * D1];

__device__ __half g_A16[8 * 128 * 512];    // Wq fp16 per-head [h][row][c]
__device__ __half g_BT16[8 * 512 * 128];   // Wk^T fp16 per-head [h][c][col]

__device__ __half g_WF[WF_TOTAL];
__device__ float g_bias[BTOTAL];

__device__ int g_deg[N_NODES];
__device__ int g_ptr[N_NODES + 1];
__device__ int g_fill[N_NODES];
__device__ int g_csr_src[N_EDGES];

__device__ float g_gate[N_NODES];
__device__ float g_gmax[N_GRAPHS];
__device__ float g_gsum[N_GRAPHS];
__device__ float g_pool[N_GRAPHS * D3];

// ---------------- cp.async helpers ----------------
__device__ __forceinline__ void cp16(uint32_t dst, const void* src)
{
    asm volatile("cp.async.cg.shared.global [%0], [%1], 16;" :: "r"(dst), "l"(src));
}
__device__ __forceinline__ void cp_commit() { asm volatile("cp.async.commit_group;"); }
template <int Np>
__device__ __forceinline__ void cp_wait() { asm volatile("cp.async.wait_group %0;" :: "n"(Np)); }

// ---------------- one-shot packing (weights, x, bias, Wq/Wk fp16, deg count) ----------------
struct PackArgs {
    const float* wsrc[12];
    long long wcum[13];
    int wncols[12];
    long long wdstBase[12];
    int wntot[12];
    int wcoff[12];
    const float* bsrc[12];
    int bcum[13];
    int boff[12];
    const float* x;
    const float* wq;
    const float* wk;
    const int* ei;
};

__global__ void pack_all(PackArgs P, __half* __restrict__ WF, __half* __restrict__ x16,
                         float* __restrict__ bias, __half* __restrict__ A16,
                         __half* __restrict__ BT16, int* __restrict__ deg,
                         long long wtotal, long long xtotal, int btotal)
{
    long long i = (long long)blockIdx.x * blockDim.x + threadIdx.x;
    if (i < wtotal) {
        int r = 0;
        while (i >= P.wcum[r + 1]) r++;
        const long long li = i - P.wcum[r];
        const int nc = P.wncols[r];
        const int k = (int)(li / nc), c = (int)(li % nc);
        const long long di = P.wdstBase[r] + (long long)k * P.wntot[r] + P.wcoff[r] + c;
        WF[di] = __float2half(P.wsrc[r][li]);
        return;
    }
    i -= wtotal;
    if (i < xtotal) {
        x16[i] = __float2half(P.x[i]);
        return;
    }
    i -= xtotal;
    if (i < btotal) {
        int j = (int)i;
        int r = 0;
        while (j >= P.bcum[r + 1]) r++;
        bias[P.boff[r] + (j - P.bcum[r])] = P.bsrc[r][j - P.bcum[r]];
        return;
    }
    i -= btotal;
    if (i < QKTOT) {
        if (i < QKTOT / 2) {
            const int idx = (int)i;
            const int k = idx >> 12, c = idx & 4095;   // row of Wq, col
            const int h = c >> 9, cc = c & 511;
            A16[(size_t)h * 65536 + k * 512 + cc] = __float2half(P.wq[idx]);
        } else {
            const int idx = (int)(i - QKTOT / 2);
            const int j = idx >> 12, c = idx & 4095;   // row of Wk, col
            const int h = c >> 9, cc = c & 511;
            BT16[(size_t)h * 65536 + cc * 128 + j] = __float2half(P.wk[idx]);
        }
        return;
    }
    i -= QKTOT;
    if (i < N_EDGES) atomicAdd(&deg[P.ei[N_EDGES + (int)i]], 1);
}

// ---------------- batched per-head MM: M_h = Wq_h @ Wk_h^T (fp16 tensor) ----------------
#define LDAH 40
#define LDBH 136
#define ASZH (128 * LDAH)
#define BSZH (32 * LDBH)
#define STAGE_H (ASZH + BSZH)

__global__ __launch_bounds__(256, 2)
void make_m_mm(const __half* __restrict__ A16, const __half* __restrict__ BT16,
               __half* __restrict__ WF)
{
    __shared__ __align__(16) __half sm[2 * STAGE_H];

    const int tid = threadIdx.x;
    const int warpId = tid >> 5;
    const int lane = tid & 31;
    const int wm = warpId >> 2;
    const int wn = warpId & 3;
    const int h = blockIdx.y;
    const __half* A = A16 + (size_t)h * 128 * 512;   // [128][512]
    const __half* B = BT16 + (size_t)h * 512 * 128;  // [512][128]
    constexpr int K = 512, N = 128;

    const int ar = tid >> 1, ac = (tid & 1) * 16;
    const int br = tid >> 3, bc = (tid & 7) * 16;

    wmma::fragment<wmma::accumulator, 16, 16, 16, float> acc[4][2];
#pragma unroll
    for (int i = 0; i < 4; i++)
#pragma unroll
        for (int j = 0; j < 2; j++) wmma::fill_fragment(acc[i][j], 0.f);

    auto issue = [&](int kb, int s) {
        __half* base = sm + s * STAGE_H;
        __half* pA = base + ar * LDAH + ac;
        const size_t off = (size_t)ar * K + kb + ac;
        cp16((uint32_t)__cvta_generic_to_shared(pA),     A + off);
        cp16((uint32_t)__cvta_generic_to_shared(pA + 8), A + off + 8);
        __half* pB = base + ASZH + br * LDBH + bc;
        const size_t boff = (size_t)(kb + br) * N + bc;
        cp16((uint32_t)__cvta_generic_to_shared(pB),     B + boff);
        cp16((uint32_t)__cvta_generic_to_shared(pB + 8), B + boff + 8);
        cp_commit();
    };

    const int nk = K >> 5;
    issue(0, 0);

    for (int it = 0; it < nk; ++it) {
        const int s = it & 1;
        if (it + 1 < nk) { issue((it + 1) << 5, s ^ 1); cp_wait<1>(); }
        else             { cp_wait<0>(); }
        __syncthreads();

        const __half* As = sm + s * STAGE_H;
        const __half* Bs = As + ASZH;

#pragma unroll
        for (int kk = 0; kk < 2; kk++) {
            wmma::fragment<wmma::matrix_a, 16, 16, 16, __half, wmma::row_major> af[4];
            wmma::fragment<wmma::matrix_b, 16, 16, 16, __half, wmma::row_major> bf[2];
#pragma unroll
            for (int i = 0; i < 4; i++)
                wmma::load_matrix_sync(af[i], As + (wm * 64 + i * 16) * LDAH + kk * 16, LDAH);
#pragma unroll
            for (int j = 0; j < 2; j++)
                wmma::load_matrix_sync(bf[j], Bs + (kk * 16) * LDBH + wn * 32 + j * 16, LDBH);
#pragma unroll
            for (int i = 0; i < 4; i++)
#pragma unroll
                for (int j = 0; j < 2; j++)
                    wmma::mma_sync(acc[i][j], af[i], bf[j], acc[i][j]);
        }
        __syncthreads();
    }

    // epilogue: WF[WF_BASE1 + row*F_N1 + h*128 + col]  (fp16)
    float* wb = reinterpret_cast<float*>(sm) + warpId * 256;
#pragma unroll
    for (int i = 0; i < 4; i++)
#pragma unroll
        for (int j = 0; j < 2; j++) {
            wmma::store_matrix_sync(wb, acc[i][j], 16, wmma::mem_row_major);
            __syncwarp();
            const int r0 = wm * 64 + i * 16;
            const int c0 = wn * 32 + j * 16;
#pragma unroll
            for (int e = lane; e < 64; e += 32) {
                const int rr = e >> 2, c4 = (e & 3) * 4;
                const float4 vv = *reinterpret_cast<float4*>(wb + rr * 16 + c4);
                uint2 p;
                *reinterpret_cast<__half2*>(&p.x) = __floats2half2_rn(vv.x, vv.y);
                *reinterpret_cast<__half2*>(&p.y) = __floats2half2_rn(vv.z, vv.w);
                *reinterpret_cast<uint2*>(&WF[WF_BASE1 + (size_t)(r0 + rr) * F_N1
                                              + h * 128 + c0 + c4]) = p;
            }
            __syncwarp();
        }
}

// ---------------- extras columns (alpha/beta/zero) + L1 logit bias ----------------
__global__ void m_extras(const float* __restrict__ wq, const float* __restrict__ wk,
                         const float* __restrict__ bq, const float* __restrict__ bk,
                         __half* __restrict__ WF, float* __restrict__ bias)
{
    __shared__ float red[128];
    const int j = blockIdx.x;          // 0..MCOLS-1
    const int tid = threadIdx.x;       // 128

    if (j < ZCOLS) {
        if (tid == 0) bias[j] = 0.f;
        return;
    }
    if (j >= 1040) {
        WF[WF_BASE1 + (size_t)tid * F_N1 + j] = __float2half(0.f);
        if (tid == 0) bias[j] = 0.f;
        return;
    }

    const bool isAlpha = (j < 1032);
    const int h = isAlpha ? (j - 1024) : (j - 1032);
    const int base = h * D1;
    const float* mat = isAlpha ? wq : wk;
    const float* vec = isAlpha ? bk : bq;

    const float4* row4 = reinterpret_cast<const float4*>(mat + (size_t)tid * (HEADS * D1) + base);
    const float4* vec4 = reinterpret_cast<const float4*>(vec + base);
    float acc = 0.f;
#pragma unroll 4
    for (int c = 0; c < D1 / 4; c++) {
        const float4 r = row4[c];
        const float4 v = vec4[c];
        acc += r.x * v.x + r.y * v.y + r.z * v.z + r.w * v.w;
    }
    WF[WF_BASE1 + (size_t)tid * F_N1 + j] = __float2half(acc);

    if (isAlpha) {
        float p = 0.f;
        for (int c = tid; c < D1; c += 128) p += bq[base + c] * bk[base + c];
        red[tid] = p;
        __syncthreads();
        if (tid < 64) red[tid] += red[tid + 64];
        __syncthreads();
        if (tid < 32) {
            float t = red[tid] + red[tid + 32];
#pragma unroll
            for (int o = 16; o > 0; o >>= 1) t += __shfl_down_sync(0xffffffffu, t, o);
            if (tid == 0) bias[j] = t;
        }
    } else {
        if (tid == 0) bias[j] = 0.f;
    }
}

// ---------------- epilogue routing table ----------------
struct EpiTab {
    float* f[4];
    __half* h[4];
    int stride[4];
    int start[4];
};

// ---------------- fp16 single-pass GEMM, BK=32 ----------------
__global__ __launch_bounds__(256, 2)
void gemm_half(const __half* __restrict__ A, const __half* __restrict__ B,
               const float* __restrict__ bias, EpiTab T,
               int M, int N, int K)
{
    __shared__ __align__(16) __half sm[2 * STAGE_H];

    const int tid = threadIdx.x;
    const int warpId = tid >> 5;
    const int lane = tid & 31;
    const int wm = warpId >> 2;
    const int wn = warpId & 3;
    const int bm = blockIdx.y * 128;
    const int bn = blockIdx.x * 128;

    const int ar = tid >> 1, ac = (tid & 1) * 16;
    const int br = tid >> 3, bc = (tid & 7) * 16;

    wmma::fragment<wmma::accumulator, 16, 16, 16, float> acc[4][2];
#pragma unroll
    for (int i = 0; i < 4; i++)
#pragma unroll
        for (int j = 0; j < 2; j++) wmma::fill_fragment(acc[i][j], 0.f);

    auto issue = [&](int kb, int s) {
        __half* base = sm + s * STAGE_H;
        __half* pA = base + ar * LDAH + ac;
        const int gr = bm + ar;
        if (gr < M) {
            const size_t off = (size_t)gr * K + kb + ac;
            cp16((uint32_t)__cvta_generic_to_shared(pA),     A + off);
            cp16((uint32_t)__cvta_generic_to_shared(pA + 8), A + off + 8);
        } else {
            uint4 z = make_uint4(0, 0, 0, 0);
            *reinterpret_cast<uint4*>(pA) = z;
            *reinterpret_cast<uint4*>(pA + 8) = z;
        }
        __half* pB = base + ASZH + br * LDBH + bc;
        const size_t boff = (size_t)(kb + br) * N + bn + bc;
        cp16((uint32_t)__cvta_generic_to_shared(pB),     B + boff);
        cp16((uint32_t)__cvta_generic_to_shared(pB + 8), B + boff + 8);
        cp_commit();
    };

    const int nk = K >> 5;
    issue(0, 0);

    for (int it = 0; it < nk; ++it) {
        const int s = it & 1;
        if (it + 1 < nk) { issue((it + 1) << 5, s ^ 1); cp_wait<1>(); }
        else             { cp_wait<0>(); }
        __syncthreads();

        const __half* As = sm + s * STAGE_H;
        const __half* Bs = As + ASZH;

#pragma unroll
        for (int kk = 0; kk < 2; kk++) {
            wmma::fragment<wmma::matrix_a, 16, 16, 16, __half, wmma::row_major> af[4];
            wmma::fragment<wmma::matrix_b, 16, 16, 16, __half, wmma::row_major> bf[2];
#pragma unroll
            for (int i = 0; i < 4; i++)
                wmma::load_matrix_sync(af[i], As + (wm * 64 + i * 16) * LDAH + kk * 16, LDAH);
#pragma unroll
            for (int j = 0; j < 2; j++)
                wmma::load_matrix_sync(bf[j], Bs + (kk * 16) * LDBH + wn * 32 + j * 16, LDBH);
#pragma unroll
            for (int i = 0; i < 4; i++)
#pragma unroll
                for (int j = 0; j < 2; j++)
                    wmma::mma_sync(acc[i][j], af[i], bf[j], acc[i][j]);
        }
        __syncthreads();
    }

    const int r = (bn >= T.start[3]) ? 3 : (bn >= T.start[2]) ? 2 : (bn >= T.start[1]) ? 1 : 0;
    float* fdst = T.f[r];
    __half* hdst = T.h[r];
    const int lcb = bn - T.start[r];
    const int stride = T.stride[r];

    float* wb = reinterpret_cast<float*>(sm) + warpId * 256;
#pragma unroll
    for (int i = 0; i < 4; i++)
#pragma unroll
        for (int j = 0; j < 2; j++) {
            wmma::store_matrix_sync(wb, acc[i][j], 16, wmma::mem_row_major);
            __syncwarp();
            const int r0 = bm + wm * 64 + i * 16;
            const int c0 = bn + wn * 32 + j * 16;
#pragma unroll
            for (int e = lane; e < 64; e += 32) {
                const int rr = e >> 2, c4 = (e & 3) * 4;
                if (r0 + rr >= M) continue;
                float4 vv = *reinterpret_cast<float4*>(wb + rr * 16 + c4);
                const int col = c0 + c4;
                vv.x += bias[col + 0];
                vv.y += bias[col + 1];
                vv.z += bias[col + 2];
                vv.w += bias[col + 3];
                const size_t o = (size_t)(r0 + rr) * stride + (lcb + (col - bn));
                if (fdst) {
                    *reinterpret_cast<float4*>(fdst + o) = vv;
                } else {
                    uint2 p;
                    *reinterpret_cast<__half2*>(&p.x) = __floats2half2_rn(vv.x, vv.y);
                    *reinterpret_cast<__half2*>(&p.y) = __floats2half2_rn(vv.z, vv.w);
                    *reinterpret_cast<uint2*>(hdst + o) = p;
                }
            }
            __syncwarp();
        }
}

// ---------------- CSR build ----------------
__global__ void scan_deg(const int* __restrict__ deg, int* __restrict__ ptr,
                         int* __restrict__ fill, int n)
{
    constexpr int PER = 10;
    const int tid = threadIdx.x;
    const int lane = tid & 31, wid = tid >> 5;
    const int base = tid * PER;

    int vals[PER];
    int s = 0;
#pragma unroll
    for (int i = 0; i < PER; i++) {
        const int idx = base + i;
        vals[i] = (idx < n) ? deg[idx] : 0;
        s += vals[i];
    }
    int sc = s;
#pragma unroll
    for (int o = 1; o < 32; o <<= 1) {
        int t = __shfl_up_sync(0xffffffffu, sc, o);
        if (lane >= o) sc += t;
    }
    __shared__ int wsum[32];
    if (lane == 31) wsum[wid] = sc;
    __syncthreads();
    if (wid == 0) {
        int w = wsum[lane];
#pragma unroll
        for (int o = 1; o < 32; o <<= 1) {
            int t = __shfl_up_sync(0xffffffffu, w, o);
            if (lane >= o) w += t;
        }
        wsum[lane] = w;
    }
    __syncthreads();
    int run = (sc - s) + (wid > 0 ? wsum[wid - 1] : 0);
#pragma unroll
    for (int i = 0; i < PER; i++) {
        const int idx = base + i;
        if (idx < n) { ptr[idx] = run; fill[idx] = run; }
        run += vals[i];
    }
    if (tid == 1023) ptr[n] = run;
}

__global__ void fill_csr(const int* __restrict__ ei, int* __restrict__ fill,
                         int* __restrict__ csr_src, int E)
{
    int e = blockIdx.x * blockDim.x + threadIdx.x;
    if (e < E) {
        const int d = ei[E + e];
        const int pos = atomicAdd(&fill[d], 1);
        csr_src[pos] = ei[e];
    }
}

// ---------------- layer-1 attention (factored logits, unroll-2, predicated) ----------------
struct Edge1 { uint2 x; uint2 v[4]; float beta; };

__global__ void attn1_kernel(const float* __restrict__ z, const __half* __restrict__ x16,
                             const float* __restrict__ ex, const __half* __restrict__ v,
                             const int* __restrict__ ptr, const int* __restrict__ csr_src,
                             const float* __restrict__ skip,
                             __half* __restrict__ outF16)
{
    constexpr int C = D1;
    constexpr int F4 = C / 128;
    __shared__ float red[HEADS * C];

    const int dst  = blockIdx.x;
    const int warp = threadIdx.x >> 5;
    const int lane = threadIdx.x & 31;
    const float scale = rsqrtf((float)C);

    const int beg = ptr[dst], end = ptr[dst + 1];

    const float4 zr = reinterpret_cast<const float4*>(z + (size_t)dst * ZCOLS + warp * F_IN)[lane];
    const float alpha = ex[(size_t)dst * 128 + warp];

    float4 acc[F4];
#pragma unroll
    for (int i = 0; i < F4; i++) acc[i] = make_float4(0.f, 0.f, 0.f, 0.f);
    float m = -INFINITY, s = 0.f;

    auto load1 = [&](Edge1& E, int e, bool valid) {
        if (valid) {
            const int src = csr_src[e];
            E.x = reinterpret_cast<const uint2*>(x16 + (size_t)src * F_IN)[lane];
            const uint2* vrow = reinterpret_cast<const uint2*>(v + (size_t)src * (HEADS * C) + warp * C);
#pragma unroll
            for (int i = 0; i < F4; i++) E.v[i] = vrow[lane + 32 * i];
            E.beta = ex[(size_t)src * 128 + 8 + warp];
        } else {
            E.x = make_uint2(0, 0);
            E.beta = 0.f;
#pragma unroll
            for (int i = 0; i < F4; i++) E.v[i] = make_uint2(0, 0);
        }
    };
    auto dotx = [&](const uint2& xx) {
        const float2 x0 = __half22float2(*reinterpret_cast<const __half2*>(&xx.x));
        const float2 x1 = __half22float2(*reinterpret_cast<const __half2*>(&xx.y));
        return zr.x * x0.x + zr.y * x0.y + zr.z * x1.x + zr.w * x1.y;
    };

    Edge1 c0, c1, n0, n1;
    if (beg < end) {
        load1(c0, beg, true);
        load1(c1, beg + 1, beg + 1 < end);
    }

    for (int j = beg; j < end; j += 2) {
        if (j + 2 < end) {
            load1(n0, j + 2, true);
            load1(n1, j + 3, j + 3 < end);
        }
        float d1 = dotx(c0.x);
        float d2 = dotx(c1.x);
#pragma unroll
        for (int o = 16; o > 0; o >>= 1) {
            d1 += __shfl_xor_sync(0xffffffffu, d1, o);
            d2 += __shfl_xor_sync(0xffffffffu, d2, o);
        }
        const float a1 = (d1 + alpha + c0.beta) * scale;
        const float a2 = (j + 1 < end) ? (d2 + alpha + c1.beta) * scale : -INFINITY;
        const float mn = fmaxf(m, fmaxf(a1, a2));
        const float corr = expf(m - mn);
        const float w1 = expf(a1 - mn);
        const float w2 = expf(a2 - mn);
        s = s * corr + w1 + w2;
        m = mn;
#pragma unroll
        for (int i = 0; i < F4; i++) {
            const float2 u0 = __half22float2(*reinterpret_cast<const __half2*>(&c0.v[i].x));
            const float2 u1 = __half22float2(*reinterpret_cast<const __half2*>(&c0.v[i].y));
            const float2 w0 = __half22float2(*reinterpret_cast<const __half2*>(&c1.v[i].x));
            const float2 w1v = __half22float2(*reinterpret_cast<const __half2*>(&c1.v[i].y));
            acc[i].x = acc[i].x * corr + w1 * u0.x + w2 * w0.x;
            acc[i].y = acc[i].y * corr + w1 * u0.y + w2 * w0.y;
            acc[i].z = acc[i].z * corr + w1 * u1.x + w2 * w1v.x;
            acc[i].w = acc[i].w * corr + w1 * u1.y + w2 * w1v.y;
        }
        c0 = n0;
        c1 = n1;
    }

    const float inv = (end > beg) ? (1.f / (s + 1e-16f)) : 0.f;
#pragma unroll
    for (int i = 0; i < F4; i++) {
        float4 o = make_float4(acc[i].x * inv, acc[i].y * inv, acc[i].z * inv, acc[i].w * inv);
        *reinterpret_cast<float4*>(&red[warp * C + i * 128 + lane * 4]) = o;
    }
    __syncthreads();

    for (int f = threadIdx.x; f < C; f += blockDim.x) {
        float t = 0.f;
#pragma unroll
        for (int h = 0; h < HEADS; h++) t += red[h * C + f];
        t = t * (1.f / HEADS) + skip[(size_t)dst * C + f];
        t = (t > 0.f) ? t : expm1f(t);
        outF16[(size_t)dst * C + f] = __float2half(t);
    }
}

// ---------------- layers 2/3 attention (unroll-2, predicated; optional fused gate) ----------------
template <int C, bool F16OUT>
__global__ void attn_kernel(const float* __restrict__ q, const __half* __restrict__ k,
                            const __half* __restrict__ v, const int* __restrict__ ptr,
                            const int* __restrict__ csr_src, const float* __restrict__ skip,
                            float* __restrict__ out, __half* __restrict__ outF16,
                            const float* __restrict__ wg, const float* __restrict__ bg,
                            const int* __restrict__ batch, float* __restrict__ gate,
                            float* __restrict__ gmax)
{
    constexpr int H = HEADS;
    constexpr int F4 = C / 128;
    __shared__ float red[H * C];

    const int dst  = blockIdx.x;
    const int warp = threadIdx.x >> 5;
    const int lane = threadIdx.x & 31;
    const float scale = rsqrtf((float)C);
    const size_t HC = (size_t)H * C;

    const int beg = ptr[dst], end = ptr[dst + 1];

    const float4* qrow = reinterpret_cast<const float4*>(q + (size_t)dst * HC + warp * C);
    float4 qr[F4], acc[F4];
#pragma unroll
    for (int i = 0; i < F4; i++) {
        qr[i] = qrow[lane + 32 * i];
        acc[i] = make_float4(0.f, 0.f, 0.f, 0.f);
    }
    float m = -INFINITY, s = 0.f;

    struct EdgeC { uint2 k[F4]; uint2 v[F4]; };
    auto loadE = [&](EdgeC& E, int e, bool valid) {
        if (valid) {
            const int src = csr_src[e];
            const uint2* krow = reinterpret_cast<const uint2*>(k + (size_t)src * HC + warp * C);
            const uint2* vrow = reinterpret_cast<const uint2*>(v + (size_t)src * HC + warp * C);
#pragma unroll
            for (int i = 0; i < F4; i++) { E.k[i] = krow[lane + 32 * i]; E.v[i] = vrow[lane + 32 * i]; }
        } else {
#pragma unroll
            for (int i = 0; i < F4; i++) { E.k[i] = make_uint2(0, 0); E.v[i] = make_uint2(0, 0); }
        }
    };
    auto dotk = [&](const EdgeC& E) {
        float d = 0.f;
#pragma unroll
        for (int i = 0; i < F4; i++) {
            const float2 k0 = __half22float2(*reinterpret_cast<const __half2*>(&E.k[i].x));
            const float2 k1 = __half22float2(*reinterpret_cast<const __half2*>(&E.k[i].y));
            d += qr[i].x * k0.x + qr[i].y * k0.y + qr[i].z * k1.x + qr[i].w * k1.y;
        }
        return d;
    };

    EdgeC c0, c1, n0, n1;
    if (beg < end) {
        loadE(c0, beg, true);
        loadE(c1, beg + 1, beg + 1 < end);
    }

    for (int j = beg; j < end; j += 2) {
        if (j + 2 < end) {
            loadE(n0, j + 2, true);
            loadE(n1, j + 3, j + 3 < end);
        }
        float d1 = dotk(c0);
        float d2 = dotk(c1);
#pragma unroll
        for (int o = 16; o > 0; o >>= 1) {
            d1 += __shfl_xor_sync(0xffffffffu, d1, o);
            d2 += __shfl_xor_sync(0xffffffffu, d2, o);
        }
        const float a1 = d1 * scale;
        const float a2 = (j + 1 < end) ? d2 * scale : -INFINITY;
        const float mn = fmaxf(m, fmaxf(a1, a2));
        const float corr = expf(m - mn);
        const float w1 = expf(a1 - mn);
        const float w2 = expf(a2 - mn);
        s = s * corr + w1 + w2;
        m = mn;
#pragma unroll
        for (int i = 0; i < F4; i++) {
            const float2 u0 = __half22float2(*reinterpret_cast<const __half2*>(&c0.v[i].x));
            const float2 u1 = __half22float2(*reinterpret_cast<const __half2*>(&c0.v[i].y));
            const float2 w0 = __half22float2(*reinterpret_cast<const __half2*>(&c1.v[i].x));
            const float2 w1v = __half22float2(*reinterpret_cast<const __half2*>(&c1.v[i].y));
            acc[i].x = acc[i].x * corr + w1 * u0.x + w2 * w0.x;
            acc[i].y = acc[i].y * corr + w1 * u0.y + w2 * w0.y;
            acc[i].z = acc[i].z * corr + w1 * u1.x + w2 * w1v.x;
            acc[i].w = acc[i].w * corr + w1 * u1.y + w2 * w1v.y;
        }
        c0 = n0;
        c1 = n1;
    }

    const float inv = (end > beg) ? (1.f / (s + 1e-16f)) : 0.f;
#pragma unroll
    for (int i = 0; i < F4; i++) {
        float4 o = make_float4(acc[i].x * inv, acc[i].y * inv, acc[i].z * inv, acc[i].w * inv);
        *reinterpret_cast<float4*>(&red[warp * C + i * 128 + lane * 4]) = o;
    }
    __syncthreads();

    float part = 0.f;
    for (int f = threadIdx.x; f < C; f += blockDim.x) {
        float t = 0.f;
#pragma unroll
        for (int h = 0; h < H; h++) t += red[h * C + f];
        t = t * (1.f / H) + skip[(size_t)dst * C + f];
        t = (t > 0.f) ? t : expm1f(t);
        const size_t idx = (size_t)dst * C + f;
        if constexpr (F16OUT) {
            outF16[idx] = __float2half(t);
        } else {
            out[idx] = t;
            part += t * wg[f];
        }
    }

    if constexpr (!F16OUT) {
        __syncthreads();
        red[threadIdx.x] = part;
        __syncthreads();
#pragma unroll
        for (int off = 128; off > 0; off >>= 1) {
            if (threadIdx.x < off) red[threadIdx.x] += red[threadIdx.x + off];
            __syncthreads();
        }
        if (threadIdx.x == 0) {
            const float d = red[0] + bg[0];
            gate[dst] = d;
            float* addr = &gmax[batch[dst]];
            if (d >= 0.f) atomicMax((int*)addr, __float_as_int(d));
            else          atomicMin((unsigned int*)addr, __float_as_uint(d));
        }
    }
}

// ---------------- global attention pooling ----------------
__global__ void init_gmax(float* gmax)
{
    if (threadIdx.x < N_GRAPHS) gmax[threadIdx.x] = -INFINITY;
}

__global__ void exp_pool(const float* __restrict__ h, const float* __restrict__ gate,
                         const int* __restrict__ batch, const float* __restrict__ gmax,
                         float* __restrict__ gsum, float* __restrict__ pool)
{
    const int node = blockIdx.x;
    const int f = threadIdx.x;
    const int b = batch[node];
    const float e = expf(gate[node] - gmax[b]);
    if (f == 0) atomicAdd(&gsum[b], e);
    atomicAdd(&pool[b * D3 + f], e * h[(size_t)node * D3 + f]);
}

__global__ void fc_kernel(const float* __restrict__ pool, const float* __restrict__ gsum,
                          const float* __restrict__ wfc, const float* __restrict__ bfc,
                          float* __restrict__ out)
{
    const int t = threadIdx.x;
    if (t >= N_GRAPHS * OUT_DIM) return;
    const int g = t / OUT_DIM, o = t % OUT_DIM;
    float s = 0.f;
#pragma unroll 16
    for (int f = 0; f < D3; f++) s += pool[g * D3 + f] * wfc[f * OUT_DIM + o];
    out[g * OUT_DIM + o] = s / (gsum[g] + 1e-16f) + bfc[o];
}

// ---------------- launch ----------------
extern "C" void kernel_launch(void* const* d_in, const int* in_sizes, int n_in,
                              void* d_out, int out_size)
{
    const float* x     = (const float*)d_in[0];
    const int*   ei    = (const int*)d_in[1];
    const int*   batch = (const int*)d_in[2];
    const float* W[12] = { (const float*)d_in[3],  (const float*)d_in[5],
                           (const float*)d_in[7],  (const float*)d_in[9],
                           (const float*)d_in[11], (const float*)d_in[13],
                           (const float*)d_in[15], (const float*)d_in[17],
                           (const float*)d_in[19], (const float*)d_in[21],
                           (const float*)d_in[23], (const float*)d_in[25] };
    const float* Bv[12] = { (const float*)d_in[4],  (const float*)d_in[6],
                            (const float*)d_in[8],  (const float*)d_in[10],
                            (const float*)d_in[12], (const float*)d_in[14],
                            (const float*)d_in[16], (const float*)d_in[18],
                            (const float*)d_in[20], (const float*)d_in[22],
                            (const float*)d_in[24], (const float*)d_in[26] };
    const float* w_g  = (const float*)d_in[27]; const float* b_g  = (const float*)d_in[28];
    const float* w_fc = (const float*)d_in[29]; const float* b_fc = (const float*)d_in[30];
    float* out = (float*)d_out;

    float *qb, *skipb, *hA, *gateb, *gmaxb, *gsumb, *poolb, *biasb, *extrasb;
    __half *kb, *vb, *x16b, *Af16b, *WFb, *A16b, *BT16b;
    int *degb, *ptrb, *fillb, *csrb;
    cudaGetSymbolAddress((void**)&qb,     g_q);
    cudaGetSymbolAddress((void**)&kb,     g_k);
    cudaGetSymbolAddress((void**)&vb,     g_v);
    cudaGetSymbolAddress((void**)&skipb,  g_skip);
    cudaGetSymbolAddress((void**)&hA,     g_hA);
    cudaGetSymbolAddress((void**)&extrasb,g_extras);
    cudaGetSymbolAddress((void**)&x16b,   g_x16);
    cudaGetSymbolAddress((void**)&Af16b,  g_Af16);
    cudaGetSymbolAddress((void**)&A16b,   g_A16);
    cudaGetSymbolAddress((void**)&BT16b,  g_BT16);
    cudaGetSymbolAddress((void**)&WFb,    g_WF);
    cudaGetSymbolAddress((void**)&biasb,  g_bias);
    cudaGetSymbolAddress((void**)&degb,   g_deg);
    cudaGetSymbolAddress((void**)&ptrb,   g_ptr);
    cudaGetSymbolAddress((void**)&fillb,  g_fill);
    cudaGetSymbolAddress((void**)&csrb,   g_csr_src);
    cudaGetSymbolAddress((void**)&gateb,  g_gate);
    cudaGetSymbolAddress((void**)&gmaxb,  g_gmax);
    cudaGetSymbolAddress((void**)&gsumb,  g_gsum);
    cudaGetSymbolAddress((void**)&poolb,  g_pool);

    const int N = N_NODES, E = N_EDGES;

    // ---- pack regions (10 weight regions; M region handled by make_m_mm) ----
    PackArgs P;
    long long wcum = 0;
    int bcum = 0;
    int ri = 0;
    auto addW = [&](const float* src, int K, int ncols, long long base, int ntot, int coff,
                    const float* bsrc, int boff) {
        P.wsrc[ri] = src; P.wcum[ri] = wcum; P.wncols[ri] = ncols;
        P.wdstBase[ri] = base; P.wntot[ri] = ntot; P.wcoff[ri] = coff;
        wcum += (long long)K * ncols;
        P.bsrc[ri] = bsrc; P.bcum[ri] = bcum; P.boff[ri] = boff;
        bcum += ncols;
        ri++;
    };
    addW(W[2], F_IN, HEADS * D1, WF_BASE1, F_N1, MCOLS, Bv[2], BB1 + MCOLS);
    addW(W[3], F_IN, D1, WF_BASE1, F_N1, MCOLS + HEADS * D1, Bv[3], BB1 + MCOLS + HEADS * D1);
    for (int p = 0; p < 4; p++) {
        const int ncols = (p < 3) ? HEADS * D2 : D2;
        const int coff = (p < 3) ? p * HEADS * D2 : 3 * HEADS * D2;
        addW(W[4 + p], D1, ncols, WF_BASE2, F_N2, coff, Bv[4 + p], BB2 + coff);
    }
    for (int p = 0; p < 4; p++) {
        const int ncols = (p < 3) ? HEADS * D3 : D3;
        const int coff = (p < 3) ? p * HEADS * D3 : 3 * HEADS * D3;
        addW(W[8 + p], D2, ncols, WF_BASE3, F_N3, coff, Bv[8 + p], BB3 + coff);
    }
    P.wcum[ri] = wcum;
    P.bcum[ri] = bcum;
    for (int r2 = ri; r2 < 12; r2++) { P.wcum[r2 + 1] = wcum; P.bcum[r2 + 1] = bcum; }
    P.x = x;
    P.wq = W[0];
    P.wk = W[1];
    P.ei = ei;

    const long long packTotal = wcum + NXTOT + bcum + QKTOT + E;
    const int gy = (N + 127) / 128;

    // epilogue tables
    EpiTab T1;  // z | extras | v | skip
    T1.start[0] = 0;     T1.f[0] = qb;      T1.h[0] = nullptr; T1.stride[0] = ZCOLS;
    T1.start[1] = ZCOLS; T1.f[1] = extrasb; T1.h[1] = nullptr; T1.stride[1] = 128;
    T1.start[2] = MCOLS; T1.f[2] = nullptr; T1.h[2] = vb;      T1.stride[2] = HEADS * D1;
    T1.start[3] = MCOLS + HEADS * D1; T1.f[3] = skipb; T1.h[3] = nullptr; T1.stride[3] = D1;
    EpiTab T2;
    T2.start[0] = 0;              T2.f[0] = qb;      T2.h[0] = nullptr; T2.stride[0] = HEADS * D2;
    T2.start[1] = HEADS * D2;     T2.f[1] = nullptr; T2.h[1] = kb;      T2.stride[1] = HEADS * D2;
    T2.start[2] = 2 * HEADS * D2; T2.f[2] = nullptr; T2.h[2] = vb;      T2.stride[2] = HEADS * D2;
    T2.start[3] = 3 * HEADS * D2; T2.f[3] = skipb;   T2.h[3] = nullptr; T2.stride[3] = D2;
    EpiTab T3;
    T3.start[0] = 0;              T3.f[0] = qb;      T3.h[0] = nullptr; T3.stride[0] = HEADS * D3;
    T3.start[1] = HEADS * D3;     T3.f[1] = nullptr; T3.h[1] = kb;      T3.stride[1] = HEADS * D3;
    T3.start[2] = 2 * HEADS * D3; T3.f[2] = nullptr; T3.h[2] = vb;      T3.stride[2] = HEADS * D3;
    T3.start[3] = 3 * HEADS * D3; T3.f[3] = skipb;   T3.h[3] = nullptr; T3.stride[3] = D3;

    // launch order: gemm_half L1 at slot 5 (ncu capture)
    cudaMemsetAsync(degb, 0, N * sizeof(int));                                          // 1
    pack_all<<<(int)((packTotal + 255) / 256), 256>>>(P, WFb, x16b, biasb, A16b, BT16b,
                                                      degb, wcum, NXTOT, bcum);         // 2
    make_m_mm<<<dim3(1, 8), 256>>>(A16b, BT16b, WFb);                                   // 3
    m_extras<<<MCOLS, 128>>>(W[0], W[1], Bv[0], Bv[1], WFb, biasb + BB1);               // 4
    gemm_half<<<dim3(F_N1 / 128, gy), 256>>>(x16b, WFb + WF_BASE1,
                                             biasb + BB1, T1, N, F_N1, F_IN);           // 5 <- profiled
    scan_deg<<<1, 1024>>>(degb, ptrb, fillb, N);                                        // 6
    fill_csr<<<(E + 255) / 256, 256>>>(ei, fillb, csrb, E);                             // 7
    attn1_kernel<<<N, 256>>>(qb, x16b, extrasb, vb, ptrb, csrb, skipb, Af16b);          // 8

    gemm_half<<<dim3(F_N2 / 128, gy), 256>>>(Af16b, WFb + WF_BASE2,
                                             biasb + BB2, T2, N, F_N2, D1);
    attn_kernel<D2, true><<<N, 256>>>(qb, kb, vb, ptrb, csrb, skipb, nullptr, Af16b,
                                      nullptr, nullptr, nullptr, nullptr, nullptr);

    gemm_half<<<dim3(F_N3 / 128, gy), 256>>>(Af16b, WFb + WF_BASE3,
                                             biasb + BB3, T3, N, F_N3, D2);
    init_gmax<<<1, 64>>>(gmaxb);
    cudaMemsetAsync(gsumb, 0, N_GRAPHS * sizeof(float));
    cudaMemsetAsync(poolb, 0, N_GRAPHS * D3 * sizeof(float));
    attn_kernel<D3, false><<<N, 256>>>(qb, kb, vb, ptrb, csrb, skipb, hA, nullptr,
                                       w_g, b_g, batch, gateb, gmaxb);

    exp_pool<<<N, D3>>>(hA, gateb, batch, gmaxb, gsumb, poolb);
    fc_kernel<<<1, 1024>>>(poolb, gsumb, w_fc, b_fc, out);
}